// round 2
// baseline (speedup 1.0000x reference)
#include <cuda_runtime.h>
#include <math.h>

typedef unsigned long long ull;

#define T_DIM 2048
#define D_DIM 2048
#define NQH 16
#define NKH 8
#define HD 128
#define WINDOW 1024
#define SOFTCAP 50.0f
#define QSCALE 0.08838834764831845f

// scratch (allocation-free rule: device globals)
__device__ float g_q[T_DIM * NQH * HD];    // [t][n][h]   16 MB
__device__ float g_k[T_DIM * NKH * HD];    // [t][kh][h]   8 MB
__device__ float g_v[T_DIM * NKH * HD];    // [t][kh][h]   8 MB
__device__ float g_enc[T_DIM * NQH * HD];  // [t][n][h]   16 MB

// ---- packed f32x2 helpers (full-rate fp32 on sm_103a) ----
__device__ __forceinline__ ull pk2(float lo, float hi) {
    ull r; asm("mov.b64 %0, {%1, %2};" : "=l"(r) : "f"(lo), "f"(hi)); return r;
}
__device__ __forceinline__ void fma2(ull& d, ull a, ull b) {
    asm("fma.rn.f32x2 %0, %1, %2, %0;" : "+l"(d) : "l"(a), "l"(b));
}
__device__ __forceinline__ void mul2(ull& d, ull a) {
    asm("mul.rn.f32x2 %0, %0, %1;" : "+l"(d) : "l"(a));
}
__device__ __forceinline__ float2 up2(ull v) {
    float2 f; asm("mov.b64 {%0, %1}, %2;" : "=f"(f.x), "=f"(f.y) : "l"(v)); return f;
}

// ============================================================
// SGEMM tile body: C[row0+128][col-tile 128] += A[128 x 2048] * B
// B element (d, c) = wbase[d*ldb + c], c in [0,128)
// 256 threads, 8x8 per thread via f32x2 pairs.
// ============================================================
__device__ __forceinline__ void sgemm_tile(
    const float* __restrict__ A,
    const float* __restrict__ wbase, int ldb,
    float* __restrict__ dst, int ldc, int row0)
{
    __shared__ float As[16][132];   // [k][m], padded vs store conflicts
    __shared__ float Bs[16][128];   // [k][n]

    const int tid = threadIdx.x;
    const int tx = tid & 15;        // col group
    const int ty = tid >> 4;        // row group

    ull acc[8][4];
#pragma unroll
    for (int i = 0; i < 8; ++i)
#pragma unroll
        for (int j = 0; j < 4; ++j) acc[i][j] = 0ull;

    for (int kk = 0; kk < D_DIM; kk += 16) {
#pragma unroll
        for (int l = 0; l < 2; ++l) {           // A tile 128x16, transposed store
            int idx = tid + l * 256;
            int r = idx >> 2;
            int c = (idx & 3) << 2;
            float4 v = *reinterpret_cast<const float4*>(&A[(row0 + r) * D_DIM + kk + c]);
            As[c + 0][r] = v.x; As[c + 1][r] = v.y;
            As[c + 2][r] = v.z; As[c + 3][r] = v.w;
        }
#pragma unroll
        for (int l = 0; l < 2; ++l) {           // B tile 16x128
            int idx = tid + l * 256;
            int k = idx >> 5;
            int c = (idx & 31) << 2;
            *reinterpret_cast<float4*>(&Bs[k][c]) =
                *reinterpret_cast<const float4*>(&wbase[(kk + k) * ldb + c]);
        }
        __syncthreads();
#pragma unroll
        for (int k = 0; k < 16; ++k) {
            float4 a0 = *reinterpret_cast<const float4*>(&As[k][ty * 8]);
            float4 a1 = *reinterpret_cast<const float4*>(&As[k][ty * 8 + 4]);
            const ull* bp = reinterpret_cast<const ull*>(&Bs[k][tx * 8]);
            ull b0 = bp[0], b1 = bp[1], b2 = bp[2], b3 = bp[3];
            ull a2[8];
            a2[0] = pk2(a0.x, a0.x); a2[1] = pk2(a0.y, a0.y);
            a2[2] = pk2(a0.z, a0.z); a2[3] = pk2(a0.w, a0.w);
            a2[4] = pk2(a1.x, a1.x); a2[5] = pk2(a1.y, a1.y);
            a2[6] = pk2(a1.z, a1.z); a2[7] = pk2(a1.w, a1.w);
#pragma unroll
            for (int i = 0; i < 8; ++i) {
                fma2(acc[i][0], a2[i], b0);
                fma2(acc[i][1], a2[i], b1);
                fma2(acc[i][2], a2[i], b2);
                fma2(acc[i][3], a2[i], b3);
            }
        }
        __syncthreads();
    }
#pragma unroll
    for (int i = 0; i < 8; ++i) {
        int r = row0 + ty * 8 + i;
        float o[8];
#pragma unroll
        for (int j = 0; j < 4; ++j) {
            float2 f = up2(acc[i][j]);
            o[2 * j] = f.x; o[2 * j + 1] = f.y;
        }
        *reinterpret_cast<float4*>(&dst[r * ldc + tx * 8]) =
            make_float4(o[0], o[1], o[2], o[3]);
        *reinterpret_cast<float4*>(&dst[r * ldc + tx * 8 + 4]) =
            make_float4(o[4], o[5], o[6], o[7]);
    }
}

// ============================================================
// Kernel 1: fused QKV projection.  4096 output cols = 16 q heads,
// 8 k heads, 8 v heads; each 128-col tile is exactly one head.
// ============================================================
__global__ __launch_bounds__(256, 2) void qkv_gemm(
    const float* __restrict__ x,
    const float* __restrict__ qw,    // (16, 2048, 128)
    const float* __restrict__ kvw)   // (2, 8, 2048, 128)
{
    const int col0 = blockIdx.x * 128;
    const int row0 = blockIdx.y * 128;
    const float* wbase;
    float* dst;
    int ldc;
    if (col0 < NQH * HD) {
        wbase = qw + (col0 >> 7) * (D_DIM * HD);
        dst = g_q + col0; ldc = NQH * HD;
    } else if (col0 < (NQH + NKH) * HD) {
        int j = col0 - NQH * HD;
        wbase = kvw + (j >> 7) * (D_DIM * HD);
        dst = g_k + j; ldc = NKH * HD;
    } else {
        int j = col0 - (NQH + NKH) * HD;
        wbase = kvw + (NKH + (j >> 7)) * (D_DIM * HD);
        dst = g_v + j; ldc = NKH * HD;
    }
    sgemm_tile(x, wbase, HD, dst, ldc, row0);
}

// ============================================================
// Kernel 2: RoPE on q (scaled) and k, in place.
// Timescales computed in double to track the f32 reference.
// ============================================================
__global__ void rope_kernel(const int* __restrict__ seg)
{
    __shared__ float s_ts[64];
    const int t = blockIdx.x;
    const int tid = threadIdx.x;
    if (tid < 64) {
        double f = (double)tid / 64.0;
        s_ts[tid] = (float)pow(10000.0, f);
    }
    __syncthreads();
    const float pos = (float)seg[t];
    for (int idx = tid; idx < (NQH + NKH) * 64; idx += 256) {
        int head = idx >> 6;
        int i = idx & 63;
        float* base = (head < NQH) ? (g_q + t * (NQH * HD) + head * HD)
                                   : (g_k + t * (NKH * HD) + (head - NQH) * HD);
        float ang = pos / s_ts[i];
        float sv, cv;
        sincosf(ang, &sv, &cv);
        float x1 = base[i], x2 = base[i + 64];
        float o1 = x1 * cv - x2 * sv;
        float o2 = x2 * cv + x1 * sv;
        if (head < NQH) { o1 *= QSCALE; o2 *= QSCALE; }
        base[i] = o1;
        base[i + 64] = o2;
    }
}

// ============================================================
// Kernel 3: sliding-window attention.
// block = (kv head, 64 queries); rows = 2 q-heads x 64 q = 128.
// Key tiles of 64, online softmax, soft-cap tanh, f32x2 matmuls.
// ============================================================
#define SST 68
#define ATT_SMEM ((128*128 + 64*128 + 64*128 + 128*SST + 256) * 4)

__global__ __launch_bounds__(256, 1) void attn_kernel()
{
    extern __shared__ float sm[];
    float* Qs = sm;                       // 128 x 128
    float* Ks = Qs + 128 * 128;           // 64 x 128
    float* Vs = Ks + 64 * 128;            // 64 x 128
    float* Ss = Vs + 64 * 128;            // 128 x SST
    float* al_s = Ss + 128 * SST;         // 128
    float* l_s = al_s + 128;              // 128

    const int kh = blockIdx.x;
    const int t0 = blockIdx.y * 64;
    const int tid = threadIdx.x;
    const int tx = tid & 15;
    const int ty = tid >> 4;

    // load Q tile: row r -> (g = r>>6, tq = r&63)
#pragma unroll
    for (int l = 0; l < 16; ++l) {
        int idx = tid + l * 256;          // float4 units, 128*32
        int r = idx >> 5;
        int c = (idx & 31) << 2;
        int t = t0 + (r & 63);
        int n = kh * 2 + (r >> 6);
        *reinterpret_cast<float4*>(&Qs[r * 128 + c]) =
            *reinterpret_cast<const float4*>(&g_q[t * (NQH * HD) + n * HD + c]);
    }

    ull acc[8][4];
#pragma unroll
    for (int i = 0; i < 8; ++i)
#pragma unroll
        for (int j = 0; j < 4; ++j) acc[i][j] = 0ull;

    float m_reg = -1e30f, l_reg = 0.0f;   // valid for tid < 128 (row owner)

    int s_begin = (t0 >= (WINDOW - 1)) ? ((t0 - (WINDOW - 1)) & ~63) : 0;

    for (int st = s_begin; st < t0 + 64; st += 64) {
        // load K/V tiles
#pragma unroll
        for (int l = 0; l < 8; ++l) {
            int idx = tid + l * 256;      // float4 units, 64*32
            int r = idx >> 5;
            int c = (idx & 31) << 2;
            *reinterpret_cast<float4*>(&Ks[r * 128 + c]) =
                *reinterpret_cast<const float4*>(&g_k[(st + r) * (NKH * HD) + kh * HD + c]);
            *reinterpret_cast<float4*>(&Vs[r * 128 + c]) =
                *reinterpret_cast<const float4*>(&g_v[(st + r) * (NKH * HD) + kh * HD + c]);
        }
        __syncthreads();

        // scores: thread -> rows ty*8..+8, cols tx*4..+4, f32x2 over h-pairs
        ull sa[8][4];
#pragma unroll
        for (int i = 0; i < 8; ++i)
#pragma unroll
            for (int j = 0; j < 4; ++j) sa[i][j] = 0ull;
#pragma unroll 4
        for (int h = 0; h < 128; h += 2) {
            ull q2[8], k2[4];
#pragma unroll
            for (int i = 0; i < 8; ++i)
                q2[i] = *reinterpret_cast<const ull*>(&Qs[(ty * 8 + i) * 128 + h]);
#pragma unroll
            for (int j = 0; j < 4; ++j)
                k2[j] = *reinterpret_cast<const ull*>(&Ks[(tx * 4 + j) * 128 + h]);
#pragma unroll
            for (int i = 0; i < 8; ++i)
#pragma unroll
                for (int j = 0; j < 4; ++j) fma2(sa[i][j], q2[i], k2[j]);
        }
        // soft-cap + mask, write S (parallel over 256 threads)
#pragma unroll
        for (int i = 0; i < 8; ++i) {
            int r = ty * 8 + i;
            int t = t0 + (r & 63);
#pragma unroll
            for (int j = 0; j < 4; ++j) {
                int s = st + tx * 4 + j;
                float2 f = up2(sa[i][j]);
                float raw = f.x + f.y;
                float capped = tanhf(raw * (1.0f / SOFTCAP)) * SOFTCAP;
                bool ok = (s <= t) && (s > t - WINDOW);
                Ss[r * SST + tx * 4 + j] = ok ? capped : -1e30f;
            }
        }
        __syncthreads();

        // online softmax row pass (one row per thread, tid < 128)
        if (tid < 128) {
            float tm = -1e30f;
#pragma unroll 8
            for (int c = 0; c < 64; ++c) tm = fmaxf(tm, Ss[tid * SST + c]);
            float mnew = fmaxf(m_reg, tm);
            float a = expf(m_reg - mnew);
            float lsum = 0.0f;
#pragma unroll 8
            for (int c = 0; c < 64; ++c) {
                float p = expf(Ss[tid * SST + c] - mnew);
                Ss[tid * SST + c] = p;
                lsum += p;
            }
            l_reg = l_reg * a + lsum;
            m_reg = mnew;
            al_s[tid] = a;
        }
        __syncthreads();

        // rescale acc, then PV: rows ty*8..+8, cols tx*8..+8
#pragma unroll
        for (int i = 0; i < 8; ++i) {
            float a = al_s[ty * 8 + i];
            ull a2 = pk2(a, a);
#pragma unroll
            for (int j = 0; j < 4; ++j) mul2(acc[i][j], a2);
        }
#pragma unroll 2
        for (int s = 0; s < 64; ++s) {
            ull v2[4];
#pragma unroll
            for (int j = 0; j < 4; ++j)
                v2[j] = *reinterpret_cast<const ull*>(&Vs[s * 128 + tx * 8 + 2 * j]);
#pragma unroll
            for (int i = 0; i < 8; ++i) {
                float p = Ss[(ty * 8 + i) * SST + s];
                ull p2 = pk2(p, p);
#pragma unroll
                for (int j = 0; j < 4; ++j) fma2(acc[i][j], p2, v2[j]);
            }
        }
        __syncthreads();
    }

    if (tid < 128) l_s[tid] = l_reg;
    __syncthreads();

#pragma unroll
    for (int i = 0; i < 8; ++i) {
        int r = ty * 8 + i;
        float inv = 1.0f / l_s[r];
        int t = t0 + (r & 63);
        int n = kh * 2 + (r >> 6);
        float o[8];
#pragma unroll
        for (int j = 0; j < 4; ++j) {
            float2 f = up2(acc[i][j]);
            o[2 * j] = f.x * inv;
            o[2 * j + 1] = f.y * inv;
        }
        float* dp = &g_enc[t * (NQH * HD) + n * HD + tx * 8];
        *reinterpret_cast<float4*>(dp) = make_float4(o[0], o[1], o[2], o[3]);
        *reinterpret_cast<float4*>(dp + 4) = make_float4(o[4], o[5], o[6], o[7]);
    }
}

// ============================================================
// Kernel 4: output projection out[t][d] = enc[t][:] . Wo[:][d]
// ============================================================
__global__ __launch_bounds__(256, 2) void out_gemm(
    const float* __restrict__ wo,    // (16,128,2048) = (2048, 2048) row-major
    float* __restrict__ out)
{
    const int col0 = blockIdx.x * 128;
    const int row0 = blockIdx.y * 128;
    sgemm_tile(g_enc, wo + col0, D_DIM, out + col0, D_DIM, row0);
}

// ============================================================
extern "C" void kernel_launch(void* const* d_in, const int* in_sizes, int n_in,
                              void* d_out, int out_size)
{
    (void)in_sizes; (void)n_in; (void)out_size;
    const float* x   = (const float*)d_in[0];
    const int*   seg = (const int*)d_in[1];
    // d_in[2] = attn_mask: exactly causal by construction; computed analytically
    const float* qw  = (const float*)d_in[3];
    const float* kvw = (const float*)d_in[4];
    const float* ow  = (const float*)d_in[5];
    float* out = (float*)d_out;

    cudaFuncSetAttribute(attn_kernel, cudaFuncAttributeMaxDynamicSharedMemorySize, ATT_SMEM);

    qkv_gemm<<<dim3(32, 16), 256>>>(x, qw, kvw);
    rope_kernel<<<T_DIM, 256>>>(seg);
    attn_kernel<<<dim3(NKH, T_DIM / 64), 256, ATT_SMEM>>>();
    out_gemm<<<dim3(16, 16), 256>>>(ow, out);
}

// round 5
// speedup vs baseline: 1.6143x; 1.6143x over previous
#include <cuda_runtime.h>
#include <cuda_bf16.h>
#include <math.h>

typedef unsigned long long ull;
typedef unsigned int u32;
typedef unsigned short u16;

#define T_DIM 2048
#define D_DIM 2048
#define NQH 16
#define NKH 8
#define HD 128
#define WINDOW 1024
#define SOFTCAP 50.0f
#define QSCALE 0.08838834764831845f

// fp32 scratch
__device__ float g_q[T_DIM * NQH * HD];
__device__ float g_k[T_DIM * NKH * HD];
__device__ float g_v[T_DIM * NKH * HD];
__device__ float g_enc[T_DIM * NQH * HD];

// bf16 split operands (hi/lo error-compensated)
__device__ u16 gx_h[T_DIM * D_DIM], gx_l[T_DIM * D_DIM];
__device__ u16 ge_h[T_DIM * D_DIM], ge_l[T_DIM * D_DIM];
__device__ u16 gw_h[4096 * D_DIM], gw_l[4096 * D_DIM];     // qkv weights, [col][k]
__device__ u16 gwo_h[D_DIM * D_DIM], gwo_l[D_DIM * D_DIM]; // out weights,  [col][k]

// ---- packed f32x2 helpers ----
__device__ __forceinline__ ull pk2(float lo, float hi) {
    ull r; asm("mov.b64 %0, {%1, %2};" : "=l"(r) : "f"(lo), "f"(hi)); return r;
}
__device__ __forceinline__ void fma2(ull& d, ull a, ull b) {
    asm("fma.rn.f32x2 %0, %1, %2, %0;" : "+l"(d) : "l"(a), "l"(b));
}
__device__ __forceinline__ void mul2(ull& d, ull a) {
    asm("mul.rn.f32x2 %0, %0, %1;" : "+l"(d) : "l"(a));
}
__device__ __forceinline__ float2 up2(ull v) {
    float2 f; asm("mov.b64 {%0, %1}, %2;" : "=f"(f.x), "=f"(f.y) : "l"(v)); return f;
}

__device__ __forceinline__ u32 smem_u32(const void* p) {
    u32 a; asm("{ .reg .u64 t; cvta.to.shared.u64 t, %1; cvt.u32.u64 %0, t; }" : "=r"(a) : "l"(p));
    return a;
}

// ---- baseline-PTX tensor ops (compile for sm_103 without 'a') ----
__device__ __forceinline__ void ldsm4(u32* r, u32 addr) {
    asm volatile("ldmatrix.sync.aligned.m8n8.x4.shared.b16 {%0,%1,%2,%3}, [%4];"
        : "=r"(r[0]), "=r"(r[1]), "=r"(r[2]), "=r"(r[3]) : "r"(addr));
}
__device__ __forceinline__ void mma_bf16(float* c, const u32* a, u32 b0, u32 b1) {
    asm volatile("mma.sync.aligned.m16n8k16.row.col.f32.bf16.bf16.f32 "
        "{%0,%1,%2,%3}, {%4,%5,%6,%7}, {%8,%9}, {%0,%1,%2,%3};"
        : "+f"(c[0]), "+f"(c[1]), "+f"(c[2]), "+f"(c[3])
        : "r"(a[0]), "r"(a[1]), "r"(a[2]), "r"(a[3]), "r"(b0), "r"(b1));
}
__device__ __forceinline__ void cp16(u32 dst, const void* src) {
    asm volatile("cp.async.cg.shared.global [%0], [%1], 16;" :: "r"(dst), "l"(src));
}
#define CP_COMMIT() asm volatile("cp.async.commit_group;" ::: "memory")
#define CP_WAIT(n)  asm volatile("cp.async.wait_group %0;" :: "n"(n) : "memory")

__device__ __forceinline__ void split_bf(float v, u16& h, u16& l) {
    __nv_bfloat16 bh = __float2bfloat16_rn(v);
    float r = v - __bfloat162float(bh);
    __nv_bfloat16 bl = __float2bfloat16_rn(r);
    h = reinterpret_cast<u16&>(bh);
    l = reinterpret_cast<u16&>(bl);
}

// ============================================================
// Elementwise split-convert: fp32 [T][D] -> bf16 hi/lo
// mode 0: src_x -> gx;  mode 1: g_enc -> ge  (src selected in
// DEVICE code — host must never reference __device__ symbols)
// ============================================================
__global__ void convert_hl(const float* __restrict__ src_x, int mode)
{
    const float* __restrict__ src = mode ? (const float*)g_enc : src_x;
    u16* __restrict__ h = mode ? ge_h : gx_h;
    u16* __restrict__ l = mode ? ge_l : gx_l;
    int i = (blockIdx.x * 256 + threadIdx.x) * 4;
    float4 v = *reinterpret_cast<const float4*>(src + i);
    u16 h0, h1, h2, h3, l0, l1, l2, l3;
    split_bf(v.x, h0, l0); split_bf(v.y, h1, l1);
    split_bf(v.z, h2, l2); split_bf(v.w, h3, l3);
    ull hp = (ull)h0 | ((ull)h1 << 16) | ((ull)h2 << 32) | ((ull)h3 << 48);
    ull lp = (ull)l0 | ((ull)l1 << 16) | ((ull)l2 << 32) | ((ull)l3 << 48);
    *reinterpret_cast<ull*>(h + i) = hp;
    *reinterpret_cast<ull*>(l + i) = lp;
}

// ============================================================
// Weight transpose + split-convert, 32x32 tiles.
// ============================================================
__global__ void wconv(const float* __restrict__ qw, const float* __restrict__ kvw,
                      const float* __restrict__ ow, int mode)
{
    __shared__ float s[32][33];
    const int c0 = blockIdx.x * 32;
    const int k0 = blockIdx.y * 32;
    const int tx = threadIdx.x & 31;
    const int ty = threadIdx.x >> 5;
    u16* __restrict__ dh = mode ? gwo_h : gw_h;
    u16* __restrict__ dl = mode ? gwo_l : gw_l;

#pragma unroll
    for (int rr = ty; rr < 32; rr += 8) {
        int k = k0 + rr;
        int c = c0 + tx;
        float v;
        if (mode == 0) {
            const float* base;
            int cc = c;
            if (cc < 2048)      base = qw + (cc >> 7) * (D_DIM * HD);
            else if (cc < 3072) { cc -= 2048; base = kvw + (cc >> 7) * (D_DIM * HD); }
            else                { cc -= 3072; base = kvw + (8 + (cc >> 7)) * (D_DIM * HD); }
            v = base[k * HD + (cc & 127)];
        } else {
            v = ow[k * D_DIM + c];
        }
        s[tx][rr] = v;
    }
    __syncthreads();
#pragma unroll
    for (int rr = ty; rr < 32; rr += 8) {
        float v = s[rr][tx];
        u16 h, l;
        split_bf(v, h, l);
        dh[(c0 + rr) * D_DIM + k0 + tx] = h;
        dl[(c0 + rr) * D_DIM + k0 + tx] = l;
    }
}

// ============================================================
// HMMA GEMM: C[128x128] tile, K=2048, split-bf16 (3 mma/step).
// A = activations [row][k], B = weights [col][k] (= .col layout).
// Smem: 2 stages x (Ah 16K | Al 16K | Bh 16K | Bl 16K), SW rows.
// ============================================================
#define STAGE_BYTES 65536
#define GEMM_SMEM (2 * STAGE_BYTES)

__device__ __forceinline__ void load_stage(
    u32 sbase, int p, int tid, int row0, int col0, int kk,
    const u16* __restrict__ Ah, const u16* __restrict__ Al,
    const u16* __restrict__ Bh, const u16* __restrict__ Bl)
{
    u32 stg = sbase + (u32)p * STAGE_BYTES;
#pragma unroll
    for (int l = 0; l < 4; ++l) {
        int idx = tid + l * 256;
        int r = idx >> 3;
        int ch = idx & 7;
        u32 doff = (u32)(r * 128) + (u32)((ch * 16) ^ ((r & 7) << 4));
        int aoff = (row0 + r) * D_DIM + kk + ch * 8;
        int boff = (col0 + r) * D_DIM + kk + ch * 8;
        cp16(stg + doff,             Ah + aoff);
        cp16(stg + 16384 + doff,     Al + aoff);
        cp16(stg + 32768 + doff,     Bh + boff);
        cp16(stg + 49152 + doff,     Bl + boff);
    }
}

__global__ __launch_bounds__(256, 1)
void hmma_gemm(float* __restrict__ dst0, int ldc0, int qkv_mode)
{
    extern __shared__ char smem[];
    const u32 sb = smem_u32(smem);
    const int tid = threadIdx.x;
    const int lane = tid & 31;
    const int w = tid >> 5;
    const int wm = w & 3;          // M group: rows wm*32
    const int wn = w >> 2;         // N group: cols wn*64
    const int row0 = blockIdx.y * 128;
    const int col0 = blockIdx.x * 128;

    const u16 *Ah, *Al, *Bh, *Bl;
    float* dst; int ldc, cofs;
    if (qkv_mode) {
        Ah = gx_h; Al = gx_l; Bh = gw_h; Bl = gw_l;
        if (col0 < 2048)      { dst = g_q; ldc = 2048; cofs = col0; }
        else if (col0 < 3072) { dst = g_k; ldc = 1024; cofs = col0 - 2048; }
        else                  { dst = g_v; ldc = 1024; cofs = col0 - 3072; }
    } else {
        Ah = ge_h; Al = ge_l; Bh = gwo_h; Bl = gwo_l;
        dst = dst0; ldc = ldc0; cofs = col0;
    }

    float acc[2][8][4];
#pragma unroll
    for (int i = 0; i < 2; ++i)
#pragma unroll
        for (int j = 0; j < 8; ++j)
#pragma unroll
            for (int q = 0; q < 4; ++q) acc[i][j][q] = 0.0f;

    // per-lane ldmatrix address components
    const u32 aRow = (u32)(wm * 32 + (lane & 15)) * 128;
    const u32 aXor = (u32)((lane & 7) << 4);
    const u32 aK   = (u32)((lane >> 4) * 16);
    const u32 bRow = (u32)(wn * 64 + ((lane >> 4) << 3) + (lane & 7)) * 128;
    const u32 bXor = aXor;
    const u32 bK   = (u32)(((lane >> 3) & 1) * 16);

    load_stage(sb, 0, tid, row0, col0, 0, Ah, Al, Bh, Bl);
    CP_COMMIT();

    for (int c = 0; c < 32; ++c) {
        if (c < 31) {
            load_stage(sb, (c + 1) & 1, tid, row0, col0, (c + 1) * 64, Ah, Al, Bh, Bl);
            CP_COMMIT();
            CP_WAIT(1);
        } else {
            CP_WAIT(0);
        }
        __syncthreads();

        const u32 stg = sb + (u32)(c & 1) * STAGE_BYTES;
#pragma unroll
        for (int ks = 0; ks < 4; ++ks) {
            const u32 kb = (u32)(ks * 32);
            u32 ah[2][4], al[2][4];
#pragma unroll
            for (int mi = 0; mi < 2; ++mi) {
                u32 ao = aRow + (u32)(mi * 2048) + ((aK + kb) ^ aXor);
                ldsm4(ah[mi], stg + ao);
                ldsm4(al[mi], stg + 16384 + ao);
            }
#pragma unroll
            for (int n4 = 0; n4 < 4; ++n4) {
                u32 bo = bRow + (u32)(n4 * 2048) + ((bK + kb) ^ bXor);
                u32 bh[4], bl[4];
                ldsm4(bh, stg + 32768 + bo);
                ldsm4(bl, stg + 49152 + bo);
#pragma unroll
                for (int mi = 0; mi < 2; ++mi) {
                    mma_bf16(acc[mi][2 * n4],     ah[mi], bh[0], bh[1]);
                    mma_bf16(acc[mi][2 * n4 + 1], ah[mi], bh[2], bh[3]);
                    mma_bf16(acc[mi][2 * n4],     ah[mi], bl[0], bl[1]);
                    mma_bf16(acc[mi][2 * n4 + 1], ah[mi], bl[2], bl[3]);
                    mma_bf16(acc[mi][2 * n4],     al[mi], bh[0], bh[1]);
                    mma_bf16(acc[mi][2 * n4 + 1], al[mi], bh[2], bh[3]);
                }
            }
        }
        __syncthreads();
    }

    // epilogue: direct float2 stores
    const int rbase = row0 + wm * 32 + (lane >> 2);
    const int cbase = cofs + wn * 64 + (lane & 3) * 2;
#pragma unroll
    for (int mi = 0; mi < 2; ++mi) {
#pragma unroll
        for (int nt = 0; nt < 8; ++nt) {
            int r = rbase + mi * 16;
            int cc = cbase + nt * 8;
            *reinterpret_cast<float2*>(dst + r * ldc + cc) =
                make_float2(acc[mi][nt][0], acc[mi][nt][1]);
            *reinterpret_cast<float2*>(dst + (r + 8) * ldc + cc) =
                make_float2(acc[mi][nt][2], acc[mi][nt][3]);
        }
    }
}

// ============================================================
// RoPE on q (scaled) and k, in place.
// ============================================================
__global__ void rope_kernel(const int* __restrict__ seg)
{
    __shared__ float s_ts[64];
    const int t = blockIdx.x;
    const int tid = threadIdx.x;
    if (tid < 64) {
        double f = (double)tid / 64.0;
        s_ts[tid] = (float)pow(10000.0, f);
    }
    __syncthreads();
    const float pos = (float)seg[t];
    for (int idx = tid; idx < (NQH + NKH) * 64; idx += 256) {
        int head = idx >> 6;
        int i = idx & 63;
        float* base = (head < NQH) ? (g_q + t * (NQH * HD) + head * HD)
                                   : (g_k + t * (NKH * HD) + (head - NQH) * HD);
        float ang = pos / s_ts[i];
        float sv, cv;
        sincosf(ang, &sv, &cv);
        float x1 = base[i], x2 = base[i + 64];
        float o1 = x1 * cv - x2 * sv;
        float o2 = x2 * cv + x1 * sv;
        if (head < NQH) { o1 *= QSCALE; o2 *= QSCALE; }
        base[i] = o1;
        base[i + 64] = o2;
    }
}

// ============================================================
// Sliding-window attention (SIMT f32x2) — known-good from R1.
// ============================================================
#define SST 68
#define ATT_SMEM ((128*128 + 64*128 + 64*128 + 128*SST + 256) * 4)

__global__ __launch_bounds__(256, 1) void attn_kernel()
{
    extern __shared__ float sm[];
    float* Qs = sm;
    float* Ks = Qs + 128 * 128;
    float* Vs = Ks + 64 * 128;
    float* Ss = Vs + 64 * 128;
    float* al_s = Ss + 128 * SST;
    float* l_s = al_s + 128;

    const int kh = blockIdx.x;
    const int t0 = blockIdx.y * 64;
    const int tid = threadIdx.x;
    const int tx = tid & 15;
    const int ty = tid >> 4;

#pragma unroll
    for (int l = 0; l < 16; ++l) {
        int idx = tid + l * 256;
        int r = idx >> 5;
        int c = (idx & 31) << 2;
        int t = t0 + (r & 63);
        int n = kh * 2 + (r >> 6);
        *reinterpret_cast<float4*>(&Qs[r * 128 + c]) =
            *reinterpret_cast<const float4*>(&g_q[t * (NQH * HD) + n * HD + c]);
    }

    ull acc[8][4];
#pragma unroll
    for (int i = 0; i < 8; ++i)
#pragma unroll
        for (int j = 0; j < 4; ++j) acc[i][j] = 0ull;

    float m_reg = -1e30f, l_reg = 0.0f;
    int s_begin = (t0 >= (WINDOW - 1)) ? ((t0 - (WINDOW - 1)) & ~63) : 0;

    for (int st = s_begin; st < t0 + 64; st += 64) {
#pragma unroll
        for (int l = 0; l < 8; ++l) {
            int idx = tid + l * 256;
            int r = idx >> 5;
            int c = (idx & 31) << 2;
            *reinterpret_cast<float4*>(&Ks[r * 128 + c]) =
                *reinterpret_cast<const float4*>(&g_k[(st + r) * (NKH * HD) + kh * HD + c]);
            *reinterpret_cast<float4*>(&Vs[r * 128 + c]) =
                *reinterpret_cast<const float4*>(&g_v[(st + r) * (NKH * HD) + kh * HD + c]);
        }
        __syncthreads();

        ull sa[8][4];
#pragma unroll
        for (int i = 0; i < 8; ++i)
#pragma unroll
            for (int j = 0; j < 4; ++j) sa[i][j] = 0ull;
#pragma unroll 4
        for (int h = 0; h < 128; h += 2) {
            ull q2[8], k2[4];
#pragma unroll
            for (int i = 0; i < 8; ++i)
                q2[i] = *reinterpret_cast<const ull*>(&Qs[(ty * 8 + i) * 128 + h]);
#pragma unroll
            for (int j = 0; j < 4; ++j)
                k2[j] = *reinterpret_cast<const ull*>(&Ks[(tx * 4 + j) * 128 + h]);
#pragma unroll
            for (int i = 0; i < 8; ++i)
#pragma unroll
                for (int j = 0; j < 4; ++j) fma2(sa[i][j], q2[i], k2[j]);
        }
#pragma unroll
        for (int i = 0; i < 8; ++i) {
            int r = ty * 8 + i;
            int t = t0 + (r & 63);
#pragma unroll
            for (int j = 0; j < 4; ++j) {
                int s = st + tx * 4 + j;
                float2 f = up2(sa[i][j]);
                float raw = f.x + f.y;
                float capped = tanhf(raw * (1.0f / SOFTCAP)) * SOFTCAP;
                bool ok = (s <= t) && (s > t - WINDOW);
                Ss[r * SST + tx * 4 + j] = ok ? capped : -1e30f;
            }
        }
        __syncthreads();

        if (tid < 128) {
            float tm = -1e30f;
#pragma unroll 8
            for (int c = 0; c < 64; ++c) tm = fmaxf(tm, Ss[tid * SST + c]);
            float mnew = fmaxf(m_reg, tm);
            float a = expf(m_reg - mnew);
            float lsum = 0.0f;
#pragma unroll 8
            for (int c = 0; c < 64; ++c) {
                float p = expf(Ss[tid * SST + c] - mnew);
                Ss[tid * SST + c] = p;
                lsum += p;
            }
            l_reg = l_reg * a + lsum;
            m_reg = mnew;
            al_s[tid] = a;
        }
        __syncthreads();

#pragma unroll
        for (int i = 0; i < 8; ++i) {
            float a = al_s[ty * 8 + i];
            ull a2 = pk2(a, a);
#pragma unroll
            for (int j = 0; j < 4; ++j) mul2(acc[i][j], a2);
        }
#pragma unroll 2
        for (int s = 0; s < 64; ++s) {
            ull v2[4];
#pragma unroll
            for (int j = 0; j < 4; ++j)
                v2[j] = *reinterpret_cast<const ull*>(&Vs[s * 128 + tx * 8 + 2 * j]);
#pragma unroll
            for (int i = 0; i < 8; ++i) {
                float p = Ss[(ty * 8 + i) * SST + s];
                ull p2 = pk2(p, p);
#pragma unroll
                for (int j = 0; j < 4; ++j) fma2(acc[i][j], p2, v2[j]);
            }
        }
        __syncthreads();
    }

    if (tid < 128) l_s[tid] = l_reg;
    __syncthreads();

#pragma unroll
    for (int i = 0; i < 8; ++i) {
        int r = ty * 8 + i;
        float inv = 1.0f / l_s[r];
        int t = t0 + (r & 63);
        int n = kh * 2 + (r >> 6);
        float o[8];
#pragma unroll
        for (int j = 0; j < 4; ++j) {
            float2 f = up2(acc[i][j]);
            o[2 * j] = f.x * inv;
            o[2 * j + 1] = f.y * inv;
        }
        float* dp = &g_enc[t * (NQH * HD) + n * HD + tx * 8];
        *reinterpret_cast<float4*>(dp) = make_float4(o[0], o[1], o[2], o[3]);
        *reinterpret_cast<float4*>(dp + 4) = make_float4(o[4], o[5], o[6], o[7]);
    }
}

// ============================================================
extern "C" void kernel_launch(void* const* d_in, const int* in_sizes, int n_in,
                              void* d_out, int out_size)
{
    (void)in_sizes; (void)n_in; (void)out_size;
    const float* x   = (const float*)d_in[0];
    const int*   seg = (const int*)d_in[1];
    const float* qw  = (const float*)d_in[3];
    const float* kvw = (const float*)d_in[4];
    const float* ow  = (const float*)d_in[5];
    float* out = (float*)d_out;

    cudaFuncSetAttribute(attn_kernel, cudaFuncAttributeMaxDynamicSharedMemorySize, ATT_SMEM);
    cudaFuncSetAttribute(hmma_gemm, cudaFuncAttributeMaxDynamicSharedMemorySize, GEMM_SMEM);

    convert_hl<<<4096, 256>>>(x, 0);
    wconv<<<dim3(128, 64), 256>>>(qw, kvw, ow, 0);
    wconv<<<dim3(64, 64), 256>>>(qw, kvw, ow, 1);
    hmma_gemm<<<dim3(32, 16), 256, GEMM_SMEM>>>(nullptr, 0, 1);   // qkv
    rope_kernel<<<T_DIM, 256>>>(seg);
    attn_kernel<<<dim3(NKH, T_DIM / 64), 256, ATT_SMEM>>>();
    convert_hl<<<4096, 256>>>(x, 1);                               // src ignored (g_enc)
    hmma_gemm<<<dim3(16, 16), 256, GEMM_SMEM>>>(out, D_DIM, 0);   // out proj
}

// round 6
// speedup vs baseline: 2.7582x; 1.7086x over previous
#include <cuda_runtime.h>
#include <cuda_bf16.h>
#include <math.h>

typedef unsigned long long ull;
typedef unsigned int u32;
typedef unsigned short u16;

#define T_DIM 2048
#define D_DIM 2048
#define NQH 16
#define NKH 8
#define HD 128
#define WINDOW 1024
#define SOFTCAP 50.0f
#define QSCALE 0.08838834764831845f
#define QELEMS (T_DIM * NQH * HD)
#define KVELEMS (T_DIM * NKH * HD)

// fp32 scratch
__device__ float g_q[QELEMS];
__device__ float g_k[KVELEMS];
__device__ float g_v[KVELEMS];
__device__ float g_enc[QELEMS];

// bf16 split operands
__device__ u16 gx_h[T_DIM * D_DIM], gx_l[T_DIM * D_DIM];
__device__ u16 ge_h[T_DIM * D_DIM], ge_l[T_DIM * D_DIM];
__device__ u16 gw_h[4096 * D_DIM], gw_l[4096 * D_DIM];
__device__ u16 gwo_h[D_DIM * D_DIM], gwo_l[D_DIM * D_DIM];
__device__ u16 gq_h[QELEMS], gq_l[QELEMS];
__device__ u16 gk_h[KVELEMS], gk_l[KVELEMS];
__device__ u16 gv_h[KVELEMS], gv_l[KVELEMS];

__device__ __forceinline__ u32 smem_u32(const void* p) {
    u32 a; asm("{ .reg .u64 t; cvta.to.shared.u64 t, %1; cvt.u32.u64 %0, t; }" : "=r"(a) : "l"(p));
    return a;
}
__device__ __forceinline__ void ldsm4(u32* r, u32 addr) {
    asm volatile("ldmatrix.sync.aligned.m8n8.x4.shared.b16 {%0,%1,%2,%3}, [%4];"
        : "=r"(r[0]), "=r"(r[1]), "=r"(r[2]), "=r"(r[3]) : "r"(addr));
}
__device__ __forceinline__ void ldsm4t(u32* r, u32 addr) {
    asm volatile("ldmatrix.sync.aligned.m8n8.x4.trans.shared.b16 {%0,%1,%2,%3}, [%4];"
        : "=r"(r[0]), "=r"(r[1]), "=r"(r[2]), "=r"(r[3]) : "r"(addr));
}
__device__ __forceinline__ void mma_bf16(float* c, const u32* a, u32 b0, u32 b1) {
    asm volatile("mma.sync.aligned.m16n8k16.row.col.f32.bf16.bf16.f32 "
        "{%0,%1,%2,%3}, {%4,%5,%6,%7}, {%8,%9}, {%0,%1,%2,%3};"
        : "+f"(c[0]), "+f"(c[1]), "+f"(c[2]), "+f"(c[3])
        : "r"(a[0]), "r"(a[1]), "r"(a[2]), "r"(a[3]), "r"(b0), "r"(b1));
}
__device__ __forceinline__ void cp16(u32 dst, const void* src) {
    asm volatile("cp.async.cg.shared.global [%0], [%1], 16;" :: "r"(dst), "l"(src));
}
#define CP_COMMIT() asm volatile("cp.async.commit_group;" ::: "memory")
#define CP_WAIT(n)  asm volatile("cp.async.wait_group %0;" :: "n"(n) : "memory")

__device__ __forceinline__ void split_bf(float v, u16& h, u16& l) {
    __nv_bfloat16 bh = __float2bfloat16_rn(v);
    float r = v - __bfloat162float(bh);
    __nv_bfloat16 bl = __float2bfloat16_rn(r);
    h = reinterpret_cast<u16&>(bh);
    l = reinterpret_cast<u16&>(bl);
}
__device__ __forceinline__ float tanh_fast(float x) {
    float c = fminf(fmaxf(x, -12.0f), 12.0f);
    float e = __expf(2.0f * c);
    return (e - 1.0f) / (e + 1.0f);
}

// ============================================================
// Elementwise split-convert: fp32 [T][D] -> bf16 hi/lo
// ============================================================
__global__ void convert_hl(const float* __restrict__ src_x, int mode)
{
    const float* __restrict__ src = mode ? (const float*)g_enc : src_x;
    u16* __restrict__ h = mode ? ge_h : gx_h;
    u16* __restrict__ l = mode ? ge_l : gx_l;
    int i = (blockIdx.x * 256 + threadIdx.x) * 4;
    float4 v = *reinterpret_cast<const float4*>(src + i);
    u16 h0, h1, h2, h3, l0, l1, l2, l3;
    split_bf(v.x, h0, l0); split_bf(v.y, h1, l1);
    split_bf(v.z, h2, l2); split_bf(v.w, h3, l3);
    *reinterpret_cast<ull*>(h + i) = (ull)h0 | ((ull)h1 << 16) | ((ull)h2 << 32) | ((ull)h3 << 48);
    *reinterpret_cast<ull*>(l + i) = (ull)l0 | ((ull)l1 << 16) | ((ull)l2 << 32) | ((ull)l3 << 48);
}

// ============================================================
// Split q/k/v (post-rope) into bf16 hi/lo
// ============================================================
__global__ void split_qkv()
{
    int i = (blockIdx.x * 256 + threadIdx.x) * 4;
    const float* src; u16 *dh, *dl; int off;
    if (i < QELEMS)                 { src = g_q; dh = gq_h; dl = gq_l; off = i; }
    else if (i < QELEMS + KVELEMS)  { src = g_k; dh = gk_h; dl = gk_l; off = i - QELEMS; }
    else                            { src = g_v; dh = gv_h; dl = gv_l; off = i - QELEMS - KVELEMS; }
    float4 v = *reinterpret_cast<const float4*>(src + off);
    u16 h0, h1, h2, h3, l0, l1, l2, l3;
    split_bf(v.x, h0, l0); split_bf(v.y, h1, l1);
    split_bf(v.z, h2, l2); split_bf(v.w, h3, l3);
    *reinterpret_cast<ull*>(dh + off) = (ull)h0 | ((ull)h1 << 16) | ((ull)h2 << 32) | ((ull)h3 << 48);
    *reinterpret_cast<ull*>(dl + off) = (ull)l0 | ((ull)l1 << 16) | ((ull)l2 << 32) | ((ull)l3 << 48);
}

// ============================================================
// Weight transpose + split-convert, 32x32 tiles.
// ============================================================
__global__ void wconv(const float* __restrict__ qw, const float* __restrict__ kvw,
                      const float* __restrict__ ow, int mode)
{
    __shared__ float s[32][33];
    const int c0 = blockIdx.x * 32;
    const int k0 = blockIdx.y * 32;
    const int tx = threadIdx.x & 31;
    const int ty = threadIdx.x >> 5;
    u16* __restrict__ dh = mode ? gwo_h : gw_h;
    u16* __restrict__ dl = mode ? gwo_l : gw_l;

#pragma unroll
    for (int rr = ty; rr < 32; rr += 8) {
        int k = k0 + rr;
        int c = c0 + tx;
        float v;
        if (mode == 0) {
            const float* base;
            int cc = c;
            if (cc < 2048)      base = qw + (cc >> 7) * (D_DIM * HD);
            else if (cc < 3072) { cc -= 2048; base = kvw + (cc >> 7) * (D_DIM * HD); }
            else                { cc -= 3072; base = kvw + (8 + (cc >> 7)) * (D_DIM * HD); }
            v = base[k * HD + (cc & 127)];
        } else {
            v = ow[k * D_DIM + c];
        }
        s[tx][rr] = v;
    }
    __syncthreads();
#pragma unroll
    for (int rr = ty; rr < 32; rr += 8) {
        float v = s[rr][tx];
        u16 h, l;
        split_bf(v, h, l);
        dh[(c0 + rr) * D_DIM + k0 + tx] = h;
        dl[(c0 + rr) * D_DIM + k0 + tx] = l;
    }
}

// ============================================================
// HMMA GEMM (unchanged, R4-verified)
// ============================================================
#define STAGE_BYTES 65536
#define GEMM_SMEM (2 * STAGE_BYTES)

__device__ __forceinline__ void load_stage(
    u32 sbase, int p, int tid, int row0, int col0, int kk,
    const u16* __restrict__ Ah, const u16* __restrict__ Al,
    const u16* __restrict__ Bh, const u16* __restrict__ Bl)
{
    u32 stg = sbase + (u32)p * STAGE_BYTES;
#pragma unroll
    for (int l = 0; l < 4; ++l) {
        int idx = tid + l * 256;
        int r = idx >> 3;
        int ch = idx & 7;
        u32 doff = (u32)(r * 128) + (u32)((ch * 16) ^ ((r & 7) << 4));
        int aoff = (row0 + r) * D_DIM + kk + ch * 8;
        int boff = (col0 + r) * D_DIM + kk + ch * 8;
        cp16(stg + doff,             Ah + aoff);
        cp16(stg + 16384 + doff,     Al + aoff);
        cp16(stg + 32768 + doff,     Bh + boff);
        cp16(stg + 49152 + doff,     Bl + boff);
    }
}

__global__ __launch_bounds__(256, 1)
void hmma_gemm(float* __restrict__ dst0, int ldc0, int qkv_mode)
{
    extern __shared__ char smem[];
    const u32 sb = smem_u32(smem);
    const int tid = threadIdx.x;
    const int lane = tid & 31;
    const int w = tid >> 5;
    const int wm = w & 3;
    const int wn = w >> 2;
    const int row0 = blockIdx.y * 128;
    const int col0 = blockIdx.x * 128;

    const u16 *Ah, *Al, *Bh, *Bl;
    float* dst; int ldc, cofs;
    if (qkv_mode) {
        Ah = gx_h; Al = gx_l; Bh = gw_h; Bl = gw_l;
        if (col0 < 2048)      { dst = g_q; ldc = 2048; cofs = col0; }
        else if (col0 < 3072) { dst = g_k; ldc = 1024; cofs = col0 - 2048; }
        else                  { dst = g_v; ldc = 1024; cofs = col0 - 3072; }
    } else {
        Ah = ge_h; Al = ge_l; Bh = gwo_h; Bl = gwo_l;
        dst = dst0; ldc = ldc0; cofs = col0;
    }

    float acc[2][8][4];
#pragma unroll
    for (int i = 0; i < 2; ++i)
#pragma unroll
        for (int j = 0; j < 8; ++j)
#pragma unroll
            for (int q = 0; q < 4; ++q) acc[i][j][q] = 0.0f;

    const u32 aRow = (u32)(wm * 32 + (lane & 15)) * 128;
    const u32 aXor = (u32)((lane & 7) << 4);
    const u32 aK   = (u32)((lane >> 4) * 16);
    const u32 bRow = (u32)(wn * 64 + ((lane >> 4) << 3) + (lane & 7)) * 128;
    const u32 bK   = (u32)(((lane >> 3) & 1) * 16);

    load_stage(sb, 0, tid, row0, col0, 0, Ah, Al, Bh, Bl);
    CP_COMMIT();

    for (int c = 0; c < 32; ++c) {
        if (c < 31) {
            load_stage(sb, (c + 1) & 1, tid, row0, col0, (c + 1) * 64, Ah, Al, Bh, Bl);
            CP_COMMIT();
            CP_WAIT(1);
        } else {
            CP_WAIT(0);
        }
        __syncthreads();

        const u32 stg = sb + (u32)(c & 1) * STAGE_BYTES;
#pragma unroll
        for (int ks = 0; ks < 4; ++ks) {
            const u32 kb = (u32)(ks * 32);
            u32 ah[2][4], al[2][4];
#pragma unroll
            for (int mi = 0; mi < 2; ++mi) {
                u32 ao = aRow + (u32)(mi * 2048) + ((aK + kb) ^ aXor);
                ldsm4(ah[mi], stg + ao);
                ldsm4(al[mi], stg + 16384 + ao);
            }
#pragma unroll
            for (int n4 = 0; n4 < 4; ++n4) {
                u32 bo = bRow + (u32)(n4 * 2048) + ((bK + kb) ^ aXor);
                u32 bh[4], bl[4];
                ldsm4(bh, stg + 32768 + bo);
                ldsm4(bl, stg + 49152 + bo);
#pragma unroll
                for (int mi = 0; mi < 2; ++mi) {
                    mma_bf16(acc[mi][2 * n4],     ah[mi], bh[0], bh[1]);
                    mma_bf16(acc[mi][2 * n4 + 1], ah[mi], bh[2], bh[3]);
                    mma_bf16(acc[mi][2 * n4],     ah[mi], bl[0], bl[1]);
                    mma_bf16(acc[mi][2 * n4 + 1], ah[mi], bl[2], bl[3]);
                    mma_bf16(acc[mi][2 * n4],     al[mi], bh[0], bh[1]);
                    mma_bf16(acc[mi][2 * n4 + 1], al[mi], bh[2], bh[3]);
                }
            }
        }
        __syncthreads();
    }

    const int rbase = row0 + wm * 32 + (lane >> 2);
    const int cbase = cofs + wn * 64 + (lane & 3) * 2;
#pragma unroll
    for (int mi = 0; mi < 2; ++mi) {
#pragma unroll
        for (int nt = 0; nt < 8; ++nt) {
            int r = rbase + mi * 16;
            int cc = cbase + nt * 8;
            *reinterpret_cast<float2*>(dst + r * ldc + cc) =
                make_float2(acc[mi][nt][0], acc[mi][nt][1]);
            *reinterpret_cast<float2*>(dst + (r + 8) * ldc + cc) =
                make_float2(acc[mi][nt][2], acc[mi][nt][3]);
        }
    }
}

// ============================================================
// RoPE on q (scaled) and k, in place.
// ============================================================
__global__ void rope_kernel(const int* __restrict__ seg)
{
    __shared__ float s_ts[64];
    const int t = blockIdx.x;
    const int tid = threadIdx.x;
    if (tid < 64) {
        double f = (double)tid / 64.0;
        s_ts[tid] = (float)pow(10000.0, f);
    }
    __syncthreads();
    const float pos = (float)seg[t];
    for (int idx = tid; idx < (NQH + NKH) * 64; idx += 256) {
        int head = idx >> 6;
        int i = idx & 63;
        float* base = (head < NQH) ? (g_q + t * (NQH * HD) + head * HD)
                                   : (g_k + t * (NKH * HD) + (head - NQH) * HD);
        float ang = pos / s_ts[i];
        float sv, cv;
        sincosf(ang, &sv, &cv);
        float x1 = base[i], x2 = base[i + 64];
        float o1 = x1 * cv - x2 * sv;
        float o2 = x2 * cv + x1 * sv;
        if (head < NQH) { o1 *= QSCALE; o2 *= QSCALE; }
        base[i] = o1;
        base[i + 64] = o2;
    }
}

// ============================================================
// Tensor-core sliding-window attention (split-bf16, 3-mma).
// Block: (kv head, 64 q) -> 128 rows (2 q-heads x 64 q).
// ============================================================
#define SMEM_Q  0
#define SMEM_K  65536
#define SMEM_V  98304
#define SMEM_S  131072
#define SMEM_P  165888
#define SMEM_AL 198656
#define SMEM_L  199168
#define ATT2_SMEM 199680

__global__ __launch_bounds__(256, 1) void attn_mma()
{
    extern __shared__ char smc[];
    const u32 sb = smem_u32(smc);
    float* S = reinterpret_cast<float*>(smc + SMEM_S);
    float* al_s = reinterpret_cast<float*>(smc + SMEM_AL);
    float* l_s = reinterpret_cast<float*>(smc + SMEM_L);

    const int tid = threadIdx.x;
    const int lane = tid & 31;
    const int w = tid >> 5;
    const int wm = w & 3;
    const int wn = w >> 2;
    const int kh = blockIdx.x;
    const int t0 = (int)(31 - blockIdx.y) * 64;   // long blocks first

    // ---- Q tile load (cp.async, split halves) ----
#pragma unroll
    for (int l = 0; l < 8; ++l) {
        int idx = tid + l * 256;          // 2048: 128 rows x 16 chunks
        int r = idx >> 4, ch = idx & 15;
        int t = t0 + (r & 63), n = kh * 2 + (r >> 6);
        u32 d = (u32)((ch >> 3) * 16384 + r * 128 + (((ch & 7) * 16) ^ ((r & 7) << 4)));
        const u16* sh = gq_h + (size_t)(t * NQH + n) * HD + ch * 8;
        const u16* sl = gq_l + (size_t)(t * NQH + n) * HD + ch * 8;
        cp16(sb + SMEM_Q + d, sh);
        cp16(sb + SMEM_Q + 32768 + d, sl);
    }
    CP_COMMIT();

    float acc_o[2][8][4];
#pragma unroll
    for (int i = 0; i < 2; ++i)
#pragma unroll
        for (int j = 0; j < 8; ++j)
#pragma unroll
            for (int q = 0; q < 4; ++q) acc_o[i][j][q] = 0.0f;

    float m_reg = -1e30f, l_reg = 0.0f;

    const u32 aRow = (u32)((wm * 32 + (lane & 15)) * 128);
    const u32 aK   = (u32)((lane >> 4) * 16);
    const u32 aXor = (u32)((lane & 7) << 4);
    const u32 bK   = (u32)(((lane >> 3) & 1) * 16);
    u32 bRow[2];
    bRow[0] = (u32)((wn * 32 + ((lane >> 4) << 3) + (lane & 7)) * 128);
    bRow[1] = bRow[0] + 16 * 128;
    const int vrow_in = (lane & 7) + (lane & 8);       // 0..15
    const u32 vh8 = (u32)((lane >> 4) << 3);           // 0 or 8

    const int s_begin = (t0 >= (WINDOW - 1)) ? ((t0 - (WINDOW - 1)) & ~63) : 0;

    for (int st = s_begin; st <= t0; st += 64) {
        // ---- K/V tile load ----
#pragma unroll
        for (int l = 0; l < 4; ++l) {
            int idx = tid + l * 256;      // 1024: 64 rows x 16 chunks
            int r = idx >> 4, ch = idx & 15;
            size_t go = (size_t)((st + r) * NKH + kh) * HD + ch * 8;
            u32 dk = (u32)((ch >> 3) * 8192 + r * 128 + (((ch & 7) * 16) ^ ((r & 7) << 4)));
            u32 dv = (u32)(r * 256 + ((ch * 16) ^ ((r & 7) << 4)));
            cp16(sb + SMEM_K + dk,         gk_h + go);
            cp16(sb + SMEM_K + 16384 + dk, gk_l + go);
            cp16(sb + SMEM_V + dv,         gv_h + go);
            cp16(sb + SMEM_V + 16384 + dv, gv_l + go);
        }
        CP_COMMIT();
        CP_WAIT(0);
        __syncthreads();

        // ---- S = Q K^T (split, 3 mma) ----
        float s_acc[2][4][4];
#pragma unroll
        for (int i = 0; i < 2; ++i)
#pragma unroll
            for (int j = 0; j < 4; ++j)
#pragma unroll
                for (int q = 0; q < 4; ++q) s_acc[i][j][q] = 0.0f;

#pragma unroll
        for (int ks = 0; ks < 8; ++ks) {
            const u32 kc = (u32)(ks >> 2);
            const u32 kb = (u32)((ks & 3) * 32);
            u32 qh[2][4], ql[2][4];
#pragma unroll
            for (int mi = 0; mi < 2; ++mi) {
                u32 ao = kc * 16384 + aRow + (u32)(mi * 2048) + ((aK + kb) ^ aXor);
                ldsm4(qh[mi], sb + SMEM_Q + ao);
                ldsm4(ql[mi], sb + SMEM_Q + 32768 + ao);
            }
#pragma unroll
            for (int g = 0; g < 2; ++g) {
                u32 bo = kc * 8192 + bRow[g] + ((bK + kb) ^ aXor);
                u32 kf[4], klf[4];
                ldsm4(kf,  sb + SMEM_K + bo);
                ldsm4(klf, sb + SMEM_K + 16384 + bo);
#pragma unroll
                for (int mi = 0; mi < 2; ++mi) {
                    mma_bf16(s_acc[mi][2 * g],     qh[mi], kf[0],  kf[1]);
                    mma_bf16(s_acc[mi][2 * g],     qh[mi], klf[0], klf[1]);
                    mma_bf16(s_acc[mi][2 * g],     ql[mi], kf[0],  kf[1]);
                    mma_bf16(s_acc[mi][2 * g + 1], qh[mi], kf[2],  kf[3]);
                    mma_bf16(s_acc[mi][2 * g + 1], qh[mi], klf[2], klf[3]);
                    mma_bf16(s_acc[mi][2 * g + 1], ql[mi], kf[2],  kf[3]);
                }
            }
        }

        // ---- softcap + mask in fragments, store S ----
#pragma unroll
        for (int mi = 0; mi < 2; ++mi) {
            int r0 = wm * 32 + mi * 16 + (lane >> 2);
#pragma unroll
            for (int n8 = 0; n8 < 4; ++n8) {
                int sl0 = wn * 32 + n8 * 8 + (lane & 3) * 2;
#pragma unroll
                for (int half = 0; half < 2; ++half) {
                    int rr = r0 + half * 8;
                    int t = t0 + (rr & 63);
                    float v0 = tanh_fast(s_acc[mi][n8][half * 2]     * (1.0f / SOFTCAP)) * SOFTCAP;
                    float v1 = tanh_fast(s_acc[mi][n8][half * 2 + 1] * (1.0f / SOFTCAP)) * SOFTCAP;
                    int sg0 = st + sl0, sg1 = sg0 + 1;
                    bool ok0 = (sg0 <= t) && (sg0 > t - WINDOW);
                    bool ok1 = (sg1 <= t) && (sg1 > t - WINDOW);
                    *reinterpret_cast<float2*>(&S[rr * 68 + sl0]) =
                        make_float2(ok0 ? v0 : -1e30f, ok1 ? v1 : -1e30f);
                }
            }
        }
        __syncthreads();

        // ---- online softmax + P split (one row per thread) ----
        if (tid < 128) {
            const int row = tid;
            float tm = -1e30f;
#pragma unroll 8
            for (int c = 0; c < 64; ++c) tm = fmaxf(tm, S[row * 68 + c]);
            float mnew = fmaxf(m_reg, tm);
            float a = __expf(m_reg - mnew);
            float lsum = 0.0f;
            u16* ph = reinterpret_cast<u16*>(smc + SMEM_P + row * 128);
            u16* pl = reinterpret_cast<u16*>(smc + SMEM_P + 16384 + row * 128);
            const u32 xr = (u32)((row & 7) << 4);
#pragma unroll 8
            for (int c = 0; c < 64; ++c) {
                float p = __expf(S[row * 68 + c] - mnew);
                lsum += p;
                u16 hh, ll;
                split_bf(p, hh, ll);
                u32 off = ((u32)(c * 2)) ^ xr;
                *reinterpret_cast<u16*>(reinterpret_cast<char*>(ph) + off) = hh;
                *reinterpret_cast<u16*>(reinterpret_cast<char*>(pl) + off) = ll;
            }
            l_reg = l_reg * a + lsum;
            m_reg = mnew;
            al_s[row] = a;
        }
        __syncthreads();

        // ---- rescale O, then O += P V (split, 3 mma) ----
#pragma unroll
        for (int mi = 0; mi < 2; ++mi) {
            int r0 = wm * 32 + mi * 16 + (lane >> 2);
            float a0 = al_s[r0], a1 = al_s[r0 + 8];
#pragma unroll
            for (int n8 = 0; n8 < 8; ++n8) {
                acc_o[mi][n8][0] *= a0; acc_o[mi][n8][1] *= a0;
                acc_o[mi][n8][2] *= a1; acc_o[mi][n8][3] *= a1;
            }
        }
#pragma unroll
        for (int ks = 0; ks < 4; ++ks) {
            const u32 kb = (u32)(ks * 32);
            u32 ph[2][4], pl[2][4];
#pragma unroll
            for (int mi = 0; mi < 2; ++mi) {
                u32 ao = aRow + (u32)(mi * 2048) + ((aK + kb) ^ aXor);
                ldsm4(ph[mi], sb + SMEM_P + ao);
                ldsm4(pl[mi], sb + SMEM_P + 16384 + ao);
            }
            const int vrow = ks * 16 + vrow_in;
            const u32 vswz = (u32)(vrow * 256);
            const u32 vxr = (u32)((vrow & 7) << 4);
#pragma unroll
            for (int pair = 0; pair < 4; ++pair) {
                u32 hq = (u32)(wn * 64 + pair * 16) + vh8;
                u32 va = sb + SMEM_V + vswz + (((hq >> 3) * 16) ^ vxr);
                u32 vhf[4], vlf[4];
                ldsm4t(vhf, va);
                ldsm4t(vlf, va + 16384);
#pragma unroll
                for (int mi = 0; mi < 2; ++mi) {
                    mma_bf16(acc_o[mi][pair * 2],     ph[mi], vhf[0], vhf[1]);
                    mma_bf16(acc_o[mi][pair * 2],     ph[mi], vlf[0], vlf[1]);
                    mma_bf16(acc_o[mi][pair * 2],     pl[mi], vhf[0], vhf[1]);
                    mma_bf16(acc_o[mi][pair * 2 + 1], ph[mi], vhf[2], vhf[3]);
                    mma_bf16(acc_o[mi][pair * 2 + 1], ph[mi], vlf[2], vlf[3]);
                    mma_bf16(acc_o[mi][pair * 2 + 1], pl[mi], vhf[2], vhf[3]);
                }
            }
        }
        __syncthreads();
    }

    if (tid < 128) l_s[tid] = l_reg;
    __syncthreads();

    // ---- finalize: O / l -> g_enc ----
#pragma unroll
    for (int mi = 0; mi < 2; ++mi) {
        int r0 = wm * 32 + mi * 16 + (lane >> 2);
        float i0 = 1.0f / l_s[r0];
        float i1 = 1.0f / l_s[r0 + 8];
#pragma unroll
        for (int n8 = 0; n8 < 8; ++n8) {
            int h = wn * 64 + n8 * 8 + (lane & 3) * 2;
#pragma unroll
            for (int half = 0; half < 2; ++half) {
                int rr = r0 + half * 8;
                int t = t0 + (rr & 63);
                int n = kh * 2 + (rr >> 6);
                float iv = half ? i1 : i0;
                *reinterpret_cast<float2*>(&g_enc[(size_t)(t * NQH + n) * HD + h]) =
                    make_float2(acc_o[mi][n8][half * 2] * iv,
                                acc_o[mi][n8][half * 2 + 1] * iv);
            }
        }
    }
}

// ============================================================
extern "C" void kernel_launch(void* const* d_in, const int* in_sizes, int n_in,
                              void* d_out, int out_size)
{
    (void)in_sizes; (void)n_in; (void)out_size;
    const float* x   = (const float*)d_in[0];
    const int*   seg = (const int*)d_in[1];
    const float* qw  = (const float*)d_in[3];
    const float* kvw = (const float*)d_in[4];
    const float* ow  = (const float*)d_in[5];
    float* out = (float*)d_out;

    cudaFuncSetAttribute(hmma_gemm, cudaFuncAttributeMaxDynamicSharedMemorySize, GEMM_SMEM);
    cudaFuncSetAttribute(attn_mma, cudaFuncAttributeMaxDynamicSharedMemorySize, ATT2_SMEM);

    convert_hl<<<4096, 256>>>(x, 0);
    wconv<<<dim3(128, 64), 256>>>(qw, kvw, ow, 0);
    wconv<<<dim3(64, 64), 256>>>(qw, kvw, ow, 1);
    hmma_gemm<<<dim3(32, 16), 256, GEMM_SMEM>>>(nullptr, 0, 1);   // qkv
    rope_kernel<<<T_DIM, 256>>>(seg);
    split_qkv<<<8192, 256>>>();
    attn_mma<<<dim3(NKH, 32), 256, ATT2_SMEM>>>();
    convert_hl<<<4096, 256>>>(x, 1);                               // g_enc -> ge
    hmma_gemm<<<dim3(16, 16), 256, GEMM_SMEM>>>(out, D_DIM, 0);   // out proj
}

// round 8
// speedup vs baseline: 2.9378x; 1.0651x over previous
#include <cuda_runtime.h>
#include <cuda_bf16.h>
#include <math.h>

typedef unsigned long long ull;
typedef unsigned int u32;
typedef unsigned short u16;

#define T_DIM 2048
#define D_DIM 2048
#define NQH 16
#define NKH 8
#define HD 128
#define WINDOW 1024
#define SOFTCAP 50.0f
#define QSCALE 0.08838834764831845f
#define QELEMS (T_DIM * NQH * HD)
#define KVELEMS (T_DIM * NKH * HD)

// fp32 scratch
__device__ float g_q[QELEMS];
__device__ float g_k[KVELEMS];
__device__ float g_v[KVELEMS];
__device__ float g_enc[QELEMS];

// bf16 split operands
__device__ u16 gx_h[T_DIM * D_DIM], gx_l[T_DIM * D_DIM];
__device__ u16 ge_h[T_DIM * D_DIM], ge_l[T_DIM * D_DIM];
__device__ u16 gw_h[4096 * D_DIM], gw_l[4096 * D_DIM];
__device__ u16 gwo_h[D_DIM * D_DIM], gwo_l[D_DIM * D_DIM];
__device__ u16 gq_h[QELEMS], gq_l[QELEMS];
__device__ u16 gk_h[KVELEMS], gk_l[KVELEMS];
__device__ u16 gv_h[KVELEMS], gv_l[KVELEMS];

__device__ __forceinline__ u32 smem_u32(const void* p) {
    u32 a; asm("{ .reg .u64 t; cvta.to.shared.u64 t, %1; cvt.u32.u64 %0, t; }" : "=r"(a) : "l"(p));
    return a;
}
__device__ __forceinline__ void ldsm4(u32* r, u32 addr) {
    asm volatile("ldmatrix.sync.aligned.m8n8.x4.shared.b16 {%0,%1,%2,%3}, [%4];"
        : "=r"(r[0]), "=r"(r[1]), "=r"(r[2]), "=r"(r[3]) : "r"(addr));
}
__device__ __forceinline__ void ldsm4t(u32* r, u32 addr) {
    asm volatile("ldmatrix.sync.aligned.m8n8.x4.trans.shared.b16 {%0,%1,%2,%3}, [%4];"
        : "=r"(r[0]), "=r"(r[1]), "=r"(r[2]), "=r"(r[3]) : "r"(addr));
}
__device__ __forceinline__ void mma_bf16(float* c, const u32* a, u32 b0, u32 b1) {
    asm volatile("mma.sync.aligned.m16n8k16.row.col.f32.bf16.bf16.f32 "
        "{%0,%1,%2,%3}, {%4,%5,%6,%7}, {%8,%9}, {%0,%1,%2,%3};"
        : "+f"(c[0]), "+f"(c[1]), "+f"(c[2]), "+f"(c[3])
        : "r"(a[0]), "r"(a[1]), "r"(a[2]), "r"(a[3]), "r"(b0), "r"(b1));
}
__device__ __forceinline__ void cp16(u32 dst, const void* src) {
    asm volatile("cp.async.cg.shared.global [%0], [%1], 16;" :: "r"(dst), "l"(src));
}
#define CP_COMMIT() asm volatile("cp.async.commit_group;" ::: "memory")
#define CP_WAIT(n)  asm volatile("cp.async.wait_group %0;" :: "n"(n) : "memory")

__device__ __forceinline__ void split_bf(float v, u16& h, u16& l) {
    __nv_bfloat16 bh = __float2bfloat16_rn(v);
    float r = v - __bfloat162float(bh);
    __nv_bfloat16 bl = __float2bfloat16_rn(r);
    h = reinterpret_cast<u16&>(bh);
    l = reinterpret_cast<u16&>(bl);
}
__device__ __forceinline__ float tanh_fast(float x) {
    float c = fminf(fmaxf(x, -12.0f), 12.0f);
    float e = __expf(2.0f * c);
    return (e - 1.0f) / (e + 1.0f);
}

// ============================================================
// Elementwise split-convert
// ============================================================
__global__ void convert_hl(const float* __restrict__ src_x, int mode)
{
    const float* __restrict__ src = mode ? (const float*)g_enc : src_x;
    u16* __restrict__ h = mode ? ge_h : gx_h;
    u16* __restrict__ l = mode ? ge_l : gx_l;
    int i = (blockIdx.x * 256 + threadIdx.x) * 4;
    float4 v = *reinterpret_cast<const float4*>(src + i);
    u16 h0, h1, h2, h3, l0, l1, l2, l3;
    split_bf(v.x, h0, l0); split_bf(v.y, h1, l1);
    split_bf(v.z, h2, l2); split_bf(v.w, h3, l3);
    *reinterpret_cast<ull*>(h + i) = (ull)h0 | ((ull)h1 << 16) | ((ull)h2 << 32) | ((ull)h3 << 48);
    *reinterpret_cast<ull*>(l + i) = (ull)l0 | ((ull)l1 << 16) | ((ull)l2 << 32) | ((ull)l3 << 48);
}

__global__ void split_qkv()
{
    int i = (blockIdx.x * 256 + threadIdx.x) * 4;
    const float* src; u16 *dh, *dl; int off;
    if (i < QELEMS)                 { src = g_q; dh = gq_h; dl = gq_l; off = i; }
    else if (i < QELEMS + KVELEMS)  { src = g_k; dh = gk_h; dl = gk_l; off = i - QELEMS; }
    else                            { src = g_v; dh = gv_h; dl = gv_l; off = i - QELEMS - KVELEMS; }
    float4 v = *reinterpret_cast<const float4*>(src + off);
    u16 h0, h1, h2, h3, l0, l1, l2, l3;
    split_bf(v.x, h0, l0); split_bf(v.y, h1, l1);
    split_bf(v.z, h2, l2); split_bf(v.w, h3, l3);
    *reinterpret_cast<ull*>(dh + off) = (ull)h0 | ((ull)h1 << 16) | ((ull)h2 << 32) | ((ull)h3 << 48);
    *reinterpret_cast<ull*>(dl + off) = (ull)l0 | ((ull)l1 << 16) | ((ull)l2 << 32) | ((ull)l3 << 48);
}

// ============================================================
// Weight transpose + split-convert, 32x32 tiles.
// ============================================================
__global__ void wconv(const float* __restrict__ qw, const float* __restrict__ kvw,
                      const float* __restrict__ ow, int mode)
{
    __shared__ float s[32][33];
    const int c0 = blockIdx.x * 32;
    const int k0 = blockIdx.y * 32;
    const int tx = threadIdx.x & 31;
    const int ty = threadIdx.x >> 5;
    u16* __restrict__ dh = mode ? gwo_h : gw_h;
    u16* __restrict__ dl = mode ? gwo_l : gw_l;

#pragma unroll
    for (int rr = ty; rr < 32; rr += 8) {
        int k = k0 + rr;
        int c = c0 + tx;
        float v;
        if (mode == 0) {
            const float* base;
            int cc = c;
            if (cc < 2048)      base = qw + (cc >> 7) * (D_DIM * HD);
            else if (cc < 3072) { cc -= 2048; base = kvw + (cc >> 7) * (D_DIM * HD); }
            else                { cc -= 3072; base = kvw + (8 + (cc >> 7)) * (D_DIM * HD); }
            v = base[k * HD + (cc & 127)];
        } else {
            v = ow[k * D_DIM + c];
        }
        s[tx][rr] = v;
    }
    __syncthreads();
#pragma unroll
    for (int rr = ty; rr < 32; rr += 8) {
        float v = s[rr][tx];
        u16 h, l;
        split_bf(v, h, l);
        dh[(c0 + rr) * D_DIM + k0 + tx] = h;
        dl[(c0 + rr) * D_DIM + k0 + tx] = l;
    }
}

// ============================================================
// HMMA GEMM: 3-stage cp.async pipeline, term-major MMA order.
// ============================================================
#define STAGE_BYTES 65536
#define GEMM_SMEM (3 * STAGE_BYTES)

__device__ __forceinline__ void load_stage(
    u32 sbase, int p, int tid, int row0, int col0, int kk,
    const u16* __restrict__ Ah, const u16* __restrict__ Al,
    const u16* __restrict__ Bh, const u16* __restrict__ Bl)
{
    u32 stg = sbase + (u32)p * STAGE_BYTES;
#pragma unroll
    for (int l = 0; l < 4; ++l) {
        int idx = tid + l * 256;
        int r = idx >> 3;
        int ch = idx & 7;
        u32 doff = (u32)(r * 128) + (u32)((ch * 16) ^ ((r & 7) << 4));
        int aoff = (row0 + r) * D_DIM + kk + ch * 8;
        int boff = (col0 + r) * D_DIM + kk + ch * 8;
        cp16(stg + doff,             Ah + aoff);
        cp16(stg + 16384 + doff,     Al + aoff);
        cp16(stg + 32768 + doff,     Bh + boff);
        cp16(stg + 49152 + doff,     Bl + boff);
    }
}

__global__ __launch_bounds__(256, 1)
void hmma_gemm(float* __restrict__ dst0, int ldc0, int qkv_mode)
{
    extern __shared__ char smem[];
    const u32 sb = smem_u32(smem);
    const int tid = threadIdx.x;
    const int lane = tid & 31;
    const int w = tid >> 5;
    const int wm = w & 3;
    const int wn = w >> 2;
    const int row0 = blockIdx.y * 128;
    const int col0 = blockIdx.x * 128;

    const u16 *Ah, *Al, *Bh, *Bl;
    float* dst; int ldc, cofs;
    if (qkv_mode) {
        Ah = gx_h; Al = gx_l; Bh = gw_h; Bl = gw_l;
        if (col0 < 2048)      { dst = g_q; ldc = 2048; cofs = col0; }
        else if (col0 < 3072) { dst = g_k; ldc = 1024; cofs = col0 - 2048; }
        else                  { dst = g_v; ldc = 1024; cofs = col0 - 3072; }
    } else {
        Ah = ge_h; Al = ge_l; Bh = gwo_h; Bl = gwo_l;
        dst = dst0; ldc = ldc0; cofs = col0;
    }

    float acc[2][8][4];
#pragma unroll
    for (int i = 0; i < 2; ++i)
#pragma unroll
        for (int j = 0; j < 8; ++j)
#pragma unroll
            for (int q = 0; q < 4; ++q) acc[i][j][q] = 0.0f;

    const u32 aRow = (u32)(wm * 32 + (lane & 15)) * 128;
    const u32 aXor = (u32)((lane & 7) << 4);
    const u32 aK   = (u32)((lane >> 4) * 16);
    const u32 bRow = (u32)(wn * 64 + ((lane >> 4) << 3) + (lane & 7)) * 128;
    const u32 bK   = (u32)(((lane >> 3) & 1) * 16);

    load_stage(sb, 0, tid, row0, col0, 0, Ah, Al, Bh, Bl);
    CP_COMMIT();
    load_stage(sb, 1, tid, row0, col0, 64, Ah, Al, Bh, Bl);
    CP_COMMIT();

    int stage_c = 0;
    for (int c = 0; c < 32; ++c) {
        if (c < 31) { CP_WAIT(1); } else { CP_WAIT(0); }
        __syncthreads();
        if (c + 2 < 32) {
            int sn = stage_c + 2; if (sn >= 3) sn -= 3;
            load_stage(sb, sn, tid, row0, col0, (c + 2) * 64, Ah, Al, Bh, Bl);
            CP_COMMIT();
        }

        const u32 stg = sb + (u32)stage_c * STAGE_BYTES;
#pragma unroll
        for (int ks = 0; ks < 4; ++ks) {
            const u32 kb = (u32)(ks * 32);
            u32 ah[2][4], al[2][4];
#pragma unroll
            for (int mi = 0; mi < 2; ++mi) {
                u32 ao = aRow + (u32)(mi * 2048) + ((aK + kb) ^ aXor);
                ldsm4(ah[mi], stg + ao);
                ldsm4(al[mi], stg + 16384 + ao);
            }
            u32 bh[4][4], bl[4][4];
#pragma unroll
            for (int n4 = 0; n4 < 4; ++n4) {
                u32 bo = bRow + (u32)(n4 * 2048) + ((bK + kb) ^ aXor);
                ldsm4(bh[n4], stg + 32768 + bo);
                ldsm4(bl[n4], stg + 49152 + bo);
            }
            // term 1: Ah x Bh
#pragma unroll
            for (int n4 = 0; n4 < 4; ++n4)
#pragma unroll
                for (int mi = 0; mi < 2; ++mi) {
                    mma_bf16(acc[mi][2 * n4],     ah[mi], bh[n4][0], bh[n4][1]);
                    mma_bf16(acc[mi][2 * n4 + 1], ah[mi], bh[n4][2], bh[n4][3]);
                }
            // term 2: Ah x Bl
#pragma unroll
            for (int n4 = 0; n4 < 4; ++n4)
#pragma unroll
                for (int mi = 0; mi < 2; ++mi) {
                    mma_bf16(acc[mi][2 * n4],     ah[mi], bl[n4][0], bl[n4][1]);
                    mma_bf16(acc[mi][2 * n4 + 1], ah[mi], bl[n4][2], bl[n4][3]);
                }
            // term 3: Al x Bh
#pragma unroll
            for (int n4 = 0; n4 < 4; ++n4)
#pragma unroll
                for (int mi = 0; mi < 2; ++mi) {
                    mma_bf16(acc[mi][2 * n4],     al[mi], bh[n4][0], bh[n4][1]);
                    mma_bf16(acc[mi][2 * n4 + 1], al[mi], bh[n4][2], bh[n4][3]);
                }
        }
        if (++stage_c >= 3) stage_c -= 3;
    }

    const int rbase = row0 + wm * 32 + (lane >> 2);
    const int cbase = cofs + wn * 64 + (lane & 3) * 2;
#pragma unroll
    for (int mi = 0; mi < 2; ++mi) {
#pragma unroll
        for (int nt = 0; nt < 8; ++nt) {
            int r = rbase + mi * 16;
            int cc = cbase + nt * 8;
            *reinterpret_cast<float2*>(dst + r * ldc + cc) =
                make_float2(acc[mi][nt][0], acc[mi][nt][1]);
            *reinterpret_cast<float2*>(dst + (r + 8) * ldc + cc) =
                make_float2(acc[mi][nt][2], acc[mi][nt][3]);
        }
    }
}

// ============================================================
// RoPE on q (scaled) and k, in place.
// ============================================================
__global__ void rope_kernel(const int* __restrict__ seg)
{
    __shared__ float s_ts[64];
    const int t = blockIdx.x;
    const int tid = threadIdx.x;
    if (tid < 64) {
        double f = (double)tid / 64.0;
        s_ts[tid] = (float)pow(10000.0, f);
    }
    __syncthreads();
    const float pos = (float)seg[t];
    for (int idx = tid; idx < (NQH + NKH) * 64; idx += 256) {
        int head = idx >> 6;
        int i = idx & 63;
        float* base = (head < NQH) ? (g_q + t * (NQH * HD) + head * HD)
                                   : (g_k + t * (NKH * HD) + (head - NQH) * HD);
        float ang = pos / s_ts[i];
        float sv, cv;
        sincosf(ang, &sv, &cv);
        float x1 = base[i], x2 = base[i + 64];
        float o1 = x1 * cv - x2 * sv;
        float o2 = x2 * cv + x1 * sv;
        if (head < NQH) { o1 *= QSCALE; o2 *= QSCALE; }
        base[i] = o1;
        base[i + 64] = o2;
    }
}

// ============================================================
// Tensor-core sliding-window attention (split-bf16).
// ============================================================
#define SMEM_Q  0
#define SMEM_K  65536
#define SMEM_V  98304
#define SMEM_S  131072
#define SMEM_P  165888
#define SMEM_AL 198656
#define SMEM_L  199168
#define ATT2_SMEM 199680

__global__ __launch_bounds__(256, 1) void attn_mma()
{
    extern __shared__ char smc[];
    const u32 sb = smem_u32(smc);
    float* S = reinterpret_cast<float*>(smc + SMEM_S);
    float* al_s = reinterpret_cast<float*>(smc + SMEM_AL);
    float* l_s = reinterpret_cast<float*>(smc + SMEM_L);

    const int tid = threadIdx.x;
    const int lane = tid & 31;
    const int w = tid >> 5;
    const int wm = w & 3;
    const int wn = w >> 2;
    const int kh = blockIdx.x;
    const int t0 = (int)(31 - blockIdx.y) * 64;

    // ---- Q tile load ----
#pragma unroll
    for (int l = 0; l < 8; ++l) {
        int idx = tid + l * 256;
        int r = idx >> 4, ch = idx & 15;
        int t = t0 + (r & 63), n = kh * 2 + (r >> 6);
        u32 d = (u32)((ch >> 3) * 16384 + r * 128 + (((ch & 7) * 16) ^ ((r & 7) << 4)));
        cp16(sb + SMEM_Q + d,          gq_h + (size_t)(t * NQH + n) * HD + ch * 8);
        cp16(sb + SMEM_Q + 32768 + d,  gq_l + (size_t)(t * NQH + n) * HD + ch * 8);
    }
    CP_COMMIT();

    float acc_o[2][8][4];
#pragma unroll
    for (int i = 0; i < 2; ++i)
#pragma unroll
        for (int j = 0; j < 8; ++j)
#pragma unroll
            for (int q = 0; q < 4; ++q) acc_o[i][j][q] = 0.0f;

    float m_reg = -1e30f, l_reg = 0.0f;

    const u32 aRow = (u32)((wm * 32 + (lane & 15)) * 128);
    const u32 aK   = (u32)((lane >> 4) * 16);
    const u32 aXor = (u32)((lane & 7) << 4);
    const u32 bK   = (u32)(((lane >> 3) & 1) * 16);
    u32 bRow[2];
    bRow[0] = (u32)((wn * 32 + ((lane >> 4) << 3) + (lane & 7)) * 128);
    bRow[1] = bRow[0] + 16 * 128;
    const int vrow_in = (lane & 7) + (lane & 8);
    const u32 vh8 = (u32)((lane >> 4) << 3);

    const int s_begin = (t0 >= (WINDOW - 1)) ? ((t0 - (WINDOW - 1)) & ~63) : 0;

    for (int st = s_begin; st <= t0; st += 64) {
        // ---- K/V tile load ----
#pragma unroll
        for (int l = 0; l < 4; ++l) {
            int idx = tid + l * 256;
            int r = idx >> 4, ch = idx & 15;
            size_t go = (size_t)((st + r) * NKH + kh) * HD + ch * 8;
            u32 dk = (u32)((ch >> 3) * 8192 + r * 128 + (((ch & 7) * 16) ^ ((r & 7) << 4)));
            u32 dv = (u32)(r * 256 + ((ch * 16) ^ ((r & 7) << 4)));
            cp16(sb + SMEM_K + dk,         gk_h + go);
            cp16(sb + SMEM_K + 16384 + dk, gk_l + go);
            cp16(sb + SMEM_V + dv,         gv_h + go);
            cp16(sb + SMEM_V + 16384 + dv, gv_l + go);
        }
        CP_COMMIT();
        CP_WAIT(0);
        __syncthreads();

        // ---- S = Q K^T (term-major, 3 mma) ----
        float s_acc[2][4][4];
#pragma unroll
        for (int i = 0; i < 2; ++i)
#pragma unroll
            for (int j = 0; j < 4; ++j)
#pragma unroll
                for (int q = 0; q < 4; ++q) s_acc[i][j][q] = 0.0f;

#pragma unroll
        for (int ks = 0; ks < 8; ++ks) {
            const u32 kc = (u32)(ks >> 2);
            const u32 kb = (u32)((ks & 3) * 32);
            u32 qh[2][4], ql[2][4];
#pragma unroll
            for (int mi = 0; mi < 2; ++mi) {
                u32 ao = kc * 16384 + aRow + (u32)(mi * 2048) + ((aK + kb) ^ aXor);
                ldsm4(qh[mi], sb + SMEM_Q + ao);
                ldsm4(ql[mi], sb + SMEM_Q + 32768 + ao);
            }
            u32 kf[2][4], kl[2][4];
#pragma unroll
            for (int g = 0; g < 2; ++g) {
                u32 bo = kc * 8192 + bRow[g] + ((bK + kb) ^ aXor);
                ldsm4(kf[g], sb + SMEM_K + bo);
                ldsm4(kl[g], sb + SMEM_K + 16384 + bo);
            }
#pragma unroll
            for (int g = 0; g < 2; ++g)
#pragma unroll
                for (int mi = 0; mi < 2; ++mi) {
                    mma_bf16(s_acc[mi][2 * g],     qh[mi], kf[g][0], kf[g][1]);
                    mma_bf16(s_acc[mi][2 * g + 1], qh[mi], kf[g][2], kf[g][3]);
                }
#pragma unroll
            for (int g = 0; g < 2; ++g)
#pragma unroll
                for (int mi = 0; mi < 2; ++mi) {
                    mma_bf16(s_acc[mi][2 * g],     qh[mi], kl[g][0], kl[g][1]);
                    mma_bf16(s_acc[mi][2 * g + 1], qh[mi], kl[g][2], kl[g][3]);
                }
#pragma unroll
            for (int g = 0; g < 2; ++g)
#pragma unroll
                for (int mi = 0; mi < 2; ++mi) {
                    mma_bf16(s_acc[mi][2 * g],     ql[mi], kf[g][0], kf[g][1]);
                    mma_bf16(s_acc[mi][2 * g + 1], ql[mi], kf[g][2], kf[g][3]);
                }
        }

        // ---- softcap + mask, store S ----
#pragma unroll
        for (int mi = 0; mi < 2; ++mi) {
            int r0 = wm * 32 + mi * 16 + (lane >> 2);
#pragma unroll
            for (int n8 = 0; n8 < 4; ++n8) {
                int sl0 = wn * 32 + n8 * 8 + (lane & 3) * 2;
#pragma unroll
                for (int half = 0; half < 2; ++half) {
                    int rr = r0 + half * 8;
                    int t = t0 + (rr & 63);
                    float v0 = tanh_fast(s_acc[mi][n8][half * 2]     * (1.0f / SOFTCAP)) * SOFTCAP;
                    float v1 = tanh_fast(s_acc[mi][n8][half * 2 + 1] * (1.0f / SOFTCAP)) * SOFTCAP;
                    int sg0 = st + sl0, sg1 = sg0 + 1;
                    bool ok0 = (sg0 <= t) && (sg0 > t - WINDOW);
                    bool ok1 = (sg1 <= t) && (sg1 > t - WINDOW);
                    *reinterpret_cast<float2*>(&S[rr * 68 + sl0]) =
                        make_float2(ok0 ? v0 : -1e30f, ok1 ? v1 : -1e30f);
                }
            }
        }
        __syncthreads();

        // ---- online softmax: 2 threads per row (all 256 threads) ----
        {
            const int row = tid >> 1;
            const int half = tid & 1;
            const int cb = half * 32;
            float tm = -1e30f;
#pragma unroll 8
            for (int c = 0; c < 32; ++c) tm = fmaxf(tm, S[row * 68 + cb + c]);
            tm = fmaxf(tm, __shfl_xor_sync(0xffffffffu, tm, 1));
            float mnew = fmaxf(m_reg, tm);
            float a = __expf(m_reg - mnew);
            float lsum = 0.0f;
            char* ph = smc + SMEM_P + row * 128;
            char* pl = smc + SMEM_P + 16384 + row * 128;
            const u32 xr = (u32)((row & 7) << 4);
#pragma unroll 8
            for (int c = 0; c < 32; ++c) {
                float p = __expf(S[row * 68 + cb + c] - mnew);
                lsum += p;
                u16 hh, ll;
                split_bf(p, hh, ll);
                u32 off = ((u32)((cb + c) * 2)) ^ xr;
                *reinterpret_cast<u16*>(ph + off) = hh;
                *reinterpret_cast<u16*>(pl + off) = ll;
            }
            lsum += __shfl_xor_sync(0xffffffffu, lsum, 1);
            l_reg = l_reg * a + lsum;
            m_reg = mnew;
            if (half == 0) al_s[row] = a;
        }
        __syncthreads();

        // ---- rescale O, then O += P V (term-major) ----
#pragma unroll
        for (int mi = 0; mi < 2; ++mi) {
            int r0 = wm * 32 + mi * 16 + (lane >> 2);
            float a0 = al_s[r0], a1 = al_s[r0 + 8];
#pragma unroll
            for (int n8 = 0; n8 < 8; ++n8) {
                acc_o[mi][n8][0] *= a0; acc_o[mi][n8][1] *= a0;
                acc_o[mi][n8][2] *= a1; acc_o[mi][n8][3] *= a1;
            }
        }
#pragma unroll
        for (int ks = 0; ks < 4; ++ks) {
            const u32 kb = (u32)(ks * 32);
            u32 ph[2][4], pl[2][4];
#pragma unroll
            for (int mi = 0; mi < 2; ++mi) {
                u32 ao = aRow + (u32)(mi * 2048) + ((aK + kb) ^ aXor);
                ldsm4(ph[mi], sb + SMEM_P + ao);
                ldsm4(pl[mi], sb + SMEM_P + 16384 + ao);
            }
            const int vrow = ks * 16 + vrow_in;
            const u32 vswz = (u32)(vrow * 256);
            const u32 vxr = (u32)((vrow & 7) << 4);
#pragma unroll
            for (int pg = 0; pg < 2; ++pg) {
                u32 vhf[2][4], vlf[2][4];
#pragma unroll
                for (int j = 0; j < 2; ++j) {
                    int pair = pg * 2 + j;
                    u32 hq = (u32)(wn * 64 + pair * 16) + vh8;
                    u32 va = sb + SMEM_V + vswz + (((hq >> 3) * 16) ^ vxr);
                    ldsm4t(vhf[j], va);
                    ldsm4t(vlf[j], va + 16384);
                }
#pragma unroll
                for (int j = 0; j < 2; ++j) {
                    int pair = pg * 2 + j;
#pragma unroll
                    for (int mi = 0; mi < 2; ++mi) {
                        mma_bf16(acc_o[mi][pair * 2],     ph[mi], vhf[j][0], vhf[j][1]);
                        mma_bf16(acc_o[mi][pair * 2 + 1], ph[mi], vhf[j][2], vhf[j][3]);
                    }
                }
#pragma unroll
                for (int j = 0; j < 2; ++j) {
                    int pair = pg * 2 + j;
#pragma unroll
                    for (int mi = 0; mi < 2; ++mi) {
                        mma_bf16(acc_o[mi][pair * 2],     ph[mi], vlf[j][0], vlf[j][1]);
                        mma_bf16(acc_o[mi][pair * 2 + 1], ph[mi], vlf[j][2], vlf[j][3]);
                    }
                }
#pragma unroll
                for (int j = 0; j < 2; ++j) {
                    int pair = pg * 2 + j;
#pragma unroll
                    for (int mi = 0; mi < 2; ++mi) {
                        mma_bf16(acc_o[mi][pair * 2],     pl[mi], vhf[j][0], vhf[j][1]);
                        mma_bf16(acc_o[mi][pair * 2 + 1], pl[mi], vhf[j][2], vhf[j][3]);
                    }
                }
            }
        }
        __syncthreads();
    }

    // l_reg belongs to row (tid >> 1); only the even thread of each pair writes.
    if ((tid & 1) == 0) l_s[tid >> 1] = l_reg;
    __syncthreads();

#pragma unroll
    for (int mi = 0; mi < 2; ++mi) {
        int r0 = wm * 32 + mi * 16 + (lane >> 2);
        float i0 = 1.0f / l_s[r0];
        float i1 = 1.0f / l_s[r0 + 8];
#pragma unroll
        for (int n8 = 0; n8 < 8; ++n8) {
            int h = wn * 64 + n8 * 8 + (lane & 3) * 2;
#pragma unroll
            for (int half = 0; half < 2; ++half) {
                int rr = r0 + half * 8;
                int t = t0 + (rr & 63);
                int n = kh * 2 + (rr >> 6);
                float iv = half ? i1 : i0;
                *reinterpret_cast<float2*>(&g_enc[(size_t)(t * NQH + n) * HD + h]) =
                    make_float2(acc_o[mi][n8][half * 2] * iv,
                                acc_o[mi][n8][half * 2 + 1] * iv);
            }
        }
    }
}

// ============================================================
extern "C" void kernel_launch(void* const* d_in, const int* in_sizes, int n_in,
                              void* d_out, int out_size)
{
    (void)in_sizes; (void)n_in; (void)out_size;
    const float* x   = (const float*)d_in[0];
    const int*   seg = (const int*)d_in[1];
    const float* qw  = (const float*)d_in[3];
    const float* kvw = (const float*)d_in[4];
    const float* ow  = (const float*)d_in[5];
    float* out = (float*)d_out;

    cudaFuncSetAttribute(hmma_gemm, cudaFuncAttributeMaxDynamicSharedMemorySize, GEMM_SMEM);
    cudaFuncSetAttribute(attn_mma, cudaFuncAttributeMaxDynamicSharedMemorySize, ATT2_SMEM);

    convert_hl<<<4096, 256>>>(x, 0);
    wconv<<<dim3(128, 64), 256>>>(qw, kvw, ow, 0);
    wconv<<<dim3(64, 64), 256>>>(qw, kvw, ow, 1);
    hmma_gemm<<<dim3(32, 16), 256, GEMM_SMEM>>>(nullptr, 0, 1);   // qkv
    rope_kernel<<<T_DIM, 256>>>(seg);
    split_qkv<<<8192, 256>>>();
    attn_mma<<<dim3(NKH, 32), 256, ATT2_SMEM>>>();
    convert_hl<<<4096, 256>>>(x, 1);                               // g_enc -> ge
    hmma_gemm<<<dim3(16, 16), 256, GEMM_SMEM>>>(out, D_DIM, 0);   // out proj
}

// round 9
// speedup vs baseline: 2.9725x; 1.0118x over previous
#include <cuda_runtime.h>
#include <cuda_bf16.h>
#include <math.h>

typedef unsigned long long ull;
typedef unsigned int u32;
typedef unsigned short u16;

#define T_DIM 2048
#define D_DIM 2048
#define NQH 16
#define NKH 8
#define HD 128
#define WINDOW 1024
#define SOFTCAP 50.0f
#define QSCALE 0.08838834764831845f
#define QELEMS (T_DIM * NQH * HD)
#define KVELEMS (T_DIM * NKH * HD)

// fp32 scratch
__device__ float g_q[QELEMS];
__device__ float g_k[KVELEMS];
__device__ float g_v[KVELEMS];
__device__ float g_enc[QELEMS];

// bf16 split operands
__device__ u16 gx_h[T_DIM * D_DIM], gx_l[T_DIM * D_DIM];
__device__ u16 ge_h[T_DIM * D_DIM], ge_l[T_DIM * D_DIM];
__device__ u16 gw_h[4096 * D_DIM], gw_l[4096 * D_DIM];
__device__ u16 gwo_h[D_DIM * D_DIM], gwo_l[D_DIM * D_DIM];
__device__ u16 gq_h[QELEMS], gq_l[QELEMS];
__device__ u16 gk_h[KVELEMS], gk_l[KVELEMS];
__device__ u16 gv_h[KVELEMS], gv_l[KVELEMS];

__device__ __forceinline__ u32 smem_u32(const void* p) {
    u32 a; asm("{ .reg .u64 t; cvta.to.shared.u64 t, %1; cvt.u32.u64 %0, t; }" : "=r"(a) : "l"(p));
    return a;
}
__device__ __forceinline__ void ldsm4(u32* r, u32 addr) {
    asm volatile("ldmatrix.sync.aligned.m8n8.x4.shared.b16 {%0,%1,%2,%3}, [%4];"
        : "=r"(r[0]), "=r"(r[1]), "=r"(r[2]), "=r"(r[3]) : "r"(addr));
}
__device__ __forceinline__ void ldsm4t(u32* r, u32 addr) {
    asm volatile("ldmatrix.sync.aligned.m8n8.x4.trans.shared.b16 {%0,%1,%2,%3}, [%4];"
        : "=r"(r[0]), "=r"(r[1]), "=r"(r[2]), "=r"(r[3]) : "r"(addr));
}
__device__ __forceinline__ void mma_bf16(float* c, const u32* a, u32 b0, u32 b1) {
    asm volatile("mma.sync.aligned.m16n8k16.row.col.f32.bf16.bf16.f32 "
        "{%0,%1,%2,%3}, {%4,%5,%6,%7}, {%8,%9}, {%0,%1,%2,%3};"
        : "+f"(c[0]), "+f"(c[1]), "+f"(c[2]), "+f"(c[3])
        : "r"(a[0]), "r"(a[1]), "r"(a[2]), "r"(a[3]), "r"(b0), "r"(b1));
}
__device__ __forceinline__ void cp16(u32 dst, const void* src) {
    asm volatile("cp.async.cg.shared.global [%0], [%1], 16;" :: "r"(dst), "l"(src));
}
#define CP_COMMIT() asm volatile("cp.async.commit_group;" ::: "memory")
#define CP_WAIT(n)  asm volatile("cp.async.wait_group %0;" :: "n"(n) : "memory")

__device__ __forceinline__ void split_bf(float v, u16& h, u16& l) {
    __nv_bfloat16 bh = __float2bfloat16_rn(v);
    float r = v - __bfloat162float(bh);
    __nv_bfloat16 bl = __float2bfloat16_rn(r);
    h = reinterpret_cast<u16&>(bh);
    l = reinterpret_cast<u16&>(bl);
}
__device__ __forceinline__ float tanh_fast(float x) {
    float c = fminf(fmaxf(x, -12.0f), 12.0f);
    float e = __expf(2.0f * c);
    return (e - 1.0f) / (e + 1.0f);
}

// ============================================================
// Elementwise split-convert
// ============================================================
__global__ void convert_hl(const float* __restrict__ src_x, int mode)
{
    const float* __restrict__ src = mode ? (const float*)g_enc : src_x;
    u16* __restrict__ h = mode ? ge_h : gx_h;
    u16* __restrict__ l = mode ? ge_l : gx_l;
    int i = (blockIdx.x * 256 + threadIdx.x) * 4;
    float4 v = *reinterpret_cast<const float4*>(src + i);
    u16 h0, h1, h2, h3, l0, l1, l2, l3;
    split_bf(v.x, h0, l0); split_bf(v.y, h1, l1);
    split_bf(v.z, h2, l2); split_bf(v.w, h3, l3);
    *reinterpret_cast<ull*>(h + i) = (ull)h0 | ((ull)h1 << 16) | ((ull)h2 << 32) | ((ull)h3 << 48);
    *reinterpret_cast<ull*>(l + i) = (ull)l0 | ((ull)l1 << 16) | ((ull)l2 << 32) | ((ull)l3 << 48);
}

// ============================================================
// Weight transpose + split-convert, 32x32 tiles.
// ============================================================
__global__ void wconv(const float* __restrict__ qw, const float* __restrict__ kvw,
                      const float* __restrict__ ow, int mode)
{
    __shared__ float s[32][33];
    const int c0 = blockIdx.x * 32;
    const int k0 = blockIdx.y * 32;
    const int tx = threadIdx.x & 31;
    const int ty = threadIdx.x >> 5;
    u16* __restrict__ dh = mode ? gwo_h : gw_h;
    u16* __restrict__ dl = mode ? gwo_l : gw_l;

#pragma unroll
    for (int rr = ty; rr < 32; rr += 8) {
        int k = k0 + rr;
        int c = c0 + tx;
        float v;
        if (mode == 0) {
            const float* base;
            int cc = c;
            if (cc < 2048)      base = qw + (cc >> 7) * (D_DIM * HD);
            else if (cc < 3072) { cc -= 2048; base = kvw + (cc >> 7) * (D_DIM * HD); }
            else                { cc -= 3072; base = kvw + (8 + (cc >> 7)) * (D_DIM * HD); }
            v = base[k * HD + (cc & 127)];
        } else {
            v = ow[k * D_DIM + c];
        }
        s[tx][rr] = v;
    }
    __syncthreads();
#pragma unroll
    for (int rr = ty; rr < 32; rr += 8) {
        float v = s[rr][tx];
        u16 h, l;
        split_bf(v, h, l);
        dh[(c0 + rr) * D_DIM + k0 + tx] = h;
        dl[(c0 + rr) * D_DIM + k0 + tx] = l;
    }
}

// ============================================================
// HMMA GEMM: 512 threads (16 warps), 3-stage cp.async pipeline.
// CTA tile 128x128, warp tile 32x32 (4M x 4N warp grid).
// ============================================================
#define STAGE_BYTES 65536
#define GEMM_SMEM (3 * STAGE_BYTES)

__device__ __forceinline__ void load_stage512(
    u32 sbase, int p, int tid, int row0, int col0, int kk,
    const u16* __restrict__ Ah, const u16* __restrict__ Al,
    const u16* __restrict__ Bh, const u16* __restrict__ Bl)
{
    u32 stg = sbase + (u32)p * STAGE_BYTES;
#pragma unroll
    for (int l = 0; l < 2; ++l) {
        int idx = tid + l * 512;
        int r = idx >> 3;
        int ch = idx & 7;
        u32 doff = (u32)(r * 128) + (u32)((ch * 16) ^ ((r & 7) << 4));
        int aoff = (row0 + r) * D_DIM + kk + ch * 8;
        int boff = (col0 + r) * D_DIM + kk + ch * 8;
        cp16(stg + doff,             Ah + aoff);
        cp16(stg + 16384 + doff,     Al + aoff);
        cp16(stg + 32768 + doff,     Bh + boff);
        cp16(stg + 49152 + doff,     Bl + boff);
    }
}

__global__ __launch_bounds__(512, 1)
void hmma_gemm(float* __restrict__ dst0, int ldc0, int qkv_mode)
{
    extern __shared__ char smem[];
    const u32 sb = smem_u32(smem);
    const int tid = threadIdx.x;
    const int lane = tid & 31;
    const int w = tid >> 5;
    const int wm = w & 3;          // M group: rows wm*32
    const int wn = w >> 2;         // N group: cols wn*32 (0..3)
    const int row0 = blockIdx.y * 128;
    const int col0 = blockIdx.x * 128;

    const u16 *Ah, *Al, *Bh, *Bl;
    float* dst; int ldc, cofs;
    if (qkv_mode) {
        Ah = gx_h; Al = gx_l; Bh = gw_h; Bl = gw_l;
        if (col0 < 2048)      { dst = g_q; ldc = 2048; cofs = col0; }
        else if (col0 < 3072) { dst = g_k; ldc = 1024; cofs = col0 - 2048; }
        else                  { dst = g_v; ldc = 1024; cofs = col0 - 3072; }
    } else {
        Ah = ge_h; Al = ge_l; Bh = gwo_h; Bl = gwo_l;
        dst = dst0; ldc = ldc0; cofs = col0;
    }

    float acc[2][4][4];
#pragma unroll
    for (int i = 0; i < 2; ++i)
#pragma unroll
        for (int j = 0; j < 4; ++j)
#pragma unroll
            for (int q = 0; q < 4; ++q) acc[i][j][q] = 0.0f;

    const u32 aRow = (u32)(wm * 32 + (lane & 15)) * 128;
    const u32 aXor = (u32)((lane & 7) << 4);
    const u32 aK   = (u32)((lane >> 4) * 16);
    const u32 bRow = (u32)(wn * 32 + ((lane >> 4) << 3) + (lane & 7)) * 128;
    const u32 bK   = (u32)(((lane >> 3) & 1) * 16);

    load_stage512(sb, 0, tid, row0, col0, 0, Ah, Al, Bh, Bl);
    CP_COMMIT();
    load_stage512(sb, 1, tid, row0, col0, 64, Ah, Al, Bh, Bl);
    CP_COMMIT();

    int stage_c = 0;
    for (int c = 0; c < 32; ++c) {
        if (c < 31) { CP_WAIT(1); } else { CP_WAIT(0); }
        __syncthreads();
        if (c + 2 < 32) {
            int sn = stage_c + 2; if (sn >= 3) sn -= 3;
            load_stage512(sb, sn, tid, row0, col0, (c + 2) * 64, Ah, Al, Bh, Bl);
            CP_COMMIT();
        }

        const u32 stg = sb + (u32)stage_c * STAGE_BYTES;
#pragma unroll
        for (int ks = 0; ks < 4; ++ks) {
            const u32 kb = (u32)(ks * 32);
            u32 ah[2][4], al[2][4];
#pragma unroll
            for (int mi = 0; mi < 2; ++mi) {
                u32 ao = aRow + (u32)(mi * 2048) + ((aK + kb) ^ aXor);
                ldsm4(ah[mi], stg + ao);
                ldsm4(al[mi], stg + 16384 + ao);
            }
            u32 bh[2][4], bl[2][4];
#pragma unroll
            for (int n4 = 0; n4 < 2; ++n4) {
                u32 bo = bRow + (u32)(n4 * 2048) + ((bK + kb) ^ aXor);
                ldsm4(bh[n4], stg + 32768 + bo);
                ldsm4(bl[n4], stg + 49152 + bo);
            }
            // term 1: Ah x Bh
#pragma unroll
            for (int n4 = 0; n4 < 2; ++n4)
#pragma unroll
                for (int mi = 0; mi < 2; ++mi) {
                    mma_bf16(acc[mi][2 * n4],     ah[mi], bh[n4][0], bh[n4][1]);
                    mma_bf16(acc[mi][2 * n4 + 1], ah[mi], bh[n4][2], bh[n4][3]);
                }
            // term 2: Ah x Bl
#pragma unroll
            for (int n4 = 0; n4 < 2; ++n4)
#pragma unroll
                for (int mi = 0; mi < 2; ++mi) {
                    mma_bf16(acc[mi][2 * n4],     ah[mi], bl[n4][0], bl[n4][1]);
                    mma_bf16(acc[mi][2 * n4 + 1], ah[mi], bl[n4][2], bl[n4][3]);
                }
            // term 3: Al x Bh
#pragma unroll
            for (int n4 = 0; n4 < 2; ++n4)
#pragma unroll
                for (int mi = 0; mi < 2; ++mi) {
                    mma_bf16(acc[mi][2 * n4],     al[mi], bh[n4][0], bh[n4][1]);
                    mma_bf16(acc[mi][2 * n4 + 1], al[mi], bh[n4][2], bh[n4][3]);
                }
        }
        if (++stage_c >= 3) stage_c -= 3;
    }

    const int rbase = row0 + wm * 32 + (lane >> 2);
    const int cbase = cofs + wn * 32 + (lane & 3) * 2;
#pragma unroll
    for (int mi = 0; mi < 2; ++mi) {
#pragma unroll
        for (int nt = 0; nt < 4; ++nt) {
            int r = rbase + mi * 16;
            int cc = cbase + nt * 8;
            *reinterpret_cast<float2*>(dst + r * ldc + cc) =
                make_float2(acc[mi][nt][0], acc[mi][nt][1]);
            *reinterpret_cast<float2*>(dst + (r + 8) * ldc + cc) =
                make_float2(acc[mi][nt][2], acc[mi][nt][3]);
        }
    }
}

// ============================================================
// RoPE + hi/lo split fused: q (scaled) and k -> gq/gk splits,
// v -> gv splits (no rope).
// ============================================================
__global__ void rope_split(const int* __restrict__ seg)
{
    __shared__ float s_ts[64];
    const int t = blockIdx.x;
    const int tid = threadIdx.x;
    if (tid < 64) {
        double f = (double)tid / 64.0;
        s_ts[tid] = (float)pow(10000.0, f);
    }
    __syncthreads();
    const float pos = (float)seg[t];
    for (int idx = tid; idx < (NQH + NKH) * 64; idx += 256) {
        int head = idx >> 6;
        int i = idx & 63;
        const float* base;
        u16 *dh, *dl;
        int off;
        if (head < NQH) {
            off = t * (NQH * HD) + head * HD;
            base = g_q + off; dh = gq_h + off; dl = gq_l + off;
        } else {
            off = t * (NKH * HD) + (head - NQH) * HD;
            base = g_k + off; dh = gk_h + off; dl = gk_l + off;
        }
        float ang = pos / s_ts[i];
        float sv, cv;
        sincosf(ang, &sv, &cv);
        float x1 = base[i], x2 = base[i + 64];
        float o1 = x1 * cv - x2 * sv;
        float o2 = x2 * cv + x1 * sv;
        if (head < NQH) { o1 *= QSCALE; o2 *= QSCALE; }
        u16 h1, l1, h2, l2;
        split_bf(o1, h1, l1);
        split_bf(o2, h2, l2);
        dh[i] = h1;       dl[i] = l1;
        dh[i + 64] = h2;  dl[i + 64] = l2;
    }
    // v: split only (1024 floats per t), 256 threads x float4
    {
        int off = t * (NKH * HD) + tid * 4;
        float4 v = *reinterpret_cast<const float4*>(g_v + off);
        u16 h0, h1, h2, h3, l0, l1, l2, l3;
        split_bf(v.x, h0, l0); split_bf(v.y, h1, l1);
        split_bf(v.z, h2, l2); split_bf(v.w, h3, l3);
        *reinterpret_cast<ull*>(gv_h + off) = (ull)h0 | ((ull)h1 << 16) | ((ull)h2 << 32) | ((ull)h3 << 48);
        *reinterpret_cast<ull*>(gv_l + off) = (ull)l0 | ((ull)l1 << 16) | ((ull)l2 << 32) | ((ull)l3 << 48);
    }
}

// ============================================================
// Tensor-core sliding-window attention (split-bf16). R7-verified.
// ============================================================
#define SMEM_Q  0
#define SMEM_K  65536
#define SMEM_V  98304
#define SMEM_S  131072
#define SMEM_P  165888
#define SMEM_AL 198656
#define SMEM_L  199168
#define ATT2_SMEM 199680

__global__ __launch_bounds__(256, 1) void attn_mma()
{
    extern __shared__ char smc[];
    const u32 sb = smem_u32(smc);
    float* S = reinterpret_cast<float*>(smc + SMEM_S);
    float* al_s = reinterpret_cast<float*>(smc + SMEM_AL);
    float* l_s = reinterpret_cast<float*>(smc + SMEM_L);

    const int tid = threadIdx.x;
    const int lane = tid & 31;
    const int w = tid >> 5;
    const int wm = w & 3;
    const int wn = w >> 2;
    const int kh = blockIdx.x;
    const int t0 = (int)(31 - blockIdx.y) * 64;

    // ---- Q tile load ----
#pragma unroll
    for (int l = 0; l < 8; ++l) {
        int idx = tid + l * 256;
        int r = idx >> 4, ch = idx & 15;
        int t = t0 + (r & 63), n = kh * 2 + (r >> 6);
        u32 d = (u32)((ch >> 3) * 16384 + r * 128 + (((ch & 7) * 16) ^ ((r & 7) << 4)));
        cp16(sb + SMEM_Q + d,          gq_h + (size_t)(t * NQH + n) * HD + ch * 8);
        cp16(sb + SMEM_Q + 32768 + d,  gq_l + (size_t)(t * NQH + n) * HD + ch * 8);
    }
    CP_COMMIT();

    float acc_o[2][8][4];
#pragma unroll
    for (int i = 0; i < 2; ++i)
#pragma unroll
        for (int j = 0; j < 8; ++j)
#pragma unroll
            for (int q = 0; q < 4; ++q) acc_o[i][j][q] = 0.0f;

    float m_reg = -1e30f, l_reg = 0.0f;

    const u32 aRow = (u32)((wm * 32 + (lane & 15)) * 128);
    const u32 aK   = (u32)((lane >> 4) * 16);
    const u32 aXor = (u32)((lane & 7) << 4);
    const u32 bK   = (u32)(((lane >> 3) & 1) * 16);
    u32 bRow[2];
    bRow[0] = (u32)((wn * 32 + ((lane >> 4) << 3) + (lane & 7)) * 128);
    bRow[1] = bRow[0] + 16 * 128;
    const int vrow_in = (lane & 7) + (lane & 8);
    const u32 vh8 = (u32)((lane >> 4) << 3);

    const int s_begin = (t0 >= (WINDOW - 1)) ? ((t0 - (WINDOW - 1)) & ~63) : 0;

    for (int st = s_begin; st <= t0; st += 64) {
        // ---- K/V tile load ----
#pragma unroll
        for (int l = 0; l < 4; ++l) {
            int idx = tid + l * 256;
            int r = idx >> 4, ch = idx & 15;
            size_t go = (size_t)((st + r) * NKH + kh) * HD + ch * 8;
            u32 dk = (u32)((ch >> 3) * 8192 + r * 128 + (((ch & 7) * 16) ^ ((r & 7) << 4)));
            u32 dv = (u32)(r * 256 + ((ch * 16) ^ ((r & 7) << 4)));
            cp16(sb + SMEM_K + dk,         gk_h + go);
            cp16(sb + SMEM_K + 16384 + dk, gk_l + go);
            cp16(sb + SMEM_V + dv,         gv_h + go);
            cp16(sb + SMEM_V + 16384 + dv, gv_l + go);
        }
        CP_COMMIT();
        CP_WAIT(0);
        __syncthreads();

        // ---- S = Q K^T (term-major, 3 mma) ----
        float s_acc[2][4][4];
#pragma unroll
        for (int i = 0; i < 2; ++i)
#pragma unroll
            for (int j = 0; j < 4; ++j)
#pragma unroll
                for (int q = 0; q < 4; ++q) s_acc[i][j][q] = 0.0f;

#pragma unroll
        for (int ks = 0; ks < 8; ++ks) {
            const u32 kc = (u32)(ks >> 2);
            const u32 kb = (u32)((ks & 3) * 32);
            u32 qh[2][4], ql[2][4];
#pragma unroll
            for (int mi = 0; mi < 2; ++mi) {
                u32 ao = kc * 16384 + aRow + (u32)(mi * 2048) + ((aK + kb) ^ aXor);
                ldsm4(qh[mi], sb + SMEM_Q + ao);
                ldsm4(ql[mi], sb + SMEM_Q + 32768 + ao);
            }
            u32 kf[2][4], kl[2][4];
#pragma unroll
            for (int g = 0; g < 2; ++g) {
                u32 bo = kc * 8192 + bRow[g] + ((bK + kb) ^ aXor);
                ldsm4(kf[g], sb + SMEM_K + bo);
                ldsm4(kl[g], sb + SMEM_K + 16384 + bo);
            }
#pragma unroll
            for (int g = 0; g < 2; ++g)
#pragma unroll
                for (int mi = 0; mi < 2; ++mi) {
                    mma_bf16(s_acc[mi][2 * g],     qh[mi], kf[g][0], kf[g][1]);
                    mma_bf16(s_acc[mi][2 * g + 1], qh[mi], kf[g][2], kf[g][3]);
                }
#pragma unroll
            for (int g = 0; g < 2; ++g)
#pragma unroll
                for (int mi = 0; mi < 2; ++mi) {
                    mma_bf16(s_acc[mi][2 * g],     qh[mi], kl[g][0], kl[g][1]);
                    mma_bf16(s_acc[mi][2 * g + 1], qh[mi], kl[g][2], kl[g][3]);
                }
#pragma unroll
            for (int g = 0; g < 2; ++g)
#pragma unroll
                for (int mi = 0; mi < 2; ++mi) {
                    mma_bf16(s_acc[mi][2 * g],     ql[mi], kf[g][0], kf[g][1]);
                    mma_bf16(s_acc[mi][2 * g + 1], ql[mi], kf[g][2], kf[g][3]);
                }
        }

        // ---- softcap + mask, store S ----
#pragma unroll
        for (int mi = 0; mi < 2; ++mi) {
            int r0 = wm * 32 + mi * 16 + (lane >> 2);
#pragma unroll
            for (int n8 = 0; n8 < 4; ++n8) {
                int sl0 = wn * 32 + n8 * 8 + (lane & 3) * 2;
#pragma unroll
                for (int half = 0; half < 2; ++half) {
                    int rr = r0 + half * 8;
                    int t = t0 + (rr & 63);
                    float v0 = tanh_fast(s_acc[mi][n8][half * 2]     * (1.0f / SOFTCAP)) * SOFTCAP;
                    float v1 = tanh_fast(s_acc[mi][n8][half * 2 + 1] * (1.0f / SOFTCAP)) * SOFTCAP;
                    int sg0 = st + sl0, sg1 = sg0 + 1;
                    bool ok0 = (sg0 <= t) && (sg0 > t - WINDOW);
                    bool ok1 = (sg1 <= t) && (sg1 > t - WINDOW);
                    *reinterpret_cast<float2*>(&S[rr * 68 + sl0]) =
                        make_float2(ok0 ? v0 : -1e30f, ok1 ? v1 : -1e30f);
                }
            }
        }
        __syncthreads();

        // ---- online softmax: 2 threads per row ----
        {
            const int row = tid >> 1;
            const int half = tid & 1;
            const int cb = half * 32;
            float tm = -1e30f;
#pragma unroll 8
            for (int c = 0; c < 32; ++c) tm = fmaxf(tm, S[row * 68 + cb + c]);
            tm = fmaxf(tm, __shfl_xor_sync(0xffffffffu, tm, 1));
            float mnew = fmaxf(m_reg, tm);
            float a = __expf(m_reg - mnew);
            float lsum = 0.0f;
            char* ph = smc + SMEM_P + row * 128;
            char* pl = smc + SMEM_P + 16384 + row * 128;
            const u32 xr = (u32)((row & 7) << 4);
#pragma unroll 8
            for (int c = 0; c < 32; ++c) {
                float p = __expf(S[row * 68 + cb + c] - mnew);
                lsum += p;
                u16 hh, ll;
                split_bf(p, hh, ll);
                u32 off = ((u32)((cb + c) * 2)) ^ xr;
                *reinterpret_cast<u16*>(ph + off) = hh;
                *reinterpret_cast<u16*>(pl + off) = ll;
            }
            lsum += __shfl_xor_sync(0xffffffffu, lsum, 1);
            l_reg = l_reg * a + lsum;
            m_reg = mnew;
            if (half == 0) al_s[row] = a;
        }
        __syncthreads();

        // ---- rescale O, then O += P V (term-major) ----
#pragma unroll
        for (int mi = 0; mi < 2; ++mi) {
            int r0 = wm * 32 + mi * 16 + (lane >> 2);
            float a0 = al_s[r0], a1 = al_s[r0 + 8];
#pragma unroll
            for (int n8 = 0; n8 < 8; ++n8) {
                acc_o[mi][n8][0] *= a0; acc_o[mi][n8][1] *= a0;
                acc_o[mi][n8][2] *= a1; acc_o[mi][n8][3] *= a1;
            }
        }
#pragma unroll
        for (int ks = 0; ks < 4; ++ks) {
            const u32 kb = (u32)(ks * 32);
            u32 ph[2][4], pl[2][4];
#pragma unroll
            for (int mi = 0; mi < 2; ++mi) {
                u32 ao = aRow + (u32)(mi * 2048) + ((aK + kb) ^ aXor);
                ldsm4(ph[mi], sb + SMEM_P + ao);
                ldsm4(pl[mi], sb + SMEM_P + 16384 + ao);
            }
            const int vrow = ks * 16 + vrow_in;
            const u32 vswz = (u32)(vrow * 256);
            const u32 vxr = (u32)((vrow & 7) << 4);
#pragma unroll
            for (int pg = 0; pg < 2; ++pg) {
                u32 vhf[2][4], vlf[2][4];
#pragma unroll
                for (int j = 0; j < 2; ++j) {
                    int pair = pg * 2 + j;
                    u32 hq = (u32)(wn * 64 + pair * 16) + vh8;
                    u32 va = sb + SMEM_V + vswz + (((hq >> 3) * 16) ^ vxr);
                    ldsm4t(vhf[j], va);
                    ldsm4t(vlf[j], va + 16384);
                }
#pragma unroll
                for (int j = 0; j < 2; ++j) {
                    int pair = pg * 2 + j;
#pragma unroll
                    for (int mi = 0; mi < 2; ++mi) {
                        mma_bf16(acc_o[mi][pair * 2],     ph[mi], vhf[j][0], vhf[j][1]);
                        mma_bf16(acc_o[mi][pair * 2 + 1], ph[mi], vhf[j][2], vhf[j][3]);
                    }
                }
#pragma unroll
                for (int j = 0; j < 2; ++j) {
                    int pair = pg * 2 + j;
#pragma unroll
                    for (int mi = 0; mi < 2; ++mi) {
                        mma_bf16(acc_o[mi][pair * 2],     ph[mi], vlf[j][0], vlf[j][1]);
                        mma_bf16(acc_o[mi][pair * 2 + 1], ph[mi], vlf[j][2], vlf[j][3]);
                    }
                }
#pragma unroll
                for (int j = 0; j < 2; ++j) {
                    int pair = pg * 2 + j;
#pragma unroll
                    for (int mi = 0; mi < 2; ++mi) {
                        mma_bf16(acc_o[mi][pair * 2],     pl[mi], vhf[j][0], vhf[j][1]);
                        mma_bf16(acc_o[mi][pair * 2 + 1], pl[mi], vhf[j][2], vhf[j][3]);
                    }
                }
            }
        }
        __syncthreads();
    }

    if ((tid & 1) == 0) l_s[tid >> 1] = l_reg;
    __syncthreads();

#pragma unroll
    for (int mi = 0; mi < 2; ++mi) {
        int r0 = wm * 32 + mi * 16 + (lane >> 2);
        float i0 = 1.0f / l_s[r0];
        float i1 = 1.0f / l_s[r0 + 8];
#pragma unroll
        for (int n8 = 0; n8 < 8; ++n8) {
            int h = wn * 64 + n8 * 8 + (lane & 3) * 2;
#pragma unroll
            for (int half = 0; half < 2; ++half) {
                int rr = r0 + half * 8;
                int t = t0 + (rr & 63);
                int n = kh * 2 + (rr >> 6);
                float iv = half ? i1 : i0;
                *reinterpret_cast<float2*>(&g_enc[(size_t)(t * NQH + n) * HD + h]) =
                    make_float2(acc_o[mi][n8][half * 2] * iv,
                                acc_o[mi][n8][half * 2 + 1] * iv);
            }
        }
    }
}

// ============================================================
extern "C" void kernel_launch(void* const* d_in, const int* in_sizes, int n_in,
                              void* d_out, int out_size)
{
    (void)in_sizes; (void)n_in; (void)out_size;
    const float* x   = (const float*)d_in[0];
    const int*   seg = (const int*)d_in[1];
    const float* qw  = (const float*)d_in[3];
    const float* kvw = (const float*)d_in[4];
    const float* ow  = (const float*)d_in[5];
    float* out = (float*)d_out;

    cudaFuncSetAttribute(hmma_gemm, cudaFuncAttributeMaxDynamicSharedMemorySize, GEMM_SMEM);
    cudaFuncSetAttribute(attn_mma, cudaFuncAttributeMaxDynamicSharedMemorySize, ATT2_SMEM);

    convert_hl<<<4096, 256>>>(x, 0);
    wconv<<<dim3(128, 64), 256>>>(qw, kvw, ow, 0);
    wconv<<<dim3(64, 64), 256>>>(qw, kvw, ow, 1);
    hmma_gemm<<<dim3(32, 16), 512, GEMM_SMEM>>>(nullptr, 0, 1);   // qkv
    rope_split<<<T_DIM, 256>>>(seg);                               // rope + split fused
    attn_mma<<<dim3(NKH, 32), 256, ATT2_SMEM>>>();
    convert_hl<<<4096, 256>>>(x, 1);                               // g_enc -> ge
    hmma_gemm<<<dim3(16, 16), 512, GEMM_SMEM>>>(out, D_DIM, 0);   // out proj
}

// round 10
// speedup vs baseline: 2.9808x; 1.0028x over previous
#include <cuda_runtime.h>
#include <cuda_bf16.h>
#include <math.h>

typedef unsigned long long ull;
typedef unsigned int u32;
typedef unsigned short u16;

#define T_DIM 2048
#define D_DIM 2048
#define NQH 16
#define NKH 8
#define HD 128
#define WINDOW 1024
#define SOFTCAP 50.0f
#define QSCALE 0.08838834764831845f
#define QELEMS (T_DIM * NQH * HD)
#define KVELEMS (T_DIM * NKH * HD)

// fp32 scratch
__device__ float g_q[QELEMS];
__device__ float g_k[KVELEMS];
__device__ float g_v[KVELEMS];
__device__ float g_enc[QELEMS];

// bf16 split operands
__device__ u16 gx_h[T_DIM * D_DIM], gx_l[T_DIM * D_DIM];
__device__ u16 ge_h[T_DIM * D_DIM], ge_l[T_DIM * D_DIM];
__device__ u16 gw_h[4096 * D_DIM], gw_l[4096 * D_DIM];
__device__ u16 gwo_h[D_DIM * D_DIM], gwo_l[D_DIM * D_DIM];
__device__ u16 gq_h[QELEMS], gq_l[QELEMS];
__device__ u16 gk_h[KVELEMS], gk_l[KVELEMS];
__device__ u16 gv_h[KVELEMS], gv_l[KVELEMS];

__device__ __forceinline__ u32 smem_u32(const void* p) {
    u32 a; asm("{ .reg .u64 t; cvta.to.shared.u64 t, %1; cvt.u32.u64 %0, t; }" : "=r"(a) : "l"(p));
    return a;
}
__device__ __forceinline__ void ldsm4(u32* r, u32 addr) {
    asm volatile("ldmatrix.sync.aligned.m8n8.x4.shared.b16 {%0,%1,%2,%3}, [%4];"
        : "=r"(r[0]), "=r"(r[1]), "=r"(r[2]), "=r"(r[3]) : "r"(addr));
}
__device__ __forceinline__ void ldsm4t(u32* r, u32 addr) {
    asm volatile("ldmatrix.sync.aligned.m8n8.x4.trans.shared.b16 {%0,%1,%2,%3}, [%4];"
        : "=r"(r[0]), "=r"(r[1]), "=r"(r[2]), "=r"(r[3]) : "r"(addr));
}
__device__ __forceinline__ void mma_bf16(float* c, const u32* a, u32 b0, u32 b1) {
    asm volatile("mma.sync.aligned.m16n8k16.row.col.f32.bf16.bf16.f32 "
        "{%0,%1,%2,%3}, {%4,%5,%6,%7}, {%8,%9}, {%0,%1,%2,%3};"
        : "+f"(c[0]), "+f"(c[1]), "+f"(c[2]), "+f"(c[3])
        : "r"(a[0]), "r"(a[1]), "r"(a[2]), "r"(a[3]), "r"(b0), "r"(b1));
}
__device__ __forceinline__ void cp16(u32 dst, const void* src) {
    asm volatile("cp.async.cg.shared.global [%0], [%1], 16;" :: "r"(dst), "l"(src));
}
#define CP_COMMIT() asm volatile("cp.async.commit_group;" ::: "memory")
#define CP_WAIT(n)  asm volatile("cp.async.wait_group %0;" :: "n"(n) : "memory")

__device__ __forceinline__ void split_bf(float v, u16& h, u16& l) {
    __nv_bfloat16 bh = __float2bfloat16_rn(v);
    float r = v - __bfloat162float(bh);
    __nv_bfloat16 bl = __float2bfloat16_rn(r);
    h = reinterpret_cast<u16&>(bh);
    l = reinterpret_cast<u16&>(bl);
}
__device__ __forceinline__ float tanh_fast(float x) {
    float c = fminf(fmaxf(x, -12.0f), 12.0f);
    float e = __expf(2.0f * c);
    return (e - 1.0f) / (e + 1.0f);
}

// ============================================================
// Elementwise split-convert
// ============================================================
__global__ void convert_hl(const float* __restrict__ src_x, int mode)
{
    const float* __restrict__ src = mode ? (const float*)g_enc : src_x;
    u16* __restrict__ h = mode ? ge_h : gx_h;
    u16* __restrict__ l = mode ? ge_l : gx_l;
    int i = (blockIdx.x * 256 + threadIdx.x) * 4;
    float4 v = *reinterpret_cast<const float4*>(src + i);
    u16 h0, h1, h2, h3, l0, l1, l2, l3;
    split_bf(v.x, h0, l0); split_bf(v.y, h1, l1);
    split_bf(v.z, h2, l2); split_bf(v.w, h3, l3);
    *reinterpret_cast<ull*>(h + i) = (ull)h0 | ((ull)h1 << 16) | ((ull)h2 << 32) | ((ull)h3 << 48);
    *reinterpret_cast<ull*>(l + i) = (ull)l0 | ((ull)l1 << 16) | ((ull)l2 << 32) | ((ull)l3 << 48);
}

// ============================================================
// Weight transpose + split-convert, 32x32 tiles.
// ============================================================
__global__ void wconv(const float* __restrict__ qw, const float* __restrict__ kvw,
                      const float* __restrict__ ow, int mode)
{
    __shared__ float s[32][33];
    const int c0 = blockIdx.x * 32;
    const int k0 = blockIdx.y * 32;
    const int tx = threadIdx.x & 31;
    const int ty = threadIdx.x >> 5;
    u16* __restrict__ dh = mode ? gwo_h : gw_h;
    u16* __restrict__ dl = mode ? gwo_l : gw_l;

#pragma unroll
    for (int rr = ty; rr < 32; rr += 8) {
        int k = k0 + rr;
        int c = c0 + tx;
        float v;
        if (mode == 0) {
            const float* base;
            int cc = c;
            if (cc < 2048)      base = qw + (cc >> 7) * (D_DIM * HD);
            else if (cc < 3072) { cc -= 2048; base = kvw + (cc >> 7) * (D_DIM * HD); }
            else                { cc -= 3072; base = kvw + (8 + (cc >> 7)) * (D_DIM * HD); }
            v = base[k * HD + (cc & 127)];
        } else {
            v = ow[k * D_DIM + c];
        }
        s[tx][rr] = v;
    }
    __syncthreads();
#pragma unroll
    for (int rr = ty; rr < 32; rr += 8) {
        float v = s[rr][tx];
        u16 h, l;
        split_bf(v, h, l);
        dh[(c0 + rr) * D_DIM + k0 + tx] = h;
        dl[(c0 + rr) * D_DIM + k0 + tx] = l;
    }
}

// ============================================================
// HMMA GEMM: 512 threads (16 warps), 3-stage cp.async pipeline,
// per-warp k-slice rotation to overlap LDSM with HMMA.
// ============================================================
#define STAGE_BYTES 65536
#define GEMM_SMEM (3 * STAGE_BYTES)

__device__ __forceinline__ void load_stage512(
    u32 sbase, int p, int tid, int row0, int col0, int kk,
    const u16* __restrict__ Ah, const u16* __restrict__ Al,
    const u16* __restrict__ Bh, const u16* __restrict__ Bl)
{
    u32 stg = sbase + (u32)p * STAGE_BYTES;
#pragma unroll
    for (int l = 0; l < 2; ++l) {
        int idx = tid + l * 512;
        int r = idx >> 3;
        int ch = idx & 7;
        u32 doff = (u32)(r * 128) + (u32)((ch * 16) ^ ((r & 7) << 4));
        int aoff = (row0 + r) * D_DIM + kk + ch * 8;
        int boff = (col0 + r) * D_DIM + kk + ch * 8;
        cp16(stg + doff,             Ah + aoff);
        cp16(stg + 16384 + doff,     Al + aoff);
        cp16(stg + 32768 + doff,     Bh + boff);
        cp16(stg + 49152 + doff,     Bl + boff);
    }
}

__global__ __launch_bounds__(512, 1)
void hmma_gemm(float* __restrict__ dst0, int ldc0, int qkv_mode)
{
    extern __shared__ char smem[];
    const u32 sb = smem_u32(smem);
    const int tid = threadIdx.x;
    const int lane = tid & 31;
    const int w = tid >> 5;
    const int wm = w & 3;
    const int wn = w >> 2;
    const int row0 = blockIdx.y * 128;
    const int col0 = blockIdx.x * 128;
    const int krot = w & 3;          // per-warp k-slice phase

    const u16 *Ah, *Al, *Bh, *Bl;
    float* dst; int ldc, cofs;
    if (qkv_mode) {
        Ah = gx_h; Al = gx_l; Bh = gw_h; Bl = gw_l;
        if (col0 < 2048)      { dst = g_q; ldc = 2048; cofs = col0; }
        else if (col0 < 3072) { dst = g_k; ldc = 1024; cofs = col0 - 2048; }
        else                  { dst = g_v; ldc = 1024; cofs = col0 - 3072; }
    } else {
        Ah = ge_h; Al = ge_l; Bh = gwo_h; Bl = gwo_l;
        dst = dst0; ldc = ldc0; cofs = col0;
    }

    float acc[2][4][4];
#pragma unroll
    for (int i = 0; i < 2; ++i)
#pragma unroll
        for (int j = 0; j < 4; ++j)
#pragma unroll
            for (int q = 0; q < 4; ++q) acc[i][j][q] = 0.0f;

    const u32 aRow = (u32)(wm * 32 + (lane & 15)) * 128;
    const u32 aXor = (u32)((lane & 7) << 4);
    const u32 aK   = (u32)((lane >> 4) * 16);
    const u32 bRow = (u32)(wn * 32 + ((lane >> 4) << 3) + (lane & 7)) * 128;
    const u32 bK   = (u32)(((lane >> 3) & 1) * 16);

    load_stage512(sb, 0, tid, row0, col0, 0, Ah, Al, Bh, Bl);
    CP_COMMIT();
    load_stage512(sb, 1, tid, row0, col0, 64, Ah, Al, Bh, Bl);
    CP_COMMIT();

    int stage_c = 0;
    for (int c = 0; c < 32; ++c) {
        if (c < 31) { CP_WAIT(1); } else { CP_WAIT(0); }
        __syncthreads();
        if (c + 2 < 32) {
            int sn = stage_c + 2; if (sn >= 3) sn -= 3;
            load_stage512(sb, sn, tid, row0, col0, (c + 2) * 64, Ah, Al, Bh, Bl);
            CP_COMMIT();
        }

        const u32 stg = sb + (u32)stage_c * STAGE_BYTES;
#pragma unroll
        for (int kk = 0; kk < 4; ++kk) {
            const int ks = (kk + krot) & 3;       // rotated k-slice
            const u32 kb = (u32)(ks * 32);
            u32 ah[2][4], al[2][4];
#pragma unroll
            for (int mi = 0; mi < 2; ++mi) {
                u32 ao = aRow + (u32)(mi * 2048) + ((aK + kb) ^ aXor);
                ldsm4(ah[mi], stg + ao);
                ldsm4(al[mi], stg + 16384 + ao);
            }
            u32 bh[2][4], bl[2][4];
#pragma unroll
            for (int n4 = 0; n4 < 2; ++n4) {
                u32 bo = bRow + (u32)(n4 * 2048) + ((bK + kb) ^ aXor);
                ldsm4(bh[n4], stg + 32768 + bo);
                ldsm4(bl[n4], stg + 49152 + bo);
            }
            // term 1: Ah x Bh
#pragma unroll
            for (int n4 = 0; n4 < 2; ++n4)
#pragma unroll
                for (int mi = 0; mi < 2; ++mi) {
                    mma_bf16(acc[mi][2 * n4],     ah[mi], bh[n4][0], bh[n4][1]);
                    mma_bf16(acc[mi][2 * n4 + 1], ah[mi], bh[n4][2], bh[n4][3]);
                }
            // term 2: Ah x Bl
#pragma unroll
            for (int n4 = 0; n4 < 2; ++n4)
#pragma unroll
                for (int mi = 0; mi < 2; ++mi) {
                    mma_bf16(acc[mi][2 * n4],     ah[mi], bl[n4][0], bl[n4][1]);
                    mma_bf16(acc[mi][2 * n4 + 1], ah[mi], bl[n4][2], bl[n4][3]);
                }
            // term 3: Al x Bh
#pragma unroll
            for (int n4 = 0; n4 < 2; ++n4)
#pragma unroll
                for (int mi = 0; mi < 2; ++mi) {
                    mma_bf16(acc[mi][2 * n4],     al[mi], bh[n4][0], bh[n4][1]);
                    mma_bf16(acc[mi][2 * n4 + 1], al[mi], bh[n4][2], bh[n4][3]);
                }
        }
        if (++stage_c >= 3) stage_c -= 3;
    }

    const int rbase = row0 + wm * 32 + (lane >> 2);
    const int cbase = cofs + wn * 32 + (lane & 3) * 2;
#pragma unroll
    for (int mi = 0; mi < 2; ++mi) {
#pragma unroll
        for (int nt = 0; nt < 4; ++nt) {
            int r = rbase + mi * 16;
            int cc = cbase + nt * 8;
            *reinterpret_cast<float2*>(dst + r * ldc + cc) =
                make_float2(acc[mi][nt][0], acc[mi][nt][1]);
            *reinterpret_cast<float2*>(dst + (r + 8) * ldc + cc) =
                make_float2(acc[mi][nt][2], acc[mi][nt][3]);
        }
    }
}

// ============================================================
// RoPE + hi/lo split fused.
// ============================================================
__global__ void rope_split(const int* __restrict__ seg)
{
    __shared__ float s_ts[64];
    const int t = blockIdx.x;
    const int tid = threadIdx.x;
    if (tid < 64) {
        double f = (double)tid / 64.0;
        s_ts[tid] = (float)pow(10000.0, f);
    }
    __syncthreads();
    const float pos = (float)seg[t];
    for (int idx = tid; idx < (NQH + NKH) * 64; idx += 256) {
        int head = idx >> 6;
        int i = idx & 63;
        const float* base;
        u16 *dh, *dl;
        int off;
        if (head < NQH) {
            off = t * (NQH * HD) + head * HD;
            base = g_q + off; dh = gq_h + off; dl = gq_l + off;
        } else {
            off = t * (NKH * HD) + (head - NQH) * HD;
            base = g_k + off; dh = gk_h + off; dl = gk_l + off;
        }
        float ang = pos / s_ts[i];
        float sv, cv;
        sincosf(ang, &sv, &cv);
        float x1 = base[i], x2 = base[i + 64];
        float o1 = x1 * cv - x2 * sv;
        float o2 = x2 * cv + x1 * sv;
        if (head < NQH) { o1 *= QSCALE; o2 *= QSCALE; }
        u16 h1, l1, h2, l2;
        split_bf(o1, h1, l1);
        split_bf(o2, h2, l2);
        dh[i] = h1;       dl[i] = l1;
        dh[i + 64] = h2;  dl[i + 64] = l2;
    }
    {
        int off = t * (NKH * HD) + tid * 4;
        float4 v = *reinterpret_cast<const float4*>(g_v + off);
        u16 h0, h1, h2, h3, l0, l1, l2, l3;
        split_bf(v.x, h0, l0); split_bf(v.y, h1, l1);
        split_bf(v.z, h2, l2); split_bf(v.w, h3, l3);
        *reinterpret_cast<ull*>(gv_h + off) = (ull)h0 | ((ull)h1 << 16) | ((ull)h2 << 32) | ((ull)h3 << 48);
        *reinterpret_cast<ull*>(gv_l + off) = (ull)l0 | ((ull)l1 << 16) | ((ull)l2 << 32) | ((ull)l3 << 48);
    }
}

// ============================================================
// Tensor-core sliding-window attention (split-bf16),
// per-warp k-slice rotation in QK and PV loops.
// ============================================================
#define SMEM_Q  0
#define SMEM_K  65536
#define SMEM_V  98304
#define SMEM_S  131072
#define SMEM_P  165888
#define SMEM_AL 198656
#define SMEM_L  199168
#define ATT2_SMEM 199680

__global__ __launch_bounds__(256, 1) void attn_mma()
{
    extern __shared__ char smc[];
    const u32 sb = smem_u32(smc);
    float* S = reinterpret_cast<float*>(smc + SMEM_S);
    float* al_s = reinterpret_cast<float*>(smc + SMEM_AL);
    float* l_s = reinterpret_cast<float*>(smc + SMEM_L);

    const int tid = threadIdx.x;
    const int lane = tid & 31;
    const int w = tid >> 5;
    const int wm = w & 3;
    const int wn = w >> 2;
    const int kh = blockIdx.x;
    const int t0 = (int)(31 - blockIdx.y) * 64;

    // ---- Q tile load ----
#pragma unroll
    for (int l = 0; l < 8; ++l) {
        int idx = tid + l * 256;
        int r = idx >> 4, ch = idx & 15;
        int t = t0 + (r & 63), n = kh * 2 + (r >> 6);
        u32 d = (u32)((ch >> 3) * 16384 + r * 128 + (((ch & 7) * 16) ^ ((r & 7) << 4)));
        cp16(sb + SMEM_Q + d,          gq_h + (size_t)(t * NQH + n) * HD + ch * 8);
        cp16(sb + SMEM_Q + 32768 + d,  gq_l + (size_t)(t * NQH + n) * HD + ch * 8);
    }
    CP_COMMIT();

    float acc_o[2][8][4];
#pragma unroll
    for (int i = 0; i < 2; ++i)
#pragma unroll
        for (int j = 0; j < 8; ++j)
#pragma unroll
            for (int q = 0; q < 4; ++q) acc_o[i][j][q] = 0.0f;

    float m_reg = -1e30f, l_reg = 0.0f;

    const u32 aRow = (u32)((wm * 32 + (lane & 15)) * 128);
    const u32 aK   = (u32)((lane >> 4) * 16);
    const u32 aXor = (u32)((lane & 7) << 4);
    const u32 bK   = (u32)(((lane >> 3) & 1) * 16);
    u32 bRow[2];
    bRow[0] = (u32)((wn * 32 + ((lane >> 4) << 3) + (lane & 7)) * 128);
    bRow[1] = bRow[0] + 16 * 128;
    const int vrow_in = (lane & 7) + (lane & 8);
    const u32 vh8 = (u32)((lane >> 4) << 3);

    const int s_begin = (t0 >= (WINDOW - 1)) ? ((t0 - (WINDOW - 1)) & ~63) : 0;

    for (int st = s_begin; st <= t0; st += 64) {
        // ---- K/V tile load ----
#pragma unroll
        for (int l = 0; l < 4; ++l) {
            int idx = tid + l * 256;
            int r = idx >> 4, ch = idx & 15;
            size_t go = (size_t)((st + r) * NKH + kh) * HD + ch * 8;
            u32 dk = (u32)((ch >> 3) * 8192 + r * 128 + (((ch & 7) * 16) ^ ((r & 7) << 4)));
            u32 dv = (u32)(r * 256 + ((ch * 16) ^ ((r & 7) << 4)));
            cp16(sb + SMEM_K + dk,         gk_h + go);
            cp16(sb + SMEM_K + 16384 + dk, gk_l + go);
            cp16(sb + SMEM_V + dv,         gv_h + go);
            cp16(sb + SMEM_V + 16384 + dv, gv_l + go);
        }
        CP_COMMIT();
        CP_WAIT(0);
        __syncthreads();

        // ---- S = Q K^T (term-major, rotated k-slices) ----
        float s_acc[2][4][4];
#pragma unroll
        for (int i = 0; i < 2; ++i)
#pragma unroll
            for (int j = 0; j < 4; ++j)
#pragma unroll
                for (int q = 0; q < 4; ++q) s_acc[i][j][q] = 0.0f;

#pragma unroll
        for (int kk = 0; kk < 8; ++kk) {
            const int ks = (kk + w) & 7;
            const u32 kc = (u32)(ks >> 2);
            const u32 kb = (u32)((ks & 3) * 32);
            u32 qh[2][4], ql[2][4];
#pragma unroll
            for (int mi = 0; mi < 2; ++mi) {
                u32 ao = kc * 16384 + aRow + (u32)(mi * 2048) + ((aK + kb) ^ aXor);
                ldsm4(qh[mi], sb + SMEM_Q + ao);
                ldsm4(ql[mi], sb + SMEM_Q + 32768 + ao);
            }
            u32 kf[2][4], kl[2][4];
#pragma unroll
            for (int g = 0; g < 2; ++g) {
                u32 bo = kc * 8192 + bRow[g] + ((bK + kb) ^ aXor);
                ldsm4(kf[g], sb + SMEM_K + bo);
                ldsm4(kl[g], sb + SMEM_K + 16384 + bo);
            }
#pragma unroll
            for (int g = 0; g < 2; ++g)
#pragma unroll
                for (int mi = 0; mi < 2; ++mi) {
                    mma_bf16(s_acc[mi][2 * g],     qh[mi], kf[g][0], kf[g][1]);
                    mma_bf16(s_acc[mi][2 * g + 1], qh[mi], kf[g][2], kf[g][3]);
                }
#pragma unroll
            for (int g = 0; g < 2; ++g)
#pragma unroll
                for (int mi = 0; mi < 2; ++mi) {
                    mma_bf16(s_acc[mi][2 * g],     qh[mi], kl[g][0], kl[g][1]);
                    mma_bf16(s_acc[mi][2 * g + 1], qh[mi], kl[g][2], kl[g][3]);
                }
#pragma unroll
            for (int g = 0; g < 2; ++g)
#pragma unroll
                for (int mi = 0; mi < 2; ++mi) {
                    mma_bf16(s_acc[mi][2 * g],     ql[mi], kf[g][0], kf[g][1]);
                    mma_bf16(s_acc[mi][2 * g + 1], ql[mi], kf[g][2], kf[g][3]);
                }
        }

        // ---- softcap + mask, store S ----
#pragma unroll
        for (int mi = 0; mi < 2; ++mi) {
            int r0 = wm * 32 + mi * 16 + (lane >> 2);
#pragma unroll
            for (int n8 = 0; n8 < 4; ++n8) {
                int sl0 = wn * 32 + n8 * 8 + (lane & 3) * 2;
#pragma unroll
                for (int half = 0; half < 2; ++half) {
                    int rr = r0 + half * 8;
                    int t = t0 + (rr & 63);
                    float v0 = tanh_fast(s_acc[mi][n8][half * 2]     * (1.0f / SOFTCAP)) * SOFTCAP;
                    float v1 = tanh_fast(s_acc[mi][n8][half * 2 + 1] * (1.0f / SOFTCAP)) * SOFTCAP;
                    int sg0 = st + sl0, sg1 = sg0 + 1;
                    bool ok0 = (sg0 <= t) && (sg0 > t - WINDOW);
                    bool ok1 = (sg1 <= t) && (sg1 > t - WINDOW);
                    *reinterpret_cast<float2*>(&S[rr * 68 + sl0]) =
                        make_float2(ok0 ? v0 : -1e30f, ok1 ? v1 : -1e30f);
                }
            }
        }
        __syncthreads();

        // ---- online softmax: 2 threads per row ----
        {
            const int row = tid >> 1;
            const int half = tid & 1;
            const int cb = half * 32;
            float tm = -1e30f;
#pragma unroll 8
            for (int c = 0; c < 32; ++c) tm = fmaxf(tm, S[row * 68 + cb + c]);
            tm = fmaxf(tm, __shfl_xor_sync(0xffffffffu, tm, 1));
            float mnew = fmaxf(m_reg, tm);
            float a = __expf(m_reg - mnew);
            float lsum = 0.0f;
            char* ph = smc + SMEM_P + row * 128;
            char* pl = smc + SMEM_P + 16384 + row * 128;
            const u32 xr = (u32)((row & 7) << 4);
#pragma unroll 8
            for (int c = 0; c < 32; ++c) {
                float p = __expf(S[row * 68 + cb + c] - mnew);
                lsum += p;
                u16 hh, ll;
                split_bf(p, hh, ll);
                u32 off = ((u32)((cb + c) * 2)) ^ xr;
                *reinterpret_cast<u16*>(ph + off) = hh;
                *reinterpret_cast<u16*>(pl + off) = ll;
            }
            lsum += __shfl_xor_sync(0xffffffffu, lsum, 1);
            l_reg = l_reg * a + lsum;
            m_reg = mnew;
            if (half == 0) al_s[row] = a;
        }
        __syncthreads();

        // ---- rescale O, then O += P V (term-major, rotated) ----
#pragma unroll
        for (int mi = 0; mi < 2; ++mi) {
            int r0 = wm * 32 + mi * 16 + (lane >> 2);
            float a0 = al_s[r0], a1 = al_s[r0 + 8];
#pragma unroll
            for (int n8 = 0; n8 < 8; ++n8) {
                acc_o[mi][n8][0] *= a0; acc_o[mi][n8][1] *= a0;
                acc_o[mi][n8][2] *= a1; acc_o[mi][n8][3] *= a1;
            }
        }
#pragma unroll
        for (int kk = 0; kk < 4; ++kk) {
            const int ks = (kk + (w & 3)) & 3;
            const u32 kb = (u32)(ks * 32);
            u32 ph[2][4], pl[2][4];
#pragma unroll
            for (int mi = 0; mi < 2; ++mi) {
                u32 ao = aRow + (u32)(mi * 2048) + ((aK + kb) ^ aXor);
                ldsm4(ph[mi], sb + SMEM_P + ao);
                ldsm4(pl[mi], sb + SMEM_P + 16384 + ao);
            }
            const int vrow = ks * 16 + vrow_in;
            const u32 vswz = (u32)(vrow * 256);
            const u32 vxr = (u32)((vrow & 7) << 4);
#pragma unroll
            for (int pg = 0; pg < 2; ++pg) {
                u32 vhf[2][4], vlf[2][4];
#pragma unroll
                for (int j = 0; j < 2; ++j) {
                    int pair = pg * 2 + j;
                    u32 hq = (u32)(wn * 64 + pair * 16) + vh8;
                    u32 va = sb + SMEM_V + vswz + (((hq >> 3) * 16) ^ vxr);
                    ldsm4t(vhf[j], va);
                    ldsm4t(vlf[j], va + 16384);
                }
#pragma unroll
                for (int j = 0; j < 2; ++j) {
                    int pair = pg * 2 + j;
#pragma unroll
                    for (int mi = 0; mi < 2; ++mi) {
                        mma_bf16(acc_o[mi][pair * 2],     ph[mi], vhf[j][0], vhf[j][1]);
                        mma_bf16(acc_o[mi][pair * 2 + 1], ph[mi], vhf[j][2], vhf[j][3]);
                    }
                }
#pragma unroll
                for (int j = 0; j < 2; ++j) {
                    int pair = pg * 2 + j;
#pragma unroll
                    for (int mi = 0; mi < 2; ++mi) {
                        mma_bf16(acc_o[mi][pair * 2],     ph[mi], vlf[j][0], vlf[j][1]);
                        mma_bf16(acc_o[mi][pair * 2 + 1], ph[mi], vlf[j][2], vlf[j][3]);
                    }
                }
#pragma unroll
                for (int j = 0; j < 2; ++j) {
                    int pair = pg * 2 + j;
#pragma unroll
                    for (int mi = 0; mi < 2; ++mi) {
                        mma_bf16(acc_o[mi][pair * 2],     pl[mi], vhf[j][0], vhf[j][1]);
                        mma_bf16(acc_o[mi][pair * 2 + 1], pl[mi], vhf[j][2], vhf[j][3]);
                    }
                }
            }
        }
        __syncthreads();
    }

    if ((tid & 1) == 0) l_s[tid >> 1] = l_reg;
    __syncthreads();

#pragma unroll
    for (int mi = 0; mi < 2; ++mi) {
        int r0 = wm * 32 + mi * 16 + (lane >> 2);
        float i0 = 1.0f / l_s[r0];
        float i1 = 1.0f / l_s[r0 + 8];
#pragma unroll
        for (int n8 = 0; n8 < 8; ++n8) {
            int h = wn * 64 + n8 * 8 + (lane & 3) * 2;
#pragma unroll
            for (int half = 0; half < 2; ++half) {
                int rr = r0 + half * 8;
                int t = t0 + (rr & 63);
                int n = kh * 2 + (rr >> 6);
                float iv = half ? i1 : i0;
                *reinterpret_cast<float2*>(&g_enc[(size_t)(t * NQH + n) * HD + h]) =
                    make_float2(acc_o[mi][n8][half * 2] * iv,
                                acc_o[mi][n8][half * 2 + 1] * iv);
            }
        }
    }
}

// ============================================================
extern "C" void kernel_launch(void* const* d_in, const int* in_sizes, int n_in,
                              void* d_out, int out_size)
{
    (void)in_sizes; (void)n_in; (void)out_size;
    const float* x   = (const float*)d_in[0];
    const int*   seg = (const int*)d_in[1];
    const float* qw  = (const float*)d_in[3];
    const float* kvw = (const float*)d_in[4];
    const float* ow  = (const float*)d_in[5];
    float* out = (float*)d_out;

    cudaFuncSetAttribute(hmma_gemm, cudaFuncAttributeMaxDynamicSharedMemorySize, GEMM_SMEM);
    cudaFuncSetAttribute(attn_mma, cudaFuncAttributeMaxDynamicSharedMemorySize, ATT2_SMEM);

    convert_hl<<<4096, 256>>>(x, 0);
    wconv<<<dim3(128, 64), 256>>>(qw, kvw, ow, 0);
    wconv<<<dim3(64, 64), 256>>>(qw, kvw, ow, 1);
    hmma_gemm<<<dim3(32, 16), 512, GEMM_SMEM>>>(nullptr, 0, 1);   // qkv
    rope_split<<<T_DIM, 256>>>(seg);
    attn_mma<<<dim3(NKH, 32), 256, ATT2_SMEM>>>();
    convert_hl<<<4096, 256>>>(x, 1);                               // g_enc -> ge
    hmma_gemm<<<dim3(16, 16), 512, GEMM_SMEM>>>(out, D_DIM, 0);   // out proj
}

// round 11
// speedup vs baseline: 3.4844x; 1.1689x over previous
#include <cuda_runtime.h>
#include <cuda_bf16.h>
#include <cuda_fp16.h>
#include <math.h>

typedef unsigned long long ull;
typedef unsigned int u32;
typedef unsigned short u16;

#define T_DIM 2048
#define D_DIM 2048
#define NQH 16
#define NKH 8
#define HD 128
#define WINDOW 1024
#define SOFTCAP 50.0f
#define QSCALE 0.08838834764831845f
#define QELEMS (T_DIM * NQH * HD)
#define KVELEMS (T_DIM * NKH * HD)

// fp32 scratch
__device__ float g_q[QELEMS];
__device__ float g_k[KVELEMS];
__device__ float g_v[KVELEMS];
__device__ float g_enc[QELEMS];

// fp16 split activations + single-fp16 weights (projection GEMMs)
__device__ u16 gx_h[T_DIM * D_DIM], gx_l[T_DIM * D_DIM];
__device__ u16 ge_h[T_DIM * D_DIM], ge_l[T_DIM * D_DIM];
__device__ u16 gw[4096 * D_DIM];        // qkv weights fp16, [col][k]
__device__ u16 gwo[D_DIM * D_DIM];      // out weights fp16, [col][k]
// bf16 split q/k/v (attention, 3-term path)
__device__ u16 gq_h[QELEMS], gq_l[QELEMS];
__device__ u16 gk_h[KVELEMS], gk_l[KVELEMS];
__device__ u16 gv_h[KVELEMS], gv_l[KVELEMS];

__device__ __forceinline__ u32 smem_u32(const void* p) {
    u32 a; asm("{ .reg .u64 t; cvta.to.shared.u64 t, %1; cvt.u32.u64 %0, t; }" : "=r"(a) : "l"(p));
    return a;
}
__device__ __forceinline__ void ldsm4(u32* r, u32 addr) {
    asm volatile("ldmatrix.sync.aligned.m8n8.x4.shared.b16 {%0,%1,%2,%3}, [%4];"
        : "=r"(r[0]), "=r"(r[1]), "=r"(r[2]), "=r"(r[3]) : "r"(addr));
}
__device__ __forceinline__ void ldsm4t(u32* r, u32 addr) {
    asm volatile("ldmatrix.sync.aligned.m8n8.x4.trans.shared.b16 {%0,%1,%2,%3}, [%4];"
        : "=r"(r[0]), "=r"(r[1]), "=r"(r[2]), "=r"(r[3]) : "r"(addr));
}
__device__ __forceinline__ void mma_bf16(float* c, const u32* a, u32 b0, u32 b1) {
    asm volatile("mma.sync.aligned.m16n8k16.row.col.f32.bf16.bf16.f32 "
        "{%0,%1,%2,%3}, {%4,%5,%6,%7}, {%8,%9}, {%0,%1,%2,%3};"
        : "+f"(c[0]), "+f"(c[1]), "+f"(c[2]), "+f"(c[3])
        : "r"(a[0]), "r"(a[1]), "r"(a[2]), "r"(a[3]), "r"(b0), "r"(b1));
}
__device__ __forceinline__ void mma_f16(float* c, const u32* a, u32 b0, u32 b1) {
    asm volatile("mma.sync.aligned.m16n8k16.row.col.f32.f16.f16.f32 "
        "{%0,%1,%2,%3}, {%4,%5,%6,%7}, {%8,%9}, {%0,%1,%2,%3};"
        : "+f"(c[0]), "+f"(c[1]), "+f"(c[2]), "+f"(c[3])
        : "r"(a[0]), "r"(a[1]), "r"(a[2]), "r"(a[3]), "r"(b0), "r"(b1));
}
__device__ __forceinline__ void cp16(u32 dst, const void* src) {
    asm volatile("cp.async.cg.shared.global [%0], [%1], 16;" :: "r"(dst), "l"(src));
}
#define CP_COMMIT() asm volatile("cp.async.commit_group;" ::: "memory")
#define CP_WAIT(n)  asm volatile("cp.async.wait_group %0;" :: "n"(n) : "memory")

__device__ __forceinline__ void split_bf(float v, u16& h, u16& l) {
    __nv_bfloat16 bh = __float2bfloat16_rn(v);
    float r = v - __bfloat162float(bh);
    __nv_bfloat16 bl = __float2bfloat16_rn(r);
    h = reinterpret_cast<u16&>(bh);
    l = reinterpret_cast<u16&>(bl);
}
__device__ __forceinline__ void split_fp16(float v, u16& h, u16& l) {
    __half hh = __float2half_rn(v);
    float r = v - __half2float(hh);
    __half ll = __float2half_rn(r);
    h = reinterpret_cast<u16&>(hh);
    l = reinterpret_cast<u16&>(ll);
}
__device__ __forceinline__ float tanh_fast(float x) {
    float c = fminf(fmaxf(x, -12.0f), 12.0f);
    float e = __expf(2.0f * c);
    return (e - 1.0f) / (e + 1.0f);
}

// ============================================================
// Elementwise split-convert to fp16 hi/lo (x or enc)
// ============================================================
__global__ void convert_hl(const float* __restrict__ src_x, int mode)
{
    const float* __restrict__ src = mode ? (const float*)g_enc : src_x;
    u16* __restrict__ h = mode ? ge_h : gx_h;
    u16* __restrict__ l = mode ? ge_l : gx_l;
    int i = (blockIdx.x * 256 + threadIdx.x) * 4;
    float4 v = *reinterpret_cast<const float4*>(src + i);
    u16 h0, h1, h2, h3, l0, l1, l2, l3;
    split_fp16(v.x, h0, l0); split_fp16(v.y, h1, l1);
    split_fp16(v.z, h2, l2); split_fp16(v.w, h3, l3);
    *reinterpret_cast<ull*>(h + i) = (ull)h0 | ((ull)h1 << 16) | ((ull)h2 << 32) | ((ull)h3 << 48);
    *reinterpret_cast<ull*>(l + i) = (ull)l0 | ((ull)l1 << 16) | ((ull)l2 << 32) | ((ull)l3 << 48);
}

// ============================================================
// Weight transpose + fp16 convert, 32x32 tiles.
// ============================================================
__global__ void wconv(const float* __restrict__ qw, const float* __restrict__ kvw,
                      const float* __restrict__ ow, int mode)
{
    __shared__ float s[32][33];
    const int c0 = blockIdx.x * 32;
    const int k0 = blockIdx.y * 32;
    const int tx = threadIdx.x & 31;
    const int ty = threadIdx.x >> 5;
    u16* __restrict__ dh = mode ? gwo : gw;

#pragma unroll
    for (int rr = ty; rr < 32; rr += 8) {
        int k = k0 + rr;
        int c = c0 + tx;
        float v;
        if (mode == 0) {
            const float* base;
            int cc = c;
            if (cc < 2048)      base = qw + (cc >> 7) * (D_DIM * HD);
            else if (cc < 3072) { cc -= 2048; base = kvw + (cc >> 7) * (D_DIM * HD); }
            else                { cc -= 3072; base = kvw + (8 + (cc >> 7)) * (D_DIM * HD); }
            v = base[k * HD + (cc & 127)];
        } else {
            v = ow[k * D_DIM + c];
        }
        s[tx][rr] = v;
    }
    __syncthreads();
#pragma unroll
    for (int rr = ty; rr < 32; rr += 8) {
        __half hv = __float2half_rn(s[rr][tx]);
        dh[(c0 + rr) * D_DIM + k0 + tx] = reinterpret_cast<u16&>(hv);
    }
}

// ============================================================
// HMMA GEMM, fp16 2-term: C = Ah*B + Al*B.
// 512 threads, 3-stage cp.async pipeline.
// Stage: Ah(16K) | Al(16K) | B(16K)
// ============================================================
#define STAGE_BYTES 49152
#define GEMM_SMEM (3 * STAGE_BYTES)

__device__ __forceinline__ void load_stage512(
    u32 sbase, int p, int tid, int row0, int col0, int kk,
    const u16* __restrict__ Ah, const u16* __restrict__ Al,
    const u16* __restrict__ B)
{
    u32 stg = sbase + (u32)p * STAGE_BYTES;
#pragma unroll
    for (int l = 0; l < 2; ++l) {
        int idx = tid + l * 512;
        int r = idx >> 3;
        int ch = idx & 7;
        u32 doff = (u32)(r * 128) + (u32)((ch * 16) ^ ((r & 7) << 4));
        int aoff = (row0 + r) * D_DIM + kk + ch * 8;
        int boff = (col0 + r) * D_DIM + kk + ch * 8;
        cp16(stg + doff,             Ah + aoff);
        cp16(stg + 16384 + doff,     Al + aoff);
        cp16(stg + 32768 + doff,     B + boff);
    }
}

__global__ __launch_bounds__(512, 1)
void hmma_gemm(float* __restrict__ dst0, int ldc0, int qkv_mode)
{
    extern __shared__ char smem[];
    const u32 sb = smem_u32(smem);
    const int tid = threadIdx.x;
    const int lane = tid & 31;
    const int w = tid >> 5;
    const int wm = w & 3;
    const int wn = w >> 2;
    const int row0 = blockIdx.y * 128;
    const int col0 = blockIdx.x * 128;

    const u16 *Ah, *Al, *B;
    float* dst; int ldc, cofs;
    if (qkv_mode) {
        Ah = gx_h; Al = gx_l; B = gw;
        if (col0 < 2048)      { dst = g_q; ldc = 2048; cofs = col0; }
        else if (col0 < 3072) { dst = g_k; ldc = 1024; cofs = col0 - 2048; }
        else                  { dst = g_v; ldc = 1024; cofs = col0 - 3072; }
    } else {
        Ah = ge_h; Al = ge_l; B = gwo;
        dst = dst0; ldc = ldc0; cofs = col0;
    }

    float acc[2][4][4];
#pragma unroll
    for (int i = 0; i < 2; ++i)
#pragma unroll
        for (int j = 0; j < 4; ++j)
#pragma unroll
            for (int q = 0; q < 4; ++q) acc[i][j][q] = 0.0f;

    const u32 aRow = (u32)(wm * 32 + (lane & 15)) * 128;
    const u32 aXor = (u32)((lane & 7) << 4);
    const u32 aK   = (u32)((lane >> 4) * 16);
    const u32 bRow = (u32)(wn * 32 + ((lane >> 4) << 3) + (lane & 7)) * 128;
    const u32 bK   = (u32)(((lane >> 3) & 1) * 16);

    load_stage512(sb, 0, tid, row0, col0, 0, Ah, Al, B);
    CP_COMMIT();
    load_stage512(sb, 1, tid, row0, col0, 64, Ah, Al, B);
    CP_COMMIT();

    int stage_c = 0;
    for (int c = 0; c < 32; ++c) {
        if (c < 31) { CP_WAIT(1); } else { CP_WAIT(0); }
        __syncthreads();
        if (c + 2 < 32) {
            int sn = stage_c + 2; if (sn >= 3) sn -= 3;
            load_stage512(sb, sn, tid, row0, col0, (c + 2) * 64, Ah, Al, B);
            CP_COMMIT();
        }

        const u32 stg = sb + (u32)stage_c * STAGE_BYTES;
#pragma unroll
        for (int ks = 0; ks < 4; ++ks) {
            const u32 kb = (u32)(ks * 32);
            u32 ah[2][4], al[2][4];
#pragma unroll
            for (int mi = 0; mi < 2; ++mi) {
                u32 ao = aRow + (u32)(mi * 2048) + ((aK + kb) ^ aXor);
                ldsm4(ah[mi], stg + ao);
                ldsm4(al[mi], stg + 16384 + ao);
            }
            u32 bf[2][4];
#pragma unroll
            for (int n4 = 0; n4 < 2; ++n4) {
                u32 bo = bRow + (u32)(n4 * 2048) + ((bK + kb) ^ aXor);
                ldsm4(bf[n4], stg + 32768 + bo);
            }
            // term 1: Ah x B
#pragma unroll
            for (int n4 = 0; n4 < 2; ++n4)
#pragma unroll
                for (int mi = 0; mi < 2; ++mi) {
                    mma_f16(acc[mi][2 * n4],     ah[mi], bf[n4][0], bf[n4][1]);
                    mma_f16(acc[mi][2 * n4 + 1], ah[mi], bf[n4][2], bf[n4][3]);
                }
            // term 2: Al x B
#pragma unroll
            for (int n4 = 0; n4 < 2; ++n4)
#pragma unroll
                for (int mi = 0; mi < 2; ++mi) {
                    mma_f16(acc[mi][2 * n4],     al[mi], bf[n4][0], bf[n4][1]);
                    mma_f16(acc[mi][2 * n4 + 1], al[mi], bf[n4][2], bf[n4][3]);
                }
        }
        if (++stage_c >= 3) stage_c -= 3;
    }

    const int rbase = row0 + wm * 32 + (lane >> 2);
    const int cbase = cofs + wn * 32 + (lane & 3) * 2;
#pragma unroll
    for (int mi = 0; mi < 2; ++mi) {
#pragma unroll
        for (int nt = 0; nt < 4; ++nt) {
            int r = rbase + mi * 16;
            int cc = cbase + nt * 8;
            *reinterpret_cast<float2*>(dst + r * ldc + cc) =
                make_float2(acc[mi][nt][0], acc[mi][nt][1]);
            *reinterpret_cast<float2*>(dst + (r + 8) * ldc + cc) =
                make_float2(acc[mi][nt][2], acc[mi][nt][3]);
        }
    }
}

// ============================================================
// RoPE + bf16 hi/lo split fused (attention operands).
// ============================================================
__global__ void rope_split(const int* __restrict__ seg)
{
    __shared__ float s_ts[64];
    const int t = blockIdx.x;
    const int tid = threadIdx.x;
    if (tid < 64) {
        double f = (double)tid / 64.0;
        s_ts[tid] = (float)pow(10000.0, f);
    }
    __syncthreads();
    const float pos = (float)seg[t];
    for (int idx = tid; idx < (NQH + NKH) * 64; idx += 256) {
        int head = idx >> 6;
        int i = idx & 63;
        const float* base;
        u16 *dh, *dl;
        int off;
        if (head < NQH) {
            off = t * (NQH * HD) + head * HD;
            base = g_q + off; dh = gq_h + off; dl = gq_l + off;
        } else {
            off = t * (NKH * HD) + (head - NQH) * HD;
            base = g_k + off; dh = gk_h + off; dl = gk_l + off;
        }
        float ang = pos / s_ts[i];
        float sv, cv;
        sincosf(ang, &sv, &cv);
        float x1 = base[i], x2 = base[i + 64];
        float o1 = x1 * cv - x2 * sv;
        float o2 = x2 * cv + x1 * sv;
        if (head < NQH) { o1 *= QSCALE; o2 *= QSCALE; }
        u16 h1, l1, h2, l2;
        split_bf(o1, h1, l1);
        split_bf(o2, h2, l2);
        dh[i] = h1;       dl[i] = l1;
        dh[i + 64] = h2;  dl[i + 64] = l2;
    }
    {
        int off = t * (NKH * HD) + tid * 4;
        float4 v = *reinterpret_cast<const float4*>(g_v + off);
        u16 h0, h1, h2, h3, l0, l1, l2, l3;
        split_bf(v.x, h0, l0); split_bf(v.y, h1, l1);
        split_bf(v.z, h2, l2); split_bf(v.w, h3, l3);
        *reinterpret_cast<ull*>(gv_h + off) = (ull)h0 | ((ull)h1 << 16) | ((ull)h2 << 32) | ((ull)h3 << 48);
        *reinterpret_cast<ull*>(gv_l + off) = (ull)l0 | ((ull)l1 << 16) | ((ull)l2 << 32) | ((ull)l3 << 48);
    }
}

// ============================================================
// Tensor-core sliding-window attention (bf16 3-term, R8-verified).
// ============================================================
#define SMEM_Q  0
#define SMEM_K  65536
#define SMEM_V  98304
#define SMEM_S  131072
#define SMEM_P  165888
#define SMEM_AL 198656
#define SMEM_L  199168
#define ATT2_SMEM 199680

__global__ __launch_bounds__(256, 1) void attn_mma()
{
    extern __shared__ char smc[];
    const u32 sb = smem_u32(smc);
    float* S = reinterpret_cast<float*>(smc + SMEM_S);
    float* al_s = reinterpret_cast<float*>(smc + SMEM_AL);
    float* l_s = reinterpret_cast<float*>(smc + SMEM_L);

    const int tid = threadIdx.x;
    const int lane = tid & 31;
    const int w = tid >> 5;
    const int wm = w & 3;
    const int wn = w >> 2;
    const int kh = blockIdx.x;
    const int t0 = (int)(31 - blockIdx.y) * 64;

#pragma unroll
    for (int l = 0; l < 8; ++l) {
        int idx = tid + l * 256;
        int r = idx >> 4, ch = idx & 15;
        int t = t0 + (r & 63), n = kh * 2 + (r >> 6);
        u32 d = (u32)((ch >> 3) * 16384 + r * 128 + (((ch & 7) * 16) ^ ((r & 7) << 4)));
        cp16(sb + SMEM_Q + d,          gq_h + (size_t)(t * NQH + n) * HD + ch * 8);
        cp16(sb + SMEM_Q + 32768 + d,  gq_l + (size_t)(t * NQH + n) * HD + ch * 8);
    }
    CP_COMMIT();

    float acc_o[2][8][4];
#pragma unroll
    for (int i = 0; i < 2; ++i)
#pragma unroll
        for (int j = 0; j < 8; ++j)
#pragma unroll
            for (int q = 0; q < 4; ++q) acc_o[i][j][q] = 0.0f;

    float m_reg = -1e30f, l_reg = 0.0f;

    const u32 aRow = (u32)((wm * 32 + (lane & 15)) * 128);
    const u32 aK   = (u32)((lane >> 4) * 16);
    const u32 aXor = (u32)((lane & 7) << 4);
    const u32 bK   = (u32)(((lane >> 3) & 1) * 16);
    u32 bRow[2];
    bRow[0] = (u32)((wn * 32 + ((lane >> 4) << 3) + (lane & 7)) * 128);
    bRow[1] = bRow[0] + 16 * 128;
    const int vrow_in = (lane & 7) + (lane & 8);
    const u32 vh8 = (u32)((lane >> 4) << 3);

    const int s_begin = (t0 >= (WINDOW - 1)) ? ((t0 - (WINDOW - 1)) & ~63) : 0;

    for (int st = s_begin; st <= t0; st += 64) {
#pragma unroll
        for (int l = 0; l < 4; ++l) {
            int idx = tid + l * 256;
            int r = idx >> 4, ch = idx & 15;
            size_t go = (size_t)((st + r) * NKH + kh) * HD + ch * 8;
            u32 dk = (u32)((ch >> 3) * 8192 + r * 128 + (((ch & 7) * 16) ^ ((r & 7) << 4)));
            u32 dv = (u32)(r * 256 + ((ch * 16) ^ ((r & 7) << 4)));
            cp16(sb + SMEM_K + dk,         gk_h + go);
            cp16(sb + SMEM_K + 16384 + dk, gk_l + go);
            cp16(sb + SMEM_V + dv,         gv_h + go);
            cp16(sb + SMEM_V + 16384 + dv, gv_l + go);
        }
        CP_COMMIT();
        CP_WAIT(0);
        __syncthreads();

        float s_acc[2][4][4];
#pragma unroll
        for (int i = 0; i < 2; ++i)
#pragma unroll
            for (int j = 0; j < 4; ++j)
#pragma unroll
                for (int q = 0; q < 4; ++q) s_acc[i][j][q] = 0.0f;

#pragma unroll
        for (int kk = 0; kk < 8; ++kk) {
            const int ks = (kk + w) & 7;
            const u32 kc = (u32)(ks >> 2);
            const u32 kb = (u32)((ks & 3) * 32);
            u32 qh[2][4], ql[2][4];
#pragma unroll
            for (int mi = 0; mi < 2; ++mi) {
                u32 ao = kc * 16384 + aRow + (u32)(mi * 2048) + ((aK + kb) ^ aXor);
                ldsm4(qh[mi], sb + SMEM_Q + ao);
                ldsm4(ql[mi], sb + SMEM_Q + 32768 + ao);
            }
            u32 kf[2][4], kl[2][4];
#pragma unroll
            for (int g = 0; g < 2; ++g) {
                u32 bo = kc * 8192 + bRow[g] + ((bK + kb) ^ aXor);
                ldsm4(kf[g], sb + SMEM_K + bo);
                ldsm4(kl[g], sb + SMEM_K + 16384 + bo);
            }
#pragma unroll
            for (int g = 0; g < 2; ++g)
#pragma unroll
                for (int mi = 0; mi < 2; ++mi) {
                    mma_bf16(s_acc[mi][2 * g],     qh[mi], kf[g][0], kf[g][1]);
                    mma_bf16(s_acc[mi][2 * g + 1], qh[mi], kf[g][2], kf[g][3]);
                }
#pragma unroll
            for (int g = 0; g < 2; ++g)
#pragma unroll
                for (int mi = 0; mi < 2; ++mi) {
                    mma_bf16(s_acc[mi][2 * g],     qh[mi], kl[g][0], kl[g][1]);
                    mma_bf16(s_acc[mi][2 * g + 1], qh[mi], kl[g][2], kl[g][3]);
                }
#pragma unroll
            for (int g = 0; g < 2; ++g)
#pragma unroll
                for (int mi = 0; mi < 2; ++mi) {
                    mma_bf16(s_acc[mi][2 * g],     ql[mi], kf[g][0], kf[g][1]);
                    mma_bf16(s_acc[mi][2 * g + 1], ql[mi], kf[g][2], kf[g][3]);
                }
        }

#pragma unroll
        for (int mi = 0; mi < 2; ++mi) {
            int r0 = wm * 32 + mi * 16 + (lane >> 2);
#pragma unroll
            for (int n8 = 0; n8 < 4; ++n8) {
                int sl0 = wn * 32 + n8 * 8 + (lane & 3) * 2;
#pragma unroll
                for (int half = 0; half < 2; ++half) {
                    int rr = r0 + half * 8;
                    int t = t0 + (rr & 63);
                    float v0 = tanh_fast(s_acc[mi][n8][half * 2]     * (1.0f / SOFTCAP)) * SOFTCAP;
                    float v1 = tanh_fast(s_acc[mi][n8][half * 2 + 1] * (1.0f / SOFTCAP)) * SOFTCAP;
                    int sg0 = st + sl0, sg1 = sg0 + 1;
                    bool ok0 = (sg0 <= t) && (sg0 > t - WINDOW);
                    bool ok1 = (sg1 <= t) && (sg1 > t - WINDOW);
                    *reinterpret_cast<float2*>(&S[rr * 68 + sl0]) =
                        make_float2(ok0 ? v0 : -1e30f, ok1 ? v1 : -1e30f);
                }
            }
        }
        __syncthreads();

        {
            const int row = tid >> 1;
            const int half = tid & 1;
            const int cb = half * 32;
            float tm = -1e30f;
#pragma unroll 8
            for (int c = 0; c < 32; ++c) tm = fmaxf(tm, S[row * 68 + cb + c]);
            tm = fmaxf(tm, __shfl_xor_sync(0xffffffffu, tm, 1));
            float mnew = fmaxf(m_reg, tm);
            float a = __expf(m_reg - mnew);
            float lsum = 0.0f;
            char* ph = smc + SMEM_P + row * 128;
            char* pl = smc + SMEM_P + 16384 + row * 128;
            const u32 xr = (u32)((row & 7) << 4);
#pragma unroll 8
            for (int c = 0; c < 32; ++c) {
                float p = __expf(S[row * 68 + cb + c] - mnew);
                lsum += p;
                u16 hh, ll;
                split_bf(p, hh, ll);
                u32 off = ((u32)((cb + c) * 2)) ^ xr;
                *reinterpret_cast<u16*>(ph + off) = hh;
                *reinterpret_cast<u16*>(pl + off) = ll;
            }
            lsum += __shfl_xor_sync(0xffffffffu, lsum, 1);
            l_reg = l_reg * a + lsum;
            m_reg = mnew;
            if (half == 0) al_s[row] = a;
        }
        __syncthreads();

#pragma unroll
        for (int mi = 0; mi < 2; ++mi) {
            int r0 = wm * 32 + mi * 16 + (lane >> 2);
            float a0 = al_s[r0], a1 = al_s[r0 + 8];
#pragma unroll
            for (int n8 = 0; n8 < 8; ++n8) {
                acc_o[mi][n8][0] *= a0; acc_o[mi][n8][1] *= a0;
                acc_o[mi][n8][2] *= a1; acc_o[mi][n8][3] *= a1;
            }
        }
#pragma unroll
        for (int kk = 0; kk < 4; ++kk) {
            const int ks = (kk + (w & 3)) & 3;
            const u32 kb = (u32)(ks * 32);
            u32 ph[2][4], pl[2][4];
#pragma unroll
            for (int mi = 0; mi < 2; ++mi) {
                u32 ao = aRow + (u32)(mi * 2048) + ((aK + kb) ^ aXor);
                ldsm4(ph[mi], sb + SMEM_P + ao);
                ldsm4(pl[mi], sb + SMEM_P + 16384 + ao);
            }
            const int vrow = ks * 16 + vrow_in;
            const u32 vswz = (u32)(vrow * 256);
            const u32 vxr = (u32)((vrow & 7) << 4);
#pragma unroll
            for (int pg = 0; pg < 2; ++pg) {
                u32 vhf[2][4], vlf[2][4];
#pragma unroll
                for (int j = 0; j < 2; ++j) {
                    int pair = pg * 2 + j;
                    u32 hq = (u32)(wn * 64 + pair * 16) + vh8;
                    u32 va = sb + SMEM_V + vswz + (((hq >> 3) * 16) ^ vxr);
                    ldsm4t(vhf[j], va);
                    ldsm4t(vlf[j], va + 16384);
                }
#pragma unroll
                for (int j = 0; j < 2; ++j) {
                    int pair = pg * 2 + j;
#pragma unroll
                    for (int mi = 0; mi < 2; ++mi) {
                        mma_bf16(acc_o[mi][pair * 2],     ph[mi], vhf[j][0], vhf[j][1]);
                        mma_bf16(acc_o[mi][pair * 2 + 1], ph[mi], vhf[j][2], vhf[j][3]);
                    }
                }
#pragma unroll
                for (int j = 0; j < 2; ++j) {
                    int pair = pg * 2 + j;
#pragma unroll
                    for (int mi = 0; mi < 2; ++mi) {
                        mma_bf16(acc_o[mi][pair * 2],     ph[mi], vlf[j][0], vlf[j][1]);
                        mma_bf16(acc_o[mi][pair * 2 + 1], ph[mi], vlf[j][2], vlf[j][3]);
                    }
                }
#pragma unroll
                for (int j = 0; j < 2; ++j) {
                    int pair = pg * 2 + j;
#pragma unroll
                    for (int mi = 0; mi < 2; ++mi) {
                        mma_bf16(acc_o[mi][pair * 2],     pl[mi], vhf[j][0], vhf[j][1]);
                        mma_bf16(acc_o[mi][pair * 2 + 1], pl[mi], vhf[j][2], vhf[j][3]);
                    }
                }
            }
        }
        __syncthreads();
    }

    if ((tid & 1) == 0) l_s[tid >> 1] = l_reg;
    __syncthreads();

#pragma unroll
    for (int mi = 0; mi < 2; ++mi) {
        int r0 = wm * 32 + mi * 16 + (lane >> 2);
        float i0 = 1.0f / l_s[r0];
        float i1 = 1.0f / l_s[r0 + 8];
#pragma unroll
        for (int n8 = 0; n8 < 8; ++n8) {
            int h = wn * 64 + n8 * 8 + (lane & 3) * 2;
#pragma unroll
            for (int half = 0; half < 2; ++half) {
                int rr = r0 + half * 8;
                int t = t0 + (rr & 63);
                int n = kh * 2 + (rr >> 6);
                float iv = half ? i1 : i0;
                *reinterpret_cast<float2*>(&g_enc[(size_t)(t * NQH + n) * HD + h]) =
                    make_float2(acc_o[mi][n8][half * 2] * iv,
                                acc_o[mi][n8][half * 2 + 1] * iv);
            }
        }
    }
}

// ============================================================
extern "C" void kernel_launch(void* const* d_in, const int* in_sizes, int n_in,
                              void* d_out, int out_size)
{
    (void)in_sizes; (void)n_in; (void)out_size;
    const float* x   = (const float*)d_in[0];
    const int*   seg = (const int*)d_in[1];
    const float* qw  = (const float*)d_in[3];
    const float* kvw = (const float*)d_in[4];
    const float* ow  = (const float*)d_in[5];
    float* out = (float*)d_out;

    cudaFuncSetAttribute(hmma_gemm, cudaFuncAttributeMaxDynamicSharedMemorySize, GEMM_SMEM);
    cudaFuncSetAttribute(attn_mma, cudaFuncAttributeMaxDynamicSharedMemorySize, ATT2_SMEM);

    convert_hl<<<4096, 256>>>(x, 0);
    wconv<<<dim3(128, 64), 256>>>(qw, kvw, ow, 0);
    wconv<<<dim3(64, 64), 256>>>(qw, kvw, ow, 1);
    hmma_gemm<<<dim3(32, 16), 512, GEMM_SMEM>>>(nullptr, 0, 1);   // qkv
    rope_split<<<T_DIM, 256>>>(seg);
    attn_mma<<<dim3(NKH, 32), 256, ATT2_SMEM>>>();
    convert_hl<<<4096, 256>>>(x, 1);                               // g_enc -> ge
    hmma_gemm<<<dim3(16, 16), 512, GEMM_SMEM>>>(out, D_DIM, 0);   // out proj
}

// round 12
// speedup vs baseline: 3.4967x; 1.0035x over previous
#include <cuda_runtime.h>
#include <cuda_bf16.h>
#include <cuda_fp16.h>
#include <math.h>

typedef unsigned long long ull;
typedef unsigned int u32;
typedef unsigned short u16;

#define T_DIM 2048
#define D_DIM 2048
#define NQH 16
#define NKH 8
#define HD 128
#define WINDOW 1024
#define SOFTCAP 50.0f
#define QSCALE 0.08838834764831845f
#define QELEMS (T_DIM * NQH * HD)
#define KVELEMS (T_DIM * NKH * HD)

// fp32 scratch
__device__ float g_q[QELEMS];
__device__ float g_k[KVELEMS];
__device__ float g_v[KVELEMS];
__device__ float g_enc[QELEMS];

// fp16 split activations + single-fp16 weights (projection GEMMs)
__device__ u16 gx_h[T_DIM * D_DIM], gx_l[T_DIM * D_DIM];
__device__ u16 ge_h[T_DIM * D_DIM], ge_l[T_DIM * D_DIM];
__device__ u16 gw[4096 * D_DIM];
__device__ u16 gwo[D_DIM * D_DIM];
// bf16 split q/k/v (attention, 3-term path)
__device__ u16 gq_h[QELEMS], gq_l[QELEMS];
__device__ u16 gk_h[KVELEMS], gk_l[KVELEMS];
__device__ u16 gv_h[KVELEMS], gv_l[KVELEMS];

__device__ __forceinline__ u32 smem_u32(const void* p) {
    u32 a; asm("{ .reg .u64 t; cvta.to.shared.u64 t, %1; cvt.u32.u64 %0, t; }" : "=r"(a) : "l"(p));
    return a;
}
__device__ __forceinline__ void ldsm4(u32* r, u32 addr) {
    asm volatile("ldmatrix.sync.aligned.m8n8.x4.shared.b16 {%0,%1,%2,%3}, [%4];"
        : "=r"(r[0]), "=r"(r[1]), "=r"(r[2]), "=r"(r[3]) : "r"(addr));
}
__device__ __forceinline__ void ldsm4t(u32* r, u32 addr) {
    asm volatile("ldmatrix.sync.aligned.m8n8.x4.trans.shared.b16 {%0,%1,%2,%3}, [%4];"
        : "=r"(r[0]), "=r"(r[1]), "=r"(r[2]), "=r"(r[3]) : "r"(addr));
}
__device__ __forceinline__ void mma_bf16(float* c, const u32* a, u32 b0, u32 b1) {
    asm volatile("mma.sync.aligned.m16n8k16.row.col.f32.bf16.bf16.f32 "
        "{%0,%1,%2,%3}, {%4,%5,%6,%7}, {%8,%9}, {%0,%1,%2,%3};"
        : "+f"(c[0]), "+f"(c[1]), "+f"(c[2]), "+f"(c[3])
        : "r"(a[0]), "r"(a[1]), "r"(a[2]), "r"(a[3]), "r"(b0), "r"(b1));
}
__device__ __forceinline__ void mma_f16(float* c, const u32* a, u32 b0, u32 b1) {
    asm volatile("mma.sync.aligned.m16n8k16.row.col.f32.f16.f16.f32 "
        "{%0,%1,%2,%3}, {%4,%5,%6,%7}, {%8,%9}, {%0,%1,%2,%3};"
        : "+f"(c[0]), "+f"(c[1]), "+f"(c[2]), "+f"(c[3])
        : "r"(a[0]), "r"(a[1]), "r"(a[2]), "r"(a[3]), "r"(b0), "r"(b1));
}
__device__ __forceinline__ void cp16(u32 dst, const void* src) {
    asm volatile("cp.async.cg.shared.global [%0], [%1], 16;" :: "r"(dst), "l"(src));
}
#define CP_COMMIT() asm volatile("cp.async.commit_group;" ::: "memory")
#define CP_WAIT(n)  asm volatile("cp.async.wait_group %0;" :: "n"(n) : "memory")

__device__ __forceinline__ void split_bf(float v, u16& h, u16& l) {
    __nv_bfloat16 bh = __float2bfloat16_rn(v);
    float r = v - __bfloat162float(bh);
    __nv_bfloat16 bl = __float2bfloat16_rn(r);
    h = reinterpret_cast<u16&>(bh);
    l = reinterpret_cast<u16&>(bl);
}
__device__ __forceinline__ void split_fp16(float v, u16& h, u16& l) {
    __half hh = __float2half_rn(v);
    float r = v - __half2float(hh);
    __half ll = __float2half_rn(r);
    h = reinterpret_cast<u16&>(hh);
    l = reinterpret_cast<u16&>(ll);
}
__device__ __forceinline__ float tanh_fast(float x) {
    float c = fminf(fmaxf(x, -12.0f), 12.0f);
    float e = __expf(2.0f * c);
    return (e - 1.0f) / (e + 1.0f);
}

// ============================================================
// Elementwise split-convert to fp16 hi/lo (x or enc)
// ============================================================
__global__ void convert_hl(const float* __restrict__ src_x, int mode)
{
    const float* __restrict__ src = mode ? (const float*)g_enc : src_x;
    u16* __restrict__ h = mode ? ge_h : gx_h;
    u16* __restrict__ l = mode ? ge_l : gx_l;
    int i = (blockIdx.x * 256 + threadIdx.x) * 4;
    float4 v = *reinterpret_cast<const float4*>(src + i);
    u16 h0, h1, h2, h3, l0, l1, l2, l3;
    split_fp16(v.x, h0, l0); split_fp16(v.y, h1, l1);
    split_fp16(v.z, h2, l2); split_fp16(v.w, h3, l3);
    *reinterpret_cast<ull*>(h + i) = (ull)h0 | ((ull)h1 << 16) | ((ull)h2 << 32) | ((ull)h3 << 48);
    *reinterpret_cast<ull*>(l + i) = (ull)l0 | ((ull)l1 << 16) | ((ull)l2 << 32) | ((ull)l3 << 48);
}

// ============================================================
// Weight transpose + fp16 convert, 32x32 tiles.
// ============================================================
__global__ void wconv(const float* __restrict__ qw, const float* __restrict__ kvw,
                      const float* __restrict__ ow, int mode)
{
    __shared__ float s[32][33];
    const int c0 = blockIdx.x * 32;
    const int k0 = blockIdx.y * 32;
    const int tx = threadIdx.x & 31;
    const int ty = threadIdx.x >> 5;
    u16* __restrict__ dh = mode ? gwo : gw;

#pragma unroll
    for (int rr = ty; rr < 32; rr += 8) {
        int k = k0 + rr;
        int c = c0 + tx;
        float v;
        if (mode == 0) {
            const float* base;
            int cc = c;
            if (cc < 2048)      base = qw + (cc >> 7) * (D_DIM * HD);
            else if (cc < 3072) { cc -= 2048; base = kvw + (cc >> 7) * (D_DIM * HD); }
            else                { cc -= 3072; base = kvw + (8 + (cc >> 7)) * (D_DIM * HD); }
            v = base[k * HD + (cc & 127)];
        } else {
            v = ow[k * D_DIM + c];
        }
        s[tx][rr] = v;
    }
    __syncthreads();
#pragma unroll
    for (int rr = ty; rr < 32; rr += 8) {
        __half hv = __float2half_rn(s[rr][tx]);
        dh[(c0 + rr) * D_DIM + k0 + tx] = reinterpret_cast<u16&>(hv);
    }
}

// ============================================================
// HMMA GEMM, fp16 2-term, SOFTWARE-PIPELINED fragments.
// 256 threads, 8 warps, warp tile 32x64, 3-stage cp.async.
// Stage: Ah(16K) | Al(16K) | B(16K)
// ============================================================
#define STAGE_BYTES 49152
#define GEMM_SMEM (3 * STAGE_BYTES)

__device__ __forceinline__ void load_stage256(
    u32 sbase, int p, int tid, int row0, int col0, int kk,
    const u16* __restrict__ Ah, const u16* __restrict__ Al,
    const u16* __restrict__ B)
{
    u32 stg = sbase + (u32)p * STAGE_BYTES;
#pragma unroll
    for (int l = 0; l < 4; ++l) {
        int idx = tid + l * 256;
        int r = idx >> 3;
        int ch = idx & 7;
        u32 doff = (u32)(r * 128) + (u32)((ch * 16) ^ ((r & 7) << 4));
        int aoff = (row0 + r) * D_DIM + kk + ch * 8;
        int boff = (col0 + r) * D_DIM + kk + ch * 8;
        cp16(stg + doff,             Ah + aoff);
        cp16(stg + 16384 + doff,     Al + aoff);
        cp16(stg + 32768 + doff,     B + boff);
    }
}

__device__ __forceinline__ void gemm_frags(
    u32 stg, u32 aRow, u32 aK, u32 aXor, u32 bRow, u32 bK, u32 kb,
    u32 ah[2][4], u32 al[2][4], u32 bf[4][4])
{
#pragma unroll
    for (int mi = 0; mi < 2; ++mi) {
        u32 ao = aRow + (u32)(mi * 2048) + ((aK + kb) ^ aXor);
        ldsm4(ah[mi], stg + ao);
        ldsm4(al[mi], stg + 16384 + ao);
    }
#pragma unroll
    for (int n4 = 0; n4 < 4; ++n4) {
        u32 bo = bRow + (u32)(n4 * 2048) + ((bK + kb) ^ aXor);
        ldsm4(bf[n4], stg + 32768 + bo);
    }
}

__global__ __launch_bounds__(256, 1)
void hmma_gemm(float* __restrict__ dst0, int ldc0, int qkv_mode)
{
    extern __shared__ char smem[];
    const u32 sb = smem_u32(smem);
    const int tid = threadIdx.x;
    const int lane = tid & 31;
    const int w = tid >> 5;
    const int wm = w & 3;          // rows wm*32
    const int wn = w >> 2;         // cols wn*64
    const int row0 = blockIdx.y * 128;
    const int col0 = blockIdx.x * 128;

    const u16 *Ah, *Al, *B;
    float* dst; int ldc, cofs;
    if (qkv_mode) {
        Ah = gx_h; Al = gx_l; B = gw;
        if (col0 < 2048)      { dst = g_q; ldc = 2048; cofs = col0; }
        else if (col0 < 3072) { dst = g_k; ldc = 1024; cofs = col0 - 2048; }
        else                  { dst = g_v; ldc = 1024; cofs = col0 - 3072; }
    } else {
        Ah = ge_h; Al = ge_l; B = gwo;
        dst = dst0; ldc = ldc0; cofs = col0;
    }

    float acc[2][8][4];
#pragma unroll
    for (int i = 0; i < 2; ++i)
#pragma unroll
        for (int j = 0; j < 8; ++j)
#pragma unroll
            for (int q = 0; q < 4; ++q) acc[i][j][q] = 0.0f;

    const u32 aRow = (u32)(wm * 32 + (lane & 15)) * 128;
    const u32 aXor = (u32)((lane & 7) << 4);
    const u32 aK   = (u32)((lane >> 4) * 16);
    const u32 bRow = (u32)(wn * 64 + ((lane >> 4) << 3) + (lane & 7)) * 128;
    const u32 bK   = (u32)(((lane >> 3) & 1) * 16);

    // double-buffered fragments
    u32 ah[2][2][4], al[2][2][4], bf[2][4][4];

    load_stage256(sb, 0, tid, row0, col0, 0, Ah, Al, B);
    CP_COMMIT();
    load_stage256(sb, 1, tid, row0, col0, 64, Ah, Al, B);
    CP_COMMIT();

    int stage_c = 0;
    for (int c = 0; c < 32; ++c) {
        if (c < 31) { CP_WAIT(1); } else { CP_WAIT(0); }
        __syncthreads();
        if (c + 2 < 32) {
            int sn = stage_c + 2; if (sn >= 3) sn -= 3;
            load_stage256(sb, sn, tid, row0, col0, (c + 2) * 64, Ah, Al, B);
            CP_COMMIT();
        }

        const u32 stg = sb + (u32)stage_c * STAGE_BYTES;
        // prologue: fragments for ks=0
        gemm_frags(stg, aRow, aK, aXor, bRow, bK, 0, ah[0], al[0], bf[0]);
#pragma unroll
        for (int ks = 0; ks < 4; ++ks) {
            const int cur = ks & 1;
            if (ks < 3) {
                // prefetch ks+1 fragments BEFORE consuming ks
                gemm_frags(stg, aRow, aK, aXor, bRow, bK, (u32)((ks + 1) * 32),
                           ah[cur ^ 1], al[cur ^ 1], bf[cur ^ 1]);
            }
            // term 1: Ah x B
#pragma unroll
            for (int n4 = 0; n4 < 4; ++n4)
#pragma unroll
                for (int mi = 0; mi < 2; ++mi) {
                    mma_f16(acc[mi][2 * n4],     ah[cur][mi], bf[cur][n4][0], bf[cur][n4][1]);
                    mma_f16(acc[mi][2 * n4 + 1], ah[cur][mi], bf[cur][n4][2], bf[cur][n4][3]);
                }
            // term 2: Al x B
#pragma unroll
            for (int n4 = 0; n4 < 4; ++n4)
#pragma unroll
                for (int mi = 0; mi < 2; ++mi) {
                    mma_f16(acc[mi][2 * n4],     al[cur][mi], bf[cur][n4][0], bf[cur][n4][1]);
                    mma_f16(acc[mi][2 * n4 + 1], al[cur][mi], bf[cur][n4][2], bf[cur][n4][3]);
                }
        }
        if (++stage_c >= 3) stage_c -= 3;
    }

    const int rbase = row0 + wm * 32 + (lane >> 2);
    const int cbase = cofs + wn * 64 + (lane & 3) * 2;
#pragma unroll
    for (int mi = 0; mi < 2; ++mi) {
#pragma unroll
        for (int nt = 0; nt < 8; ++nt) {
            int r = rbase + mi * 16;
            int cc = cbase + nt * 8;
            *reinterpret_cast<float2*>(dst + r * ldc + cc) =
                make_float2(acc[mi][nt][0], acc[mi][nt][1]);
            *reinterpret_cast<float2*>(dst + (r + 8) * ldc + cc) =
                make_float2(acc[mi][nt][2], acc[mi][nt][3]);
        }
    }
}

// ============================================================
// RoPE + bf16 hi/lo split fused (attention operands).
// ============================================================
__global__ void rope_split(const int* __restrict__ seg)
{
    __shared__ float s_ts[64];
    const int t = blockIdx.x;
    const int tid = threadIdx.x;
    if (tid < 64) {
        double f = (double)tid / 64.0;
        s_ts[tid] = (float)pow(10000.0, f);
    }
    __syncthreads();
    const float pos = (float)seg[t];
    for (int idx = tid; idx < (NQH + NKH) * 64; idx += 256) {
        int head = idx >> 6;
        int i = idx & 63;
        const float* base;
        u16 *dh, *dl;
        int off;
        if (head < NQH) {
            off = t * (NQH * HD) + head * HD;
            base = g_q + off; dh = gq_h + off; dl = gq_l + off;
        } else {
            off = t * (NKH * HD) + (head - NQH) * HD;
            base = g_k + off; dh = gk_h + off; dl = gk_l + off;
        }
        float ang = pos / s_ts[i];
        float sv, cv;
        sincosf(ang, &sv, &cv);
        float x1 = base[i], x2 = base[i + 64];
        float o1 = x1 * cv - x2 * sv;
        float o2 = x2 * cv + x1 * sv;
        if (head < NQH) { o1 *= QSCALE; o2 *= QSCALE; }
        u16 h1, l1, h2, l2;
        split_bf(o1, h1, l1);
        split_bf(o2, h2, l2);
        dh[i] = h1;       dl[i] = l1;
        dh[i + 64] = h2;  dl[i + 64] = l2;
    }
    {
        int off = t * (NKH * HD) + tid * 4;
        float4 v = *reinterpret_cast<const float4*>(g_v + off);
        u16 h0, h1, h2, h3, l0, l1, l2, l3;
        split_bf(v.x, h0, l0); split_bf(v.y, h1, l1);
        split_bf(v.z, h2, l2); split_bf(v.w, h3, l3);
        *reinterpret_cast<ull*>(gv_h + off) = (ull)h0 | ((ull)h1 << 16) | ((ull)h2 << 32) | ((ull)h3 << 48);
        *reinterpret_cast<ull*>(gv_l + off) = (ull)l0 | ((ull)l1 << 16) | ((ull)l2 << 32) | ((ull)l3 << 48);
    }
}

// ============================================================
// Tensor-core sliding-window attention (bf16 3-term, R10-verified).
// ============================================================
#define SMEM_Q  0
#define SMEM_K  65536
#define SMEM_V  98304
#define SMEM_S  131072
#define SMEM_P  165888
#define SMEM_AL 198656
#define SMEM_L  199168
#define ATT2_SMEM 199680

__global__ __launch_bounds__(256, 1) void attn_mma()
{
    extern __shared__ char smc[];
    const u32 sb = smem_u32(smc);
    float* S = reinterpret_cast<float*>(smc + SMEM_S);
    float* al_s = reinterpret_cast<float*>(smc + SMEM_AL);
    float* l_s = reinterpret_cast<float*>(smc + SMEM_L);

    const int tid = threadIdx.x;
    const int lane = tid & 31;
    const int w = tid >> 5;
    const int wm = w & 3;
    const int wn = w >> 2;
    const int kh = blockIdx.x;
    const int t0 = (int)(31 - blockIdx.y) * 64;

#pragma unroll
    for (int l = 0; l < 8; ++l) {
        int idx = tid + l * 256;
        int r = idx >> 4, ch = idx & 15;
        int t = t0 + (r & 63), n = kh * 2 + (r >> 6);
        u32 d = (u32)((ch >> 3) * 16384 + r * 128 + (((ch & 7) * 16) ^ ((r & 7) << 4)));
        cp16(sb + SMEM_Q + d,          gq_h + (size_t)(t * NQH + n) * HD + ch * 8);
        cp16(sb + SMEM_Q + 32768 + d,  gq_l + (size_t)(t * NQH + n) * HD + ch * 8);
    }
    CP_COMMIT();

    float acc_o[2][8][4];
#pragma unroll
    for (int i = 0; i < 2; ++i)
#pragma unroll
        for (int j = 0; j < 8; ++j)
#pragma unroll
            for (int q = 0; q < 4; ++q) acc_o[i][j][q] = 0.0f;

    float m_reg = -1e30f, l_reg = 0.0f;

    const u32 aRow = (u32)((wm * 32 + (lane & 15)) * 128);
    const u32 aK   = (u32)((lane >> 4) * 16);
    const u32 aXor = (u32)((lane & 7) << 4);
    const u32 bK   = (u32)(((lane >> 3) & 1) * 16);
    u32 bRow[2];
    bRow[0] = (u32)((wn * 32 + ((lane >> 4) << 3) + (lane & 7)) * 128);
    bRow[1] = bRow[0] + 16 * 128;
    const int vrow_in = (lane & 7) + (lane & 8);
    const u32 vh8 = (u32)((lane >> 4) << 3);

    const int s_begin = (t0 >= (WINDOW - 1)) ? ((t0 - (WINDOW - 1)) & ~63) : 0;

    for (int st = s_begin; st <= t0; st += 64) {
#pragma unroll
        for (int l = 0; l < 4; ++l) {
            int idx = tid + l * 256;
            int r = idx >> 4, ch = idx & 15;
            size_t go = (size_t)((st + r) * NKH + kh) * HD + ch * 8;
            u32 dk = (u32)((ch >> 3) * 8192 + r * 128 + (((ch & 7) * 16) ^ ((r & 7) << 4)));
            u32 dv = (u32)(r * 256 + ((ch * 16) ^ ((r & 7) << 4)));
            cp16(sb + SMEM_K + dk,         gk_h + go);
            cp16(sb + SMEM_K + 16384 + dk, gk_l + go);
            cp16(sb + SMEM_V + dv,         gv_h + go);
            cp16(sb + SMEM_V + 16384 + dv, gv_l + go);
        }
        CP_COMMIT();
        CP_WAIT(0);
        __syncthreads();

        float s_acc[2][4][4];
#pragma unroll
        for (int i = 0; i < 2; ++i)
#pragma unroll
            for (int j = 0; j < 4; ++j)
#pragma unroll
                for (int q = 0; q < 4; ++q) s_acc[i][j][q] = 0.0f;

#pragma unroll
        for (int kk = 0; kk < 8; ++kk) {
            const int ks = (kk + w) & 7;
            const u32 kc = (u32)(ks >> 2);
            const u32 kb = (u32)((ks & 3) * 32);
            u32 qh[2][4], ql[2][4];
#pragma unroll
            for (int mi = 0; mi < 2; ++mi) {
                u32 ao = kc * 16384 + aRow + (u32)(mi * 2048) + ((aK + kb) ^ aXor);
                ldsm4(qh[mi], sb + SMEM_Q + ao);
                ldsm4(ql[mi], sb + SMEM_Q + 32768 + ao);
            }
            u32 kf[2][4], kl[2][4];
#pragma unroll
            for (int g = 0; g < 2; ++g) {
                u32 bo = kc * 8192 + bRow[g] + ((bK + kb) ^ aXor);
                ldsm4(kf[g], sb + SMEM_K + bo);
                ldsm4(kl[g], sb + SMEM_K + 16384 + bo);
            }
#pragma unroll
            for (int g = 0; g < 2; ++g)
#pragma unroll
                for (int mi = 0; mi < 2; ++mi) {
                    mma_bf16(s_acc[mi][2 * g],     qh[mi], kf[g][0], kf[g][1]);
                    mma_bf16(s_acc[mi][2 * g + 1], qh[mi], kf[g][2], kf[g][3]);
                }
#pragma unroll
            for (int g = 0; g < 2; ++g)
#pragma unroll
                for (int mi = 0; mi < 2; ++mi) {
                    mma_bf16(s_acc[mi][2 * g],     qh[mi], kl[g][0], kl[g][1]);
                    mma_bf16(s_acc[mi][2 * g + 1], qh[mi], kl[g][2], kl[g][3]);
                }
#pragma unroll
            for (int g = 0; g < 2; ++g)
#pragma unroll
                for (int mi = 0; mi < 2; ++mi) {
                    mma_bf16(s_acc[mi][2 * g],     ql[mi], kf[g][0], kf[g][1]);
                    mma_bf16(s_acc[mi][2 * g + 1], ql[mi], kf[g][2], kf[g][3]);
                }
        }

#pragma unroll
        for (int mi = 0; mi < 2; ++mi) {
            int r0 = wm * 32 + mi * 16 + (lane >> 2);
#pragma unroll
            for (int n8 = 0; n8 < 4; ++n8) {
                int sl0 = wn * 32 + n8 * 8 + (lane & 3) * 2;
#pragma unroll
                for (int half = 0; half < 2; ++half) {
                    int rr = r0 + half * 8;
                    int t = t0 + (rr & 63);
                    float v0 = tanh_fast(s_acc[mi][n8][half * 2]     * (1.0f / SOFTCAP)) * SOFTCAP;
                    float v1 = tanh_fast(s_acc[mi][n8][half * 2 + 1] * (1.0f / SOFTCAP)) * SOFTCAP;
                    int sg0 = st + sl0, sg1 = sg0 + 1;
                    bool ok0 = (sg0 <= t) && (sg0 > t - WINDOW);
                    bool ok1 = (sg1 <= t) && (sg1 > t - WINDOW);
                    *reinterpret_cast<float2*>(&S[rr * 68 + sl0]) =
                        make_float2(ok0 ? v0 : -1e30f, ok1 ? v1 : -1e30f);
                }
            }
        }
        __syncthreads();

        {
            const int row = tid >> 1;
            const int half = tid & 1;
            const int cb = half * 32;
            float tm = -1e30f;
#pragma unroll 8
            for (int c = 0; c < 32; ++c) tm = fmaxf(tm, S[row * 68 + cb + c]);
            tm = fmaxf(tm, __shfl_xor_sync(0xffffffffu, tm, 1));
            float mnew = fmaxf(m_reg, tm);
            float a = __expf(m_reg - mnew);
            float lsum = 0.0f;
            char* ph = smc + SMEM_P + row * 128;
            char* pl = smc + SMEM_P + 16384 + row * 128;
            const u32 xr = (u32)((row & 7) << 4);
#pragma unroll 8
            for (int c = 0; c < 32; ++c) {
                float p = __expf(S[row * 68 + cb + c] - mnew);
                lsum += p;
                u16 hh, ll;
                split_bf(p, hh, ll);
                u32 off = ((u32)((cb + c) * 2)) ^ xr;
                *reinterpret_cast<u16*>(ph + off) = hh;
                *reinterpret_cast<u16*>(pl + off) = ll;
            }
            lsum += __shfl_xor_sync(0xffffffffu, lsum, 1);
            l_reg = l_reg * a + lsum;
            m_reg = mnew;
            if (half == 0) al_s[row] = a;
        }
        __syncthreads();

#pragma unroll
        for (int mi = 0; mi < 2; ++mi) {
            int r0 = wm * 32 + mi * 16 + (lane >> 2);
            float a0 = al_s[r0], a1 = al_s[r0 + 8];
#pragma unroll
            for (int n8 = 0; n8 < 8; ++n8) {
                acc_o[mi][n8][0] *= a0; acc_o[mi][n8][1] *= a0;
                acc_o[mi][n8][2] *= a1; acc_o[mi][n8][3] *= a1;
            }
        }
#pragma unroll
        for (int kk = 0; kk < 4; ++kk) {
            const int ks = (kk + (w & 3)) & 3;
            const u32 kb = (u32)(ks * 32);
            u32 ph[2][4], pl[2][4];
#pragma unroll
            for (int mi = 0; mi < 2; ++mi) {
                u32 ao = aRow + (u32)(mi * 2048) + ((aK + kb) ^ aXor);
                ldsm4(ph[mi], sb + SMEM_P + ao);
                ldsm4(pl[mi], sb + SMEM_P + 16384 + ao);
            }
            const int vrow = ks * 16 + vrow_in;
            const u32 vswz = (u32)(vrow * 256);
            const u32 vxr = (u32)((vrow & 7) << 4);
#pragma unroll
            for (int pg = 0; pg < 2; ++pg) {
                u32 vhf[2][4], vlf[2][4];
#pragma unroll
                for (int j = 0; j < 2; ++j) {
                    int pair = pg * 2 + j;
                    u32 hq = (u32)(wn * 64 + pair * 16) + vh8;
                    u32 va = sb + SMEM_V + vswz + (((hq >> 3) * 16) ^ vxr);
                    ldsm4t(vhf[j], va);
                    ldsm4t(vlf[j], va + 16384);
                }
#pragma unroll
                for (int j = 0; j < 2; ++j) {
                    int pair = pg * 2 + j;
#pragma unroll
                    for (int mi = 0; mi < 2; ++mi) {
                        mma_bf16(acc_o[mi][pair * 2],     ph[mi], vhf[j][0], vhf[j][1]);
                        mma_bf16(acc_o[mi][pair * 2 + 1], ph[mi], vhf[j][2], vhf[j][3]);
                    }
                }
#pragma unroll
                for (int j = 0; j < 2; ++j) {
                    int pair = pg * 2 + j;
#pragma unroll
                    for (int mi = 0; mi < 2; ++mi) {
                        mma_bf16(acc_o[mi][pair * 2],     ph[mi], vlf[j][0], vlf[j][1]);
                        mma_bf16(acc_o[mi][pair * 2 + 1], ph[mi], vlf[j][2], vlf[j][3]);
                    }
                }
#pragma unroll
                for (int j = 0; j < 2; ++j) {
                    int pair = pg * 2 + j;
#pragma unroll
                    for (int mi = 0; mi < 2; ++mi) {
                        mma_bf16(acc_o[mi][pair * 2],     pl[mi], vhf[j][0], vhf[j][1]);
                        mma_bf16(acc_o[mi][pair * 2 + 1], pl[mi], vhf[j][2], vhf[j][3]);
                    }
                }
            }
        }
        __syncthreads();
    }

    if ((tid & 1) == 0) l_s[tid >> 1] = l_reg;
    __syncthreads();

#pragma unroll
    for (int mi = 0; mi < 2; ++mi) {
        int r0 = wm * 32 + mi * 16 + (lane >> 2);
        float i0 = 1.0f / l_s[r0];
        float i1 = 1.0f / l_s[r0 + 8];
#pragma unroll
        for (int n8 = 0; n8 < 8; ++n8) {
            int h = wn * 64 + n8 * 8 + (lane & 3) * 2;
#pragma unroll
            for (int half = 0; half < 2; ++half) {
                int rr = r0 + half * 8;
                int t = t0 + (rr & 63);
                int n = kh * 2 + (rr >> 6);
                float iv = half ? i1 : i0;
                *reinterpret_cast<float2*>(&g_enc[(size_t)(t * NQH + n) * HD + h]) =
                    make_float2(acc_o[mi][n8][half * 2] * iv,
                                acc_o[mi][n8][half * 2 + 1] * iv);
            }
        }
    }
}

// ============================================================
extern "C" void kernel_launch(void* const* d_in, const int* in_sizes, int n_in,
                              void* d_out, int out_size)
{
    (void)in_sizes; (void)n_in; (void)out_size;
    const float* x   = (const float*)d_in[0];
    const int*   seg = (const int*)d_in[1];
    const float* qw  = (const float*)d_in[3];
    const float* kvw = (const float*)d_in[4];
    const float* ow  = (const float*)d_in[5];
    float* out = (float*)d_out;

    cudaFuncSetAttribute(hmma_gemm, cudaFuncAttributeMaxDynamicSharedMemorySize, GEMM_SMEM);
    cudaFuncSetAttribute(attn_mma, cudaFuncAttributeMaxDynamicSharedMemorySize, ATT2_SMEM);

    convert_hl<<<4096, 256>>>(x, 0);
    wconv<<<dim3(128, 64), 256>>>(qw, kvw, ow, 0);
    wconv<<<dim3(64, 64), 256>>>(qw, kvw, ow, 1);
    hmma_gemm<<<dim3(32, 16), 256, GEMM_SMEM>>>(nullptr, 0, 1);   // qkv
    rope_split<<<T_DIM, 256>>>(seg);
    attn_mma<<<dim3(NKH, 32), 256, ATT2_SMEM>>>();
    convert_hl<<<4096, 256>>>(x, 1);                               // g_enc -> ge
    hmma_gemm<<<dim3(16, 16), 256, GEMM_SMEM>>>(out, D_DIM, 0);   // out proj
}

// round 13
// speedup vs baseline: 3.7613x; 1.0757x over previous
#include <cuda_runtime.h>
#include <cuda_bf16.h>
#include <cuda_fp16.h>
#include <math.h>

typedef unsigned long long ull;
typedef unsigned int u32;
typedef unsigned short u16;

#define T_DIM 2048
#define D_DIM 2048
#define NQH 16
#define NKH 8
#define HD 128
#define WINDOW 1024
#define SOFTCAP 50.0f
#define QSCALE 0.08838834764831845f
#define QELEMS (T_DIM * NQH * HD)
#define KVELEMS (T_DIM * NKH * HD)

// fp32 scratch
__device__ float g_q[QELEMS];
__device__ float g_k[KVELEMS];
__device__ float g_v[KVELEMS];
__device__ float g_enc[QELEMS];

// fp16 split activations + single-fp16 weights (projection GEMMs)
__device__ u16 gx_h[T_DIM * D_DIM], gx_l[T_DIM * D_DIM];
__device__ u16 ge_h[T_DIM * D_DIM], ge_l[T_DIM * D_DIM];
__device__ u16 gw[4096 * D_DIM];
__device__ u16 gwo[D_DIM * D_DIM];
// attention operands: q split fp16, k/v single fp16
__device__ u16 gq_h[QELEMS], gq_l[QELEMS];
__device__ u16 gk16[KVELEMS];
__device__ u16 gv16[KVELEMS];

__device__ __forceinline__ u32 smem_u32(const void* p) {
    u32 a; asm("{ .reg .u64 t; cvta.to.shared.u64 t, %1; cvt.u32.u64 %0, t; }" : "=r"(a) : "l"(p));
    return a;
}
__device__ __forceinline__ void ldsm4(u32* r, u32 addr) {
    asm volatile("ldmatrix.sync.aligned.m8n8.x4.shared.b16 {%0,%1,%2,%3}, [%4];"
        : "=r"(r[0]), "=r"(r[1]), "=r"(r[2]), "=r"(r[3]) : "r"(addr));
}
__device__ __forceinline__ void ldsm4t(u32* r, u32 addr) {
    asm volatile("ldmatrix.sync.aligned.m8n8.x4.trans.shared.b16 {%0,%1,%2,%3}, [%4];"
        : "=r"(r[0]), "=r"(r[1]), "=r"(r[2]), "=r"(r[3]) : "r"(addr));
}
__device__ __forceinline__ void mma_f16(float* c, const u32* a, u32 b0, u32 b1) {
    asm volatile("mma.sync.aligned.m16n8k16.row.col.f32.f16.f16.f32 "
        "{%0,%1,%2,%3}, {%4,%5,%6,%7}, {%8,%9}, {%0,%1,%2,%3};"
        : "+f"(c[0]), "+f"(c[1]), "+f"(c[2]), "+f"(c[3])
        : "r"(a[0]), "r"(a[1]), "r"(a[2]), "r"(a[3]), "r"(b0), "r"(b1));
}
__device__ __forceinline__ void cp16(u32 dst, const void* src) {
    asm volatile("cp.async.cg.shared.global [%0], [%1], 16;" :: "r"(dst), "l"(src));
}
#define CP_COMMIT() asm volatile("cp.async.commit_group;" ::: "memory")
#define CP_WAIT(n)  asm volatile("cp.async.wait_group %0;" :: "n"(n) : "memory")

__device__ __forceinline__ void split_fp16(float v, u16& h, u16& l) {
    __half hh = __float2half_rn(v);
    float r = v - __half2float(hh);
    __half ll = __float2half_rn(r);
    h = reinterpret_cast<u16&>(hh);
    l = reinterpret_cast<u16&>(ll);
}
__device__ __forceinline__ float tanh_fast(float x) {
    float c = fminf(fmaxf(x, -12.0f), 12.0f);
    float e = __expf(2.0f * c);
    return (e - 1.0f) / (e + 1.0f);
}

// ============================================================
// Elementwise split-convert to fp16 hi/lo (x or enc)
// ============================================================
__global__ void convert_hl(const float* __restrict__ src_x, int mode)
{
    const float* __restrict__ src = mode ? (const float*)g_enc : src_x;
    u16* __restrict__ h = mode ? ge_h : gx_h;
    u16* __restrict__ l = mode ? ge_l : gx_l;
    int i = (blockIdx.x * 256 + threadIdx.x) * 4;
    float4 v = *reinterpret_cast<const float4*>(src + i);
    u16 h0, h1, h2, h3, l0, l1, l2, l3;
    split_fp16(v.x, h0, l0); split_fp16(v.y, h1, l1);
    split_fp16(v.z, h2, l2); split_fp16(v.w, h3, l3);
    *reinterpret_cast<ull*>(h + i) = (ull)h0 | ((ull)h1 << 16) | ((ull)h2 << 32) | ((ull)h3 << 48);
    *reinterpret_cast<ull*>(l + i) = (ull)l0 | ((ull)l1 << 16) | ((ull)l2 << 32) | ((ull)l3 << 48);
}

// ============================================================
// Weight transpose + fp16 convert, 32x32 tiles.
// ============================================================
__global__ void wconv(const float* __restrict__ qw, const float* __restrict__ kvw,
                      const float* __restrict__ ow, int mode)
{
    __shared__ float s[32][33];
    const int c0 = blockIdx.x * 32;
    const int k0 = blockIdx.y * 32;
    const int tx = threadIdx.x & 31;
    const int ty = threadIdx.x >> 5;
    u16* __restrict__ dh = mode ? gwo : gw;

#pragma unroll
    for (int rr = ty; rr < 32; rr += 8) {
        int k = k0 + rr;
        int c = c0 + tx;
        float v;
        if (mode == 0) {
            const float* base;
            int cc = c;
            if (cc < 2048)      base = qw + (cc >> 7) * (D_DIM * HD);
            else if (cc < 3072) { cc -= 2048; base = kvw + (cc >> 7) * (D_DIM * HD); }
            else                { cc -= 3072; base = kvw + (8 + (cc >> 7)) * (D_DIM * HD); }
            v = base[k * HD + (cc & 127)];
        } else {
            v = ow[k * D_DIM + c];
        }
        s[tx][rr] = v;
    }
    __syncthreads();
#pragma unroll
    for (int rr = ty; rr < 32; rr += 8) {
        __half hv = __float2half_rn(s[rr][tx]);
        dh[(c0 + rr) * D_DIM + k0 + tx] = reinterpret_cast<u16&>(hv);
    }
}

// ============================================================
// HMMA GEMM, fp16 2-term (R11-verified, unchanged).
// ============================================================
#define STAGE_BYTES 49152
#define GEMM_SMEM (3 * STAGE_BYTES)

__device__ __forceinline__ void load_stage256(
    u32 sbase, int p, int tid, int row0, int col0, int kk,
    const u16* __restrict__ Ah, const u16* __restrict__ Al,
    const u16* __restrict__ B)
{
    u32 stg = sbase + (u32)p * STAGE_BYTES;
#pragma unroll
    for (int l = 0; l < 4; ++l) {
        int idx = tid + l * 256;
        int r = idx >> 3;
        int ch = idx & 7;
        u32 doff = (u32)(r * 128) + (u32)((ch * 16) ^ ((r & 7) << 4));
        int aoff = (row0 + r) * D_DIM + kk + ch * 8;
        int boff = (col0 + r) * D_DIM + kk + ch * 8;
        cp16(stg + doff,             Ah + aoff);
        cp16(stg + 16384 + doff,     Al + aoff);
        cp16(stg + 32768 + doff,     B + boff);
    }
}

__device__ __forceinline__ void gemm_frags(
    u32 stg, u32 aRow, u32 aK, u32 aXor, u32 bRow, u32 bK, u32 kb,
    u32 ah[2][4], u32 al[2][4], u32 bf[4][4])
{
#pragma unroll
    for (int mi = 0; mi < 2; ++mi) {
        u32 ao = aRow + (u32)(mi * 2048) + ((aK + kb) ^ aXor);
        ldsm4(ah[mi], stg + ao);
        ldsm4(al[mi], stg + 16384 + ao);
    }
#pragma unroll
    for (int n4 = 0; n4 < 4; ++n4) {
        u32 bo = bRow + (u32)(n4 * 2048) + ((bK + kb) ^ aXor);
        ldsm4(bf[n4], stg + 32768 + bo);
    }
}

__global__ __launch_bounds__(256, 1)
void hmma_gemm(float* __restrict__ dst0, int ldc0, int qkv_mode)
{
    extern __shared__ char smem[];
    const u32 sb = smem_u32(smem);
    const int tid = threadIdx.x;
    const int lane = tid & 31;
    const int w = tid >> 5;
    const int wm = w & 3;
    const int wn = w >> 2;
    const int row0 = blockIdx.y * 128;
    const int col0 = blockIdx.x * 128;

    const u16 *Ah, *Al, *B;
    float* dst; int ldc, cofs;
    if (qkv_mode) {
        Ah = gx_h; Al = gx_l; B = gw;
        if (col0 < 2048)      { dst = g_q; ldc = 2048; cofs = col0; }
        else if (col0 < 3072) { dst = g_k; ldc = 1024; cofs = col0 - 2048; }
        else                  { dst = g_v; ldc = 1024; cofs = col0 - 3072; }
    } else {
        Ah = ge_h; Al = ge_l; B = gwo;
        dst = dst0; ldc = ldc0; cofs = col0;
    }

    float acc[2][8][4];
#pragma unroll
    for (int i = 0; i < 2; ++i)
#pragma unroll
        for (int j = 0; j < 8; ++j)
#pragma unroll
            for (int q = 0; q < 4; ++q) acc[i][j][q] = 0.0f;

    const u32 aRow = (u32)(wm * 32 + (lane & 15)) * 128;
    const u32 aXor = (u32)((lane & 7) << 4);
    const u32 aK   = (u32)((lane >> 4) * 16);
    const u32 bRow = (u32)(wn * 64 + ((lane >> 4) << 3) + (lane & 7)) * 128;
    const u32 bK   = (u32)(((lane >> 3) & 1) * 16);

    u32 ah[2][2][4], al[2][2][4], bf[2][4][4];

    load_stage256(sb, 0, tid, row0, col0, 0, Ah, Al, B);
    CP_COMMIT();
    load_stage256(sb, 1, tid, row0, col0, 64, Ah, Al, B);
    CP_COMMIT();

    int stage_c = 0;
    for (int c = 0; c < 32; ++c) {
        if (c < 31) { CP_WAIT(1); } else { CP_WAIT(0); }
        __syncthreads();
        if (c + 2 < 32) {
            int sn = stage_c + 2; if (sn >= 3) sn -= 3;
            load_stage256(sb, sn, tid, row0, col0, (c + 2) * 64, Ah, Al, B);
            CP_COMMIT();
        }

        const u32 stg = sb + (u32)stage_c * STAGE_BYTES;
        gemm_frags(stg, aRow, aK, aXor, bRow, bK, 0, ah[0], al[0], bf[0]);
#pragma unroll
        for (int ks = 0; ks < 4; ++ks) {
            const int cur = ks & 1;
            if (ks < 3) {
                gemm_frags(stg, aRow, aK, aXor, bRow, bK, (u32)((ks + 1) * 32),
                           ah[cur ^ 1], al[cur ^ 1], bf[cur ^ 1]);
            }
#pragma unroll
            for (int n4 = 0; n4 < 4; ++n4)
#pragma unroll
                for (int mi = 0; mi < 2; ++mi) {
                    mma_f16(acc[mi][2 * n4],     ah[cur][mi], bf[cur][n4][0], bf[cur][n4][1]);
                    mma_f16(acc[mi][2 * n4 + 1], ah[cur][mi], bf[cur][n4][2], bf[cur][n4][3]);
                }
#pragma unroll
            for (int n4 = 0; n4 < 4; ++n4)
#pragma unroll
                for (int mi = 0; mi < 2; ++mi) {
                    mma_f16(acc[mi][2 * n4],     al[cur][mi], bf[cur][n4][0], bf[cur][n4][1]);
                    mma_f16(acc[mi][2 * n4 + 1], al[cur][mi], bf[cur][n4][2], bf[cur][n4][3]);
                }
        }
        if (++stage_c >= 3) stage_c -= 3;
    }

    const int rbase = row0 + wm * 32 + (lane >> 2);
    const int cbase = cofs + wn * 64 + (lane & 3) * 2;
#pragma unroll
    for (int mi = 0; mi < 2; ++mi) {
#pragma unroll
        for (int nt = 0; nt < 8; ++nt) {
            int r = rbase + mi * 16;
            int cc = cbase + nt * 8;
            *reinterpret_cast<float2*>(dst + r * ldc + cc) =
                make_float2(acc[mi][nt][0], acc[mi][nt][1]);
            *reinterpret_cast<float2*>(dst + (r + 8) * ldc + cc) =
                make_float2(acc[mi][nt][2], acc[mi][nt][3]);
        }
    }
}

// ============================================================
// RoPE + fp16 convert fused: q split hi/lo, k/v single fp16.
// ============================================================
__global__ void rope_split(const int* __restrict__ seg)
{
    __shared__ float s_ts[64];
    const int t = blockIdx.x;
    const int tid = threadIdx.x;
    if (tid < 64) {
        double f = (double)tid / 64.0;
        s_ts[tid] = (float)pow(10000.0, f);
    }
    __syncthreads();
    const float pos = (float)seg[t];
    for (int idx = tid; idx < (NQH + NKH) * 64; idx += 256) {
        int head = idx >> 6;
        int i = idx & 63;
        float ang = pos / s_ts[i];
        float sv, cv;
        sincosf(ang, &sv, &cv);
        if (head < NQH) {
            int off = t * (NQH * HD) + head * HD;
            const float* base = g_q + off;
            float x1 = base[i], x2 = base[i + 64];
            float o1 = (x1 * cv - x2 * sv) * QSCALE;
            float o2 = (x2 * cv + x1 * sv) * QSCALE;
            u16 h1, l1, h2, l2;
            split_fp16(o1, h1, l1);
            split_fp16(o2, h2, l2);
            gq_h[off + i] = h1;       gq_l[off + i] = l1;
            gq_h[off + i + 64] = h2;  gq_l[off + i + 64] = l2;
        } else {
            int off = t * (NKH * HD) + (head - NQH) * HD;
            const float* base = g_k + off;
            float x1 = base[i], x2 = base[i + 64];
            float o1 = x1 * cv - x2 * sv;
            float o2 = x2 * cv + x1 * sv;
            __half h1 = __float2half_rn(o1);
            __half h2 = __float2half_rn(o2);
            gk16[off + i]      = reinterpret_cast<u16&>(h1);
            gk16[off + i + 64] = reinterpret_cast<u16&>(h2);
        }
    }
    {
        int off = t * (NKH * HD) + tid * 4;
        float4 v = *reinterpret_cast<const float4*>(g_v + off);
        __half v0 = __float2half_rn(v.x), v1 = __float2half_rn(v.y);
        __half v2 = __float2half_rn(v.z), v3 = __float2half_rn(v.w);
        ull pk = (ull)reinterpret_cast<u16&>(v0) | ((ull)reinterpret_cast<u16&>(v1) << 16)
               | ((ull)reinterpret_cast<u16&>(v2) << 32) | ((ull)reinterpret_cast<u16&>(v3) << 48);
        *reinterpret_cast<ull*>(gv16 + off) = pk;
    }
}

// ============================================================
// Tensor-core sliding-window attention, fp16 2-term:
// S = (Qh + Ql) K^T ;  O = (Ph + Pl) V
// ============================================================
#define SMEM_Q  0                    // Qh 32K | Ql 32K
#define SMEM_K  65536                // K single 16K
#define SMEM_V  81920                // V single 16K
#define SMEM_S  98304                // 128 x 68 f32 = 34816
#define SMEM_P  133120               // Ph 16K | Pl 16K
#define SMEM_AL 165888
#define SMEM_L  166400
#define ATT2_SMEM 166912

__global__ __launch_bounds__(256, 1) void attn_mma()
{
    extern __shared__ char smc[];
    const u32 sb = smem_u32(smc);
    float* S = reinterpret_cast<float*>(smc + SMEM_S);
    float* al_s = reinterpret_cast<float*>(smc + SMEM_AL);
    float* l_s = reinterpret_cast<float*>(smc + SMEM_L);

    const int tid = threadIdx.x;
    const int lane = tid & 31;
    const int w = tid >> 5;
    const int wm = w & 3;
    const int wn = w >> 2;
    const int kh = blockIdx.x;
    const int t0 = (int)(31 - blockIdx.y) * 64;

    // ---- Q tile load (split fp16) ----
#pragma unroll
    for (int l = 0; l < 8; ++l) {
        int idx = tid + l * 256;
        int r = idx >> 4, ch = idx & 15;
        int t = t0 + (r & 63), n = kh * 2 + (r >> 6);
        u32 d = (u32)((ch >> 3) * 16384 + r * 128 + (((ch & 7) * 16) ^ ((r & 7) << 4)));
        cp16(sb + SMEM_Q + d,          gq_h + (size_t)(t * NQH + n) * HD + ch * 8);
        cp16(sb + SMEM_Q + 32768 + d,  gq_l + (size_t)(t * NQH + n) * HD + ch * 8);
    }
    CP_COMMIT();

    float acc_o[2][8][4];
#pragma unroll
    for (int i = 0; i < 2; ++i)
#pragma unroll
        for (int j = 0; j < 8; ++j)
#pragma unroll
            for (int q = 0; q < 4; ++q) acc_o[i][j][q] = 0.0f;

    float m_reg = -1e30f, l_reg = 0.0f;

    const u32 aRow = (u32)((wm * 32 + (lane & 15)) * 128);
    const u32 aK   = (u32)((lane >> 4) * 16);
    const u32 aXor = (u32)((lane & 7) << 4);
    const u32 bK   = (u32)(((lane >> 3) & 1) * 16);
    u32 bRow[2];
    bRow[0] = (u32)((wn * 32 + ((lane >> 4) << 3) + (lane & 7)) * 128);
    bRow[1] = bRow[0] + 16 * 128;
    const int vrow_in = (lane & 7) + (lane & 8);
    const u32 vh8 = (u32)((lane >> 4) << 3);

    const int s_begin = (t0 >= (WINDOW - 1)) ? ((t0 - (WINDOW - 1)) & ~63) : 0;

    for (int st = s_begin; st <= t0; st += 64) {
        // ---- K/V tile load (single fp16) ----
#pragma unroll
        for (int l = 0; l < 4; ++l) {
            int idx = tid + l * 256;
            int r = idx >> 4, ch = idx & 15;
            size_t go = (size_t)((st + r) * NKH + kh) * HD + ch * 8;
            u32 dk = (u32)((ch >> 3) * 8192 + r * 128 + (((ch & 7) * 16) ^ ((r & 7) << 4)));
            u32 dv = (u32)(r * 256 + ((ch * 16) ^ ((r & 7) << 4)));
            cp16(sb + SMEM_K + dk, gk16 + go);
            cp16(sb + SMEM_V + dv, gv16 + go);
        }
        CP_COMMIT();
        CP_WAIT(0);
        __syncthreads();

        // ---- S = Q K^T (2-term fp16) ----
        float s_acc[2][4][4];
#pragma unroll
        for (int i = 0; i < 2; ++i)
#pragma unroll
            for (int j = 0; j < 4; ++j)
#pragma unroll
                for (int q = 0; q < 4; ++q) s_acc[i][j][q] = 0.0f;

#pragma unroll
        for (int kk = 0; kk < 8; ++kk) {
            const int ks = (kk + w) & 7;
            const u32 kc = (u32)(ks >> 2);
            const u32 kb = (u32)((ks & 3) * 32);
            u32 qh[2][4], ql[2][4];
#pragma unroll
            for (int mi = 0; mi < 2; ++mi) {
                u32 ao = kc * 16384 + aRow + (u32)(mi * 2048) + ((aK + kb) ^ aXor);
                ldsm4(qh[mi], sb + SMEM_Q + ao);
                ldsm4(ql[mi], sb + SMEM_Q + 32768 + ao);
            }
            u32 kf[2][4];
#pragma unroll
            for (int g = 0; g < 2; ++g) {
                u32 bo = kc * 8192 + bRow[g] + ((bK + kb) ^ aXor);
                ldsm4(kf[g], sb + SMEM_K + bo);
            }
            // term 1: Qh x K
#pragma unroll
            for (int g = 0; g < 2; ++g)
#pragma unroll
                for (int mi = 0; mi < 2; ++mi) {
                    mma_f16(s_acc[mi][2 * g],     qh[mi], kf[g][0], kf[g][1]);
                    mma_f16(s_acc[mi][2 * g + 1], qh[mi], kf[g][2], kf[g][3]);
                }
            // term 2: Ql x K
#pragma unroll
            for (int g = 0; g < 2; ++g)
#pragma unroll
                for (int mi = 0; mi < 2; ++mi) {
                    mma_f16(s_acc[mi][2 * g],     ql[mi], kf[g][0], kf[g][1]);
                    mma_f16(s_acc[mi][2 * g + 1], ql[mi], kf[g][2], kf[g][3]);
                }
        }

        // ---- softcap + mask, store S ----
#pragma unroll
        for (int mi = 0; mi < 2; ++mi) {
            int r0 = wm * 32 + mi * 16 + (lane >> 2);
#pragma unroll
            for (int n8 = 0; n8 < 4; ++n8) {
                int sl0 = wn * 32 + n8 * 8 + (lane & 3) * 2;
#pragma unroll
                for (int half = 0; half < 2; ++half) {
                    int rr = r0 + half * 8;
                    int t = t0 + (rr & 63);
                    float v0 = tanh_fast(s_acc[mi][n8][half * 2]     * (1.0f / SOFTCAP)) * SOFTCAP;
                    float v1 = tanh_fast(s_acc[mi][n8][half * 2 + 1] * (1.0f / SOFTCAP)) * SOFTCAP;
                    int sg0 = st + sl0, sg1 = sg0 + 1;
                    bool ok0 = (sg0 <= t) && (sg0 > t - WINDOW);
                    bool ok1 = (sg1 <= t) && (sg1 > t - WINDOW);
                    *reinterpret_cast<float2*>(&S[rr * 68 + sl0]) =
                        make_float2(ok0 ? v0 : -1e30f, ok1 ? v1 : -1e30f);
                }
            }
        }
        __syncthreads();

        // ---- online softmax: 2 threads per row, P split fp16 ----
        {
            const int row = tid >> 1;
            const int half = tid & 1;
            const int cb = half * 32;
            float tm = -1e30f;
#pragma unroll 8
            for (int c = 0; c < 32; ++c) tm = fmaxf(tm, S[row * 68 + cb + c]);
            tm = fmaxf(tm, __shfl_xor_sync(0xffffffffu, tm, 1));
            float mnew = fmaxf(m_reg, tm);
            float a = __expf(m_reg - mnew);
            float lsum = 0.0f;
            char* ph = smc + SMEM_P + row * 128;
            char* pl = smc + SMEM_P + 16384 + row * 128;
            const u32 xr = (u32)((row & 7) << 4);
#pragma unroll 8
            for (int c = 0; c < 32; ++c) {
                float p = __expf(S[row * 68 + cb + c] - mnew);
                lsum += p;
                u16 hh, ll;
                split_fp16(p, hh, ll);
                u32 off = ((u32)((cb + c) * 2)) ^ xr;
                *reinterpret_cast<u16*>(ph + off) = hh;
                *reinterpret_cast<u16*>(pl + off) = ll;
            }
            lsum += __shfl_xor_sync(0xffffffffu, lsum, 1);
            l_reg = l_reg * a + lsum;
            m_reg = mnew;
            if (half == 0) al_s[row] = a;
        }
        __syncthreads();

        // ---- rescale O, then O += P V (2-term fp16) ----
#pragma unroll
        for (int mi = 0; mi < 2; ++mi) {
            int r0 = wm * 32 + mi * 16 + (lane >> 2);
            float a0 = al_s[r0], a1 = al_s[r0 + 8];
#pragma unroll
            for (int n8 = 0; n8 < 8; ++n8) {
                acc_o[mi][n8][0] *= a0; acc_o[mi][n8][1] *= a0;
                acc_o[mi][n8][2] *= a1; acc_o[mi][n8][3] *= a1;
            }
        }
#pragma unroll
        for (int kk = 0; kk < 4; ++kk) {
            const int ks = (kk + (w & 3)) & 3;
            const u32 kb = (u32)(ks * 32);
            u32 ph[2][4], pl[2][4];
#pragma unroll
            for (int mi = 0; mi < 2; ++mi) {
                u32 ao = aRow + (u32)(mi * 2048) + ((aK + kb) ^ aXor);
                ldsm4(ph[mi], sb + SMEM_P + ao);
                ldsm4(pl[mi], sb + SMEM_P + 16384 + ao);
            }
            const int vrow = ks * 16 + vrow_in;
            const u32 vswz = (u32)(vrow * 256);
            const u32 vxr = (u32)((vrow & 7) << 4);
#pragma unroll
            for (int pg = 0; pg < 2; ++pg) {
                u32 vhf[2][4];
#pragma unroll
                for (int j = 0; j < 2; ++j) {
                    int pair = pg * 2 + j;
                    u32 hq = (u32)(wn * 64 + pair * 16) + vh8;
                    u32 va = sb + SMEM_V + vswz + (((hq >> 3) * 16) ^ vxr);
                    ldsm4t(vhf[j], va);
                }
                // term 1: Ph x V
#pragma unroll
                for (int j = 0; j < 2; ++j) {
                    int pair = pg * 2 + j;
#pragma unroll
                    for (int mi = 0; mi < 2; ++mi) {
                        mma_f16(acc_o[mi][pair * 2],     ph[mi], vhf[j][0], vhf[j][1]);
                        mma_f16(acc_o[mi][pair * 2 + 1], ph[mi], vhf[j][2], vhf[j][3]);
                    }
                }
                // term 2: Pl x V
#pragma unroll
                for (int j = 0; j < 2; ++j) {
                    int pair = pg * 2 + j;
#pragma unroll
                    for (int mi = 0; mi < 2; ++mi) {
                        mma_f16(acc_o[mi][pair * 2],     pl[mi], vhf[j][0], vhf[j][1]);
                        mma_f16(acc_o[mi][pair * 2 + 1], pl[mi], vhf[j][2], vhf[j][3]);
                    }
                }
            }
        }
        __syncthreads();
    }

    if ((tid & 1) == 0) l_s[tid >> 1] = l_reg;
    __syncthreads();

#pragma unroll
    for (int mi = 0; mi < 2; ++mi) {
        int r0 = wm * 32 + mi * 16 + (lane >> 2);
        float i0 = 1.0f / l_s[r0];
        float i1 = 1.0f / l_s[r0 + 8];
#pragma unroll
        for (int n8 = 0; n8 < 8; ++n8) {
            int h = wn * 64 + n8 * 8 + (lane & 3) * 2;
#pragma unroll
            for (int half = 0; half < 2; ++half) {
                int rr = r0 + half * 8;
                int t = t0 + (rr & 63);
                int n = kh * 2 + (rr >> 6);
                float iv = half ? i1 : i0;
                *reinterpret_cast<float2*>(&g_enc[(size_t)(t * NQH + n) * HD + h]) =
                    make_float2(acc_o[mi][n8][half * 2] * iv,
                                acc_o[mi][n8][half * 2 + 1] * iv);
            }
        }
    }
}

// ============================================================
extern "C" void kernel_launch(void* const* d_in, const int* in_sizes, int n_in,
                              void* d_out, int out_size)
{
    (void)in_sizes; (void)n_in; (void)out_size;
    const float* x   = (const float*)d_in[0];
    const int*   seg = (const int*)d_in[1];
    const float* qw  = (const float*)d_in[3];
    const float* kvw = (const float*)d_in[4];
    const float* ow  = (const float*)d_in[5];
    float* out = (float*)d_out;

    cudaFuncSetAttribute(hmma_gemm, cudaFuncAttributeMaxDynamicSharedMemorySize, GEMM_SMEM);
    cudaFuncSetAttribute(attn_mma, cudaFuncAttributeMaxDynamicSharedMemorySize, ATT2_SMEM);

    convert_hl<<<4096, 256>>>(x, 0);
    wconv<<<dim3(128, 64), 256>>>(qw, kvw, ow, 0);
    wconv<<<dim3(64, 64), 256>>>(qw, kvw, ow, 1);
    hmma_gemm<<<dim3(32, 16), 256, GEMM_SMEM>>>(nullptr, 0, 1);   // qkv
    rope_split<<<T_DIM, 256>>>(seg);
    attn_mma<<<dim3(NKH, 32), 256, ATT2_SMEM>>>();
    convert_hl<<<4096, 256>>>(x, 1);                               // g_enc -> ge
    hmma_gemm<<<dim3(16, 16), 256, GEMM_SMEM>>>(out, D_DIM, 0);   // out proj
}

// round 14
// speedup vs baseline: 4.3697x; 1.1618x over previous
#include <cuda_runtime.h>
#include <cuda_bf16.h>
#include <cuda_fp16.h>
#include <math.h>

typedef unsigned long long ull;
typedef unsigned int u32;
typedef unsigned short u16;

#define T_DIM 2048
#define D_DIM 2048
#define NQH 16
#define NKH 8
#define HD 128
#define WINDOW 1024
#define SOFTCAP 50.0f
#define QSCALE 0.08838834764831845f
#define QELEMS (T_DIM * NQH * HD)
#define KVELEMS (T_DIM * NKH * HD)

// fp32 scratch
__device__ float g_q[QELEMS];
__device__ float g_k[KVELEMS];
__device__ float g_v[KVELEMS];
__device__ float g_enc[QELEMS];

// fp16 split activations + single-fp16 weights (projection GEMMs)
__device__ u16 gx_h[T_DIM * D_DIM], gx_l[T_DIM * D_DIM];
__device__ u16 ge_h[T_DIM * D_DIM], ge_l[T_DIM * D_DIM];
__device__ u16 gw[4096 * D_DIM];
__device__ u16 gwo[D_DIM * D_DIM];
// attention operands: q split fp16, k/v single fp16
__device__ u16 gq_h[QELEMS], gq_l[QELEMS];
__device__ u16 gk16[KVELEMS];
__device__ u16 gv16[KVELEMS];

__device__ __forceinline__ u32 smem_u32(const void* p) {
    u32 a; asm("{ .reg .u64 t; cvta.to.shared.u64 t, %1; cvt.u32.u64 %0, t; }" : "=r"(a) : "l"(p));
    return a;
}
__device__ __forceinline__ void ldsm4(u32* r, u32 addr) {
    asm volatile("ldmatrix.sync.aligned.m8n8.x4.shared.b16 {%0,%1,%2,%3}, [%4];"
        : "=r"(r[0]), "=r"(r[1]), "=r"(r[2]), "=r"(r[3]) : "r"(addr));
}
__device__ __forceinline__ void ldsm4t(u32* r, u32 addr) {
    asm volatile("ldmatrix.sync.aligned.m8n8.x4.trans.shared.b16 {%0,%1,%2,%3}, [%4];"
        : "=r"(r[0]), "=r"(r[1]), "=r"(r[2]), "=r"(r[3]) : "r"(addr));
}
__device__ __forceinline__ void mma_f16(float* c, const u32* a, u32 b0, u32 b1) {
    asm volatile("mma.sync.aligned.m16n8k16.row.col.f32.f16.f16.f32 "
        "{%0,%1,%2,%3}, {%4,%5,%6,%7}, {%8,%9}, {%0,%1,%2,%3};"
        : "+f"(c[0]), "+f"(c[1]), "+f"(c[2]), "+f"(c[3])
        : "r"(a[0]), "r"(a[1]), "r"(a[2]), "r"(a[3]), "r"(b0), "r"(b1));
}
__device__ __forceinline__ void cp16(u32 dst, const void* src) {
    asm volatile("cp.async.cg.shared.global [%0], [%1], 16;" :: "r"(dst), "l"(src));
}
#define CP_COMMIT() asm volatile("cp.async.commit_group;" ::: "memory")
#define CP_WAIT(n)  asm volatile("cp.async.wait_group %0;" :: "n"(n) : "memory")

__device__ __forceinline__ void split_fp16(float v, u16& h, u16& l) {
    __half hh = __float2half_rn(v);
    float r = v - __half2float(hh);
    __half ll = __float2half_rn(r);
    h = reinterpret_cast<u16&>(hh);
    l = reinterpret_cast<u16&>(ll);
}
__device__ __forceinline__ float tanh_fast(float x) {
    float c = fminf(fmaxf(x, -12.0f), 12.0f);
    float e = __expf(2.0f * c);
    return (e - 1.0f) / (e + 1.0f);
}

// ============================================================
// Elementwise split-convert to fp16 hi/lo (x or enc)
// ============================================================
__global__ void convert_hl(const float* __restrict__ src_x, int mode)
{
    const float* __restrict__ src = mode ? (const float*)g_enc : src_x;
    u16* __restrict__ h = mode ? ge_h : gx_h;
    u16* __restrict__ l = mode ? ge_l : gx_l;
    int i = (blockIdx.x * 256 + threadIdx.x) * 4;
    float4 v = *reinterpret_cast<const float4*>(src + i);
    u16 h0, h1, h2, h3, l0, l1, l2, l3;
    split_fp16(v.x, h0, l0); split_fp16(v.y, h1, l1);
    split_fp16(v.z, h2, l2); split_fp16(v.w, h3, l3);
    *reinterpret_cast<ull*>(h + i) = (ull)h0 | ((ull)h1 << 16) | ((ull)h2 << 32) | ((ull)h3 << 48);
    *reinterpret_cast<ull*>(l + i) = (ull)l0 | ((ull)l1 << 16) | ((ull)l2 << 32) | ((ull)l3 << 48);
}

// ============================================================
// Weight transpose + fp16 convert, 32x32 tiles.
// ============================================================
__global__ void wconv(const float* __restrict__ qw, const float* __restrict__ kvw,
                      const float* __restrict__ ow, int mode)
{
    __shared__ float s[32][33];
    const int c0 = blockIdx.x * 32;
    const int k0 = blockIdx.y * 32;
    const int tx = threadIdx.x & 31;
    const int ty = threadIdx.x >> 5;
    u16* __restrict__ dh = mode ? gwo : gw;

#pragma unroll
    for (int rr = ty; rr < 32; rr += 8) {
        int k = k0 + rr;
        int c = c0 + tx;
        float v;
        if (mode == 0) {
            const float* base;
            int cc = c;
            if (cc < 2048)      base = qw + (cc >> 7) * (D_DIM * HD);
            else if (cc < 3072) { cc -= 2048; base = kvw + (cc >> 7) * (D_DIM * HD); }
            else                { cc -= 3072; base = kvw + (8 + (cc >> 7)) * (D_DIM * HD); }
            v = base[k * HD + (cc & 127)];
        } else {
            v = ow[k * D_DIM + c];
        }
        s[tx][rr] = v;
    }
    __syncthreads();
#pragma unroll
    for (int rr = ty; rr < 32; rr += 8) {
        __half hv = __float2half_rn(s[rr][tx]);
        dh[(c0 + rr) * D_DIM + k0 + tx] = reinterpret_cast<u16&>(hv);
    }
}

// ============================================================
// HMMA GEMM: fp16, runtime 1- or 2-term A (qkv=1-term, out=2-term).
// 256 threads, software-pipelined fragments, 3-stage cp.async.
// ============================================================
#define STAGE_BYTES 49152
#define GEMM_SMEM (3 * STAGE_BYTES)

__device__ __forceinline__ void load_stage256(
    u32 sbase, int p, int tid, int row0, int col0, int kk,
    const u16* __restrict__ Ah, const u16* __restrict__ Al,
    const u16* __restrict__ B, int two)
{
    u32 stg = sbase + (u32)p * STAGE_BYTES;
#pragma unroll
    for (int l = 0; l < 4; ++l) {
        int idx = tid + l * 256;
        int r = idx >> 3;
        int ch = idx & 7;
        u32 doff = (u32)(r * 128) + (u32)((ch * 16) ^ ((r & 7) << 4));
        int aoff = (row0 + r) * D_DIM + kk + ch * 8;
        int boff = (col0 + r) * D_DIM + kk + ch * 8;
        cp16(stg + doff,             Ah + aoff);
        if (two) cp16(stg + 16384 + doff, Al + aoff);
        cp16(stg + 32768 + doff,     B + boff);
    }
}

__device__ __forceinline__ void gemm_frags(
    u32 stg, u32 aRow, u32 aK, u32 aXor, u32 bRow, u32 bK, u32 kb,
    u32 ah[2][4], u32 al[2][4], u32 bf[4][4], int two)
{
#pragma unroll
    for (int mi = 0; mi < 2; ++mi) {
        u32 ao = aRow + (u32)(mi * 2048) + ((aK + kb) ^ aXor);
        ldsm4(ah[mi], stg + ao);
        if (two) ldsm4(al[mi], stg + 16384 + ao);
    }
#pragma unroll
    for (int n4 = 0; n4 < 4; ++n4) {
        u32 bo = bRow + (u32)(n4 * 2048) + ((bK + kb) ^ aXor);
        ldsm4(bf[n4], stg + 32768 + bo);
    }
}

__global__ __launch_bounds__(256, 1)
void hmma_gemm(float* __restrict__ dst0, int ldc0, int qkv_mode)
{
    extern __shared__ char smem[];
    const u32 sb = smem_u32(smem);
    const int tid = threadIdx.x;
    const int lane = tid & 31;
    const int w = tid >> 5;
    const int wm = w & 3;
    const int wn = w >> 2;
    const int row0 = blockIdx.y * 128;
    const int col0 = blockIdx.x * 128;
    const int two = qkv_mode ? 0 : 1;     // qkv: single-A; out: split-A

    const u16 *Ah, *Al, *B;
    float* dst; int ldc, cofs;
    if (qkv_mode) {
        Ah = gx_h; Al = gx_l; B = gw;
        if (col0 < 2048)      { dst = g_q; ldc = 2048; cofs = col0; }
        else if (col0 < 3072) { dst = g_k; ldc = 1024; cofs = col0 - 2048; }
        else                  { dst = g_v; ldc = 1024; cofs = col0 - 3072; }
    } else {
        Ah = ge_h; Al = ge_l; B = gwo;
        dst = dst0; ldc = ldc0; cofs = col0;
    }

    float acc[2][8][4];
#pragma unroll
    for (int i = 0; i < 2; ++i)
#pragma unroll
        for (int j = 0; j < 8; ++j)
#pragma unroll
            for (int q = 0; q < 4; ++q) acc[i][j][q] = 0.0f;

    const u32 aRow = (u32)(wm * 32 + (lane & 15)) * 128;
    const u32 aXor = (u32)((lane & 7) << 4);
    const u32 aK   = (u32)((lane >> 4) * 16);
    const u32 bRow = (u32)(wn * 64 + ((lane >> 4) << 3) + (lane & 7)) * 128;
    const u32 bK   = (u32)(((lane >> 3) & 1) * 16);

    u32 ah[2][2][4], al[2][2][4], bf[2][4][4];

    load_stage256(sb, 0, tid, row0, col0, 0, Ah, Al, B, two);
    CP_COMMIT();
    load_stage256(sb, 1, tid, row0, col0, 64, Ah, Al, B, two);
    CP_COMMIT();

    int stage_c = 0;
    for (int c = 0; c < 32; ++c) {
        if (c < 31) { CP_WAIT(1); } else { CP_WAIT(0); }
        __syncthreads();
        if (c + 2 < 32) {
            int sn = stage_c + 2; if (sn >= 3) sn -= 3;
            load_stage256(sb, sn, tid, row0, col0, (c + 2) * 64, Ah, Al, B, two);
            CP_COMMIT();
        }

        const u32 stg = sb + (u32)stage_c * STAGE_BYTES;
        gemm_frags(stg, aRow, aK, aXor, bRow, bK, 0, ah[0], al[0], bf[0], two);
#pragma unroll
        for (int ks = 0; ks < 4; ++ks) {
            const int cur = ks & 1;
            if (ks < 3) {
                gemm_frags(stg, aRow, aK, aXor, bRow, bK, (u32)((ks + 1) * 32),
                           ah[cur ^ 1], al[cur ^ 1], bf[cur ^ 1], two);
            }
#pragma unroll
            for (int n4 = 0; n4 < 4; ++n4)
#pragma unroll
                for (int mi = 0; mi < 2; ++mi) {
                    mma_f16(acc[mi][2 * n4],     ah[cur][mi], bf[cur][n4][0], bf[cur][n4][1]);
                    mma_f16(acc[mi][2 * n4 + 1], ah[cur][mi], bf[cur][n4][2], bf[cur][n4][3]);
                }
            if (two) {
#pragma unroll
                for (int n4 = 0; n4 < 4; ++n4)
#pragma unroll
                    for (int mi = 0; mi < 2; ++mi) {
                        mma_f16(acc[mi][2 * n4],     al[cur][mi], bf[cur][n4][0], bf[cur][n4][1]);
                        mma_f16(acc[mi][2 * n4 + 1], al[cur][mi], bf[cur][n4][2], bf[cur][n4][3]);
                    }
            }
        }
        if (++stage_c >= 3) stage_c -= 3;
    }

    const int rbase = row0 + wm * 32 + (lane >> 2);
    const int cbase = cofs + wn * 64 + (lane & 3) * 2;
#pragma unroll
    for (int mi = 0; mi < 2; ++mi) {
#pragma unroll
        for (int nt = 0; nt < 8; ++nt) {
            int r = rbase + mi * 16;
            int cc = cbase + nt * 8;
            *reinterpret_cast<float2*>(dst + r * ldc + cc) =
                make_float2(acc[mi][nt][0], acc[mi][nt][1]);
            *reinterpret_cast<float2*>(dst + (r + 8) * ldc + cc) =
                make_float2(acc[mi][nt][2], acc[mi][nt][3]);
        }
    }
}

// ============================================================
// RoPE + fp16 convert fused: q split hi/lo, k/v single fp16.
// ============================================================
__global__ void rope_split(const int* __restrict__ seg)
{
    __shared__ float s_ts[64];
    const int t = blockIdx.x;
    const int tid = threadIdx.x;
    if (tid < 64) {
        double f = (double)tid / 64.0;
        s_ts[tid] = (float)pow(10000.0, f);
    }
    __syncthreads();
    const float pos = (float)seg[t];
    for (int idx = tid; idx < (NQH + NKH) * 64; idx += 256) {
        int head = idx >> 6;
        int i = idx & 63;
        float ang = pos / s_ts[i];
        float sv, cv;
        sincosf(ang, &sv, &cv);
        if (head < NQH) {
            int off = t * (NQH * HD) + head * HD;
            const float* base = g_q + off;
            float x1 = base[i], x2 = base[i + 64];
            float o1 = (x1 * cv - x2 * sv) * QSCALE;
            float o2 = (x2 * cv + x1 * sv) * QSCALE;
            u16 h1, l1, h2, l2;
            split_fp16(o1, h1, l1);
            split_fp16(o2, h2, l2);
            gq_h[off + i] = h1;       gq_l[off + i] = l1;
            gq_h[off + i + 64] = h2;  gq_l[off + i + 64] = l2;
        } else {
            int off = t * (NKH * HD) + (head - NQH) * HD;
            const float* base = g_k + off;
            float x1 = base[i], x2 = base[i + 64];
            float o1 = x1 * cv - x2 * sv;
            float o2 = x2 * cv + x1 * sv;
            __half h1 = __float2half_rn(o1);
            __half h2 = __float2half_rn(o2);
            gk16[off + i]      = reinterpret_cast<u16&>(h1);
            gk16[off + i + 64] = reinterpret_cast<u16&>(h2);
        }
    }
    {
        int off = t * (NKH * HD) + tid * 4;
        float4 v = *reinterpret_cast<const float4*>(g_v + off);
        __half v0 = __float2half_rn(v.x), v1 = __float2half_rn(v.y);
        __half v2 = __float2half_rn(v.z), v3 = __float2half_rn(v.w);
        ull pk = (ull)reinterpret_cast<u16&>(v0) | ((ull)reinterpret_cast<u16&>(v1) << 16)
               | ((ull)reinterpret_cast<u16&>(v2) << 32) | ((ull)reinterpret_cast<u16&>(v3) << 48);
        *reinterpret_cast<ull*>(gv16 + off) = pk;
    }
}

// ============================================================
// Tensor-core sliding-window attention, fp16 2-term,
// K/V double-buffered prefetch across tiles.
// SMEM: Q 64K | KV[2] 2x32K | S 34K | P 32K | al/l
// ============================================================
#define SMEM_Q   0
#define SMEM_KV  65536       // buf p at +p*32768: K 16K, V 16K
#define SMEM_S   131072
#define SMEM_P   165888
#define SMEM_AL  198656
#define SMEM_L   199168
#define ATT2_SMEM 199680

__device__ __forceinline__ void attn_load_kv(u32 sb, int p, int tid, int st, int kh)
{
    u32 kvb = sb + SMEM_KV + (u32)p * 32768;
#pragma unroll
    for (int l = 0; l < 4; ++l) {
        int idx = tid + l * 256;
        int r = idx >> 4, ch = idx & 15;
        size_t go = (size_t)((st + r) * NKH + kh) * HD + ch * 8;
        u32 dk = (u32)((ch >> 3) * 8192 + r * 128 + (((ch & 7) * 16) ^ ((r & 7) << 4)));
        u32 dv = (u32)(r * 256 + ((ch * 16) ^ ((r & 7) << 4)));
        cp16(kvb + dk,         gk16 + go);
        cp16(kvb + 16384 + dv, gv16 + go);
    }
}

__global__ __launch_bounds__(256, 1) void attn_mma()
{
    extern __shared__ char smc[];
    const u32 sb = smem_u32(smc);
    float* S = reinterpret_cast<float*>(smc + SMEM_S);
    float* al_s = reinterpret_cast<float*>(smc + SMEM_AL);
    float* l_s = reinterpret_cast<float*>(smc + SMEM_L);

    const int tid = threadIdx.x;
    const int lane = tid & 31;
    const int w = tid >> 5;
    const int wm = w & 3;
    const int wn = w >> 2;
    const int kh = blockIdx.x;
    const int t0 = (int)(31 - blockIdx.y) * 64;

    // ---- Q tile load (split fp16) ----
#pragma unroll
    for (int l = 0; l < 8; ++l) {
        int idx = tid + l * 256;
        int r = idx >> 4, ch = idx & 15;
        int t = t0 + (r & 63), n = kh * 2 + (r >> 6);
        u32 d = (u32)((ch >> 3) * 16384 + r * 128 + (((ch & 7) * 16) ^ ((r & 7) << 4)));
        cp16(sb + SMEM_Q + d,          gq_h + (size_t)(t * NQH + n) * HD + ch * 8);
        cp16(sb + SMEM_Q + 32768 + d,  gq_l + (size_t)(t * NQH + n) * HD + ch * 8);
    }
    CP_COMMIT();

    float acc_o[2][8][4];
#pragma unroll
    for (int i = 0; i < 2; ++i)
#pragma unroll
        for (int j = 0; j < 8; ++j)
#pragma unroll
            for (int q = 0; q < 4; ++q) acc_o[i][j][q] = 0.0f;

    float m_reg = -1e30f, l_reg = 0.0f;

    const u32 aRow = (u32)((wm * 32 + (lane & 15)) * 128);
    const u32 aK   = (u32)((lane >> 4) * 16);
    const u32 aXor = (u32)((lane & 7) << 4);
    const u32 bK   = (u32)(((lane >> 3) & 1) * 16);
    u32 bRow[2];
    bRow[0] = (u32)((wn * 32 + ((lane >> 4) << 3) + (lane & 7)) * 128);
    bRow[1] = bRow[0] + 16 * 128;
    const int vrow_in = (lane & 7) + (lane & 8);
    const u32 vh8 = (u32)((lane >> 4) << 3);

    const int s_begin = (t0 >= (WINDOW - 1)) ? ((t0 - (WINDOW - 1)) & ~63) : 0;
    const int ntile = (t0 - s_begin) / 64 + 1;

    attn_load_kv(sb, 0, tid, s_begin, kh);
    CP_COMMIT();

    for (int it = 0; it < ntile; ++it) {
        const int st = s_begin + it * 64;
        const int p = it & 1;
        if (it + 1 < ntile) {
            attn_load_kv(sb, p ^ 1, tid, st + 64, kh);
            CP_COMMIT();
            CP_WAIT(1);
        } else {
            CP_WAIT(0);
        }
        __syncthreads();
        const u32 kvb = sb + SMEM_KV + (u32)p * 32768;

        // ---- S = Q K^T (2-term fp16) ----
        float s_acc[2][4][4];
#pragma unroll
        for (int i = 0; i < 2; ++i)
#pragma unroll
            for (int j = 0; j < 4; ++j)
#pragma unroll
                for (int q = 0; q < 4; ++q) s_acc[i][j][q] = 0.0f;

#pragma unroll
        for (int kk = 0; kk < 8; ++kk) {
            const int ks = (kk + w) & 7;
            const u32 kc = (u32)(ks >> 2);
            const u32 kb = (u32)((ks & 3) * 32);
            u32 qh[2][4], ql[2][4];
#pragma unroll
            for (int mi = 0; mi < 2; ++mi) {
                u32 ao = kc * 16384 + aRow + (u32)(mi * 2048) + ((aK + kb) ^ aXor);
                ldsm4(qh[mi], sb + SMEM_Q + ao);
                ldsm4(ql[mi], sb + SMEM_Q + 32768 + ao);
            }
            u32 kf[2][4];
#pragma unroll
            for (int g = 0; g < 2; ++g) {
                u32 bo = kc * 8192 + bRow[g] + ((bK + kb) ^ aXor);
                ldsm4(kf[g], kvb + bo);
            }
#pragma unroll
            for (int g = 0; g < 2; ++g)
#pragma unroll
                for (int mi = 0; mi < 2; ++mi) {
                    mma_f16(s_acc[mi][2 * g],     qh[mi], kf[g][0], kf[g][1]);
                    mma_f16(s_acc[mi][2 * g + 1], qh[mi], kf[g][2], kf[g][3]);
                }
#pragma unroll
            for (int g = 0; g < 2; ++g)
#pragma unroll
                for (int mi = 0; mi < 2; ++mi) {
                    mma_f16(s_acc[mi][2 * g],     ql[mi], kf[g][0], kf[g][1]);
                    mma_f16(s_acc[mi][2 * g + 1], ql[mi], kf[g][2], kf[g][3]);
                }
        }

        // ---- softcap + mask, store S ----
#pragma unroll
        for (int mi = 0; mi < 2; ++mi) {
            int r0 = wm * 32 + mi * 16 + (lane >> 2);
#pragma unroll
            for (int n8 = 0; n8 < 4; ++n8) {
                int sl0 = wn * 32 + n8 * 8 + (lane & 3) * 2;
#pragma unroll
                for (int half = 0; half < 2; ++half) {
                    int rr = r0 + half * 8;
                    int t = t0 + (rr & 63);
                    float v0 = tanh_fast(s_acc[mi][n8][half * 2]     * (1.0f / SOFTCAP)) * SOFTCAP;
                    float v1 = tanh_fast(s_acc[mi][n8][half * 2 + 1] * (1.0f / SOFTCAP)) * SOFTCAP;
                    int sg0 = st + sl0, sg1 = sg0 + 1;
                    bool ok0 = (sg0 <= t) && (sg0 > t - WINDOW);
                    bool ok1 = (sg1 <= t) && (sg1 > t - WINDOW);
                    *reinterpret_cast<float2*>(&S[rr * 68 + sl0]) =
                        make_float2(ok0 ? v0 : -1e30f, ok1 ? v1 : -1e30f);
                }
            }
        }
        __syncthreads();

        // ---- online softmax: 2 threads per row, P split fp16 ----
        {
            const int row = tid >> 1;
            const int half = tid & 1;
            const int cb = half * 32;
            float tm = -1e30f;
#pragma unroll 8
            for (int c = 0; c < 32; ++c) tm = fmaxf(tm, S[row * 68 + cb + c]);
            tm = fmaxf(tm, __shfl_xor_sync(0xffffffffu, tm, 1));
            float mnew = fmaxf(m_reg, tm);
            float a = __expf(m_reg - mnew);
            float lsum = 0.0f;
            char* ph = smc + SMEM_P + row * 128;
            char* pl = smc + SMEM_P + 16384 + row * 128;
            const u32 xr = (u32)((row & 7) << 4);
#pragma unroll 8
            for (int c = 0; c < 32; ++c) {
                float p = __expf(S[row * 68 + cb + c] - mnew);
                lsum += p;
                u16 hh, ll;
                split_fp16(p, hh, ll);
                u32 off = ((u32)((cb + c) * 2)) ^ xr;
                *reinterpret_cast<u16*>(ph + off) = hh;
                *reinterpret_cast<u16*>(pl + off) = ll;
            }
            lsum += __shfl_xor_sync(0xffffffffu, lsum, 1);
            l_reg = l_reg * a + lsum;
            m_reg = mnew;
            if (half == 0) al_s[row] = a;
        }
        __syncthreads();

        // ---- rescale O, then O += P V (2-term fp16) ----
#pragma unroll
        for (int mi = 0; mi < 2; ++mi) {
            int r0 = wm * 32 + mi * 16 + (lane >> 2);
            float a0 = al_s[r0], a1 = al_s[r0 + 8];
#pragma unroll
            for (int n8 = 0; n8 < 8; ++n8) {
                acc_o[mi][n8][0] *= a0; acc_o[mi][n8][1] *= a0;
                acc_o[mi][n8][2] *= a1; acc_o[mi][n8][3] *= a1;
            }
        }
#pragma unroll
        for (int kk = 0; kk < 4; ++kk) {
            const int ks = (kk + (w & 3)) & 3;
            const u32 kb = (u32)(ks * 32);
            u32 ph[2][4], pl[2][4];
#pragma unroll
            for (int mi = 0; mi < 2; ++mi) {
                u32 ao = aRow + (u32)(mi * 2048) + ((aK + kb) ^ aXor);
                ldsm4(ph[mi], sb + SMEM_P + ao);
                ldsm4(pl[mi], sb + SMEM_P + 16384 + ao);
            }
            const int vrow = ks * 16 + vrow_in;
            const u32 vswz = (u32)(vrow * 256);
            const u32 vxr = (u32)((vrow & 7) << 4);
#pragma unroll
            for (int pg = 0; pg < 2; ++pg) {
                u32 vhf[2][4];
#pragma unroll
                for (int j = 0; j < 2; ++j) {
                    int pair = pg * 2 + j;
                    u32 hq = (u32)(wn * 64 + pair * 16) + vh8;
                    u32 va = kvb + 16384 + vswz + (((hq >> 3) * 16) ^ vxr);
                    ldsm4t(vhf[j], va);
                }
#pragma unroll
                for (int j = 0; j < 2; ++j) {
                    int pair = pg * 2 + j;
#pragma unroll
                    for (int mi = 0; mi < 2; ++mi) {
                        mma_f16(acc_o[mi][pair * 2],     ph[mi], vhf[j][0], vhf[j][1]);
                        mma_f16(acc_o[mi][pair * 2 + 1], ph[mi], vhf[j][2], vhf[j][3]);
                    }
                }
#pragma unroll
                for (int j = 0; j < 2; ++j) {
                    int pair = pg * 2 + j;
#pragma unroll
                    for (int mi = 0; mi < 2; ++mi) {
                        mma_f16(acc_o[mi][pair * 2],     pl[mi], vhf[j][0], vhf[j][1]);
                        mma_f16(acc_o[mi][pair * 2 + 1], pl[mi], vhf[j][2], vhf[j][3]);
                    }
                }
            }
        }
        __syncthreads();
    }

    if ((tid & 1) == 0) l_s[tid >> 1] = l_reg;
    __syncthreads();

#pragma unroll
    for (int mi = 0; mi < 2; ++mi) {
        int r0 = wm * 32 + mi * 16 + (lane >> 2);
        float i0 = 1.0f / l_s[r0];
        float i1 = 1.0f / l_s[r0 + 8];
#pragma unroll
        for (int n8 = 0; n8 < 8; ++n8) {
            int h = wn * 64 + n8 * 8 + (lane & 3) * 2;
#pragma unroll
            for (int half = 0; half < 2; ++half) {
                int rr = r0 + half * 8;
                int t = t0 + (rr & 63);
                int n = kh * 2 + (rr >> 6);
                float iv = half ? i1 : i0;
                *reinterpret_cast<float2*>(&g_enc[(size_t)(t * NQH + n) * HD + h]) =
                    make_float2(acc_o[mi][n8][half * 2] * iv,
                                acc_o[mi][n8][half * 2 + 1] * iv);
            }
        }
    }
}

// ============================================================
extern "C" void kernel_launch(void* const* d_in, const int* in_sizes, int n_in,
                              void* d_out, int out_size)
{
    (void)in_sizes; (void)n_in; (void)out_size;
    const float* x   = (const float*)d_in[0];
    const int*   seg = (const int*)d_in[1];
    const float* qw  = (const float*)d_in[3];
    const float* kvw = (const float*)d_in[4];
    const float* ow  = (const float*)d_in[5];
    float* out = (float*)d_out;

    cudaFuncSetAttribute(hmma_gemm, cudaFuncAttributeMaxDynamicSharedMemorySize, GEMM_SMEM);
    cudaFuncSetAttribute(attn_mma, cudaFuncAttributeMaxDynamicSharedMemorySize, ATT2_SMEM);

    convert_hl<<<4096, 256>>>(x, 0);
    wconv<<<dim3(128, 64), 256>>>(qw, kvw, ow, 0);
    wconv<<<dim3(64, 64), 256>>>(qw, kvw, ow, 1);
    hmma_gemm<<<dim3(32, 16), 256, GEMM_SMEM>>>(nullptr, 0, 1);   // qkv (single-A)
    rope_split<<<T_DIM, 256>>>(seg);
    attn_mma<<<dim3(NKH, 32), 256, ATT2_SMEM>>>();
    convert_hl<<<4096, 256>>>(x, 1);                               // g_enc -> ge
    hmma_gemm<<<dim3(16, 16), 256, GEMM_SMEM>>>(out, D_DIM, 0);   // out proj (split-A)
}

// round 15
// speedup vs baseline: 4.5072x; 1.0315x over previous
#include <cuda_runtime.h>
#include <cuda_bf16.h>
#include <cuda_fp16.h>
#include <math.h>

typedef unsigned long long ull;
typedef unsigned int u32;
typedef unsigned short u16;

#define T_DIM 2048
#define D_DIM 2048
#define NQH 16
#define NKH 8
#define HD 128
#define WINDOW 1024
#define SOFTCAP 50.0f
#define QSCALE 0.08838834764831845f
#define QELEMS (T_DIM * NQH * HD)
#define KVELEMS (T_DIM * NKH * HD)

// fp32 scratch
__device__ float g_q[QELEMS];
__device__ float g_k[KVELEMS];
__device__ float g_v[KVELEMS];

// projection operands
__device__ u16 gx16[T_DIM * D_DIM];                 // x single fp16 (qkv A)
__device__ u16 ge_h[T_DIM * D_DIM], ge_l[T_DIM * D_DIM];  // enc split (out A)
__device__ u16 gw[4096 * D_DIM];
__device__ u16 gwo[D_DIM * D_DIM];
// attention operands: q/k/v single fp16
__device__ u16 gq16[QELEMS];
__device__ u16 gk16[KVELEMS];
__device__ u16 gv16[KVELEMS];

__device__ __forceinline__ u32 smem_u32(const void* p) {
    u32 a; asm("{ .reg .u64 t; cvta.to.shared.u64 t, %1; cvt.u32.u64 %0, t; }" : "=r"(a) : "l"(p));
    return a;
}
__device__ __forceinline__ void ldsm4(u32* r, u32 addr) {
    asm volatile("ldmatrix.sync.aligned.m8n8.x4.shared.b16 {%0,%1,%2,%3}, [%4];"
        : "=r"(r[0]), "=r"(r[1]), "=r"(r[2]), "=r"(r[3]) : "r"(addr));
}
__device__ __forceinline__ void ldsm4t(u32* r, u32 addr) {
    asm volatile("ldmatrix.sync.aligned.m8n8.x4.trans.shared.b16 {%0,%1,%2,%3}, [%4];"
        : "=r"(r[0]), "=r"(r[1]), "=r"(r[2]), "=r"(r[3]) : "r"(addr));
}
__device__ __forceinline__ void mma_f16(float* c, const u32* a, u32 b0, u32 b1) {
    asm volatile("mma.sync.aligned.m16n8k16.row.col.f32.f16.f16.f32 "
        "{%0,%1,%2,%3}, {%4,%5,%6,%7}, {%8,%9}, {%0,%1,%2,%3};"
        : "+f"(c[0]), "+f"(c[1]), "+f"(c[2]), "+f"(c[3])
        : "r"(a[0]), "r"(a[1]), "r"(a[2]), "r"(a[3]), "r"(b0), "r"(b1));
}
__device__ __forceinline__ void cp16(u32 dst, const void* src) {
    asm volatile("cp.async.cg.shared.global [%0], [%1], 16;" :: "r"(dst), "l"(src));
}
#define CP_COMMIT() asm volatile("cp.async.commit_group;" ::: "memory")
#define CP_WAIT(n)  asm volatile("cp.async.wait_group %0;" :: "n"(n) : "memory")

__device__ __forceinline__ void split_fp16(float v, u16& h, u16& l) {
    __half hh = __float2half_rn(v);
    float r = v - __half2float(hh);
    __half ll = __float2half_rn(r);
    h = reinterpret_cast<u16&>(hh);
    l = reinterpret_cast<u16&>(ll);
}
__device__ __forceinline__ float tanh_fast(float x) {
    float c = fminf(fmaxf(x, -12.0f), 12.0f);
    float e = __expf(2.0f * c);
    return (e - 1.0f) / (e + 1.0f);
}

// ============================================================
// x -> single fp16
// ============================================================
__global__ void convert_x(const float* __restrict__ src)
{
    int i = (blockIdx.x * 256 + threadIdx.x) * 4;
    float4 v = *reinterpret_cast<const float4*>(src + i);
    __half h0 = __float2half_rn(v.x), h1 = __float2half_rn(v.y);
    __half h2 = __float2half_rn(v.z), h3 = __float2half_rn(v.w);
    ull pk = (ull)reinterpret_cast<u16&>(h0) | ((ull)reinterpret_cast<u16&>(h1) << 16)
           | ((ull)reinterpret_cast<u16&>(h2) << 32) | ((ull)reinterpret_cast<u16&>(h3) << 48);
    *reinterpret_cast<ull*>(gx16 + i) = pk;
}

// ============================================================
// Weight transpose + fp16 convert, 32x32 tiles.
// ============================================================
__global__ void wconv(const float* __restrict__ qw, const float* __restrict__ kvw,
                      const float* __restrict__ ow, int mode)
{
    __shared__ float s[32][33];
    const int c0 = blockIdx.x * 32;
    const int k0 = blockIdx.y * 32;
    const int tx = threadIdx.x & 31;
    const int ty = threadIdx.x >> 5;
    u16* __restrict__ dh = mode ? gwo : gw;

#pragma unroll
    for (int rr = ty; rr < 32; rr += 8) {
        int k = k0 + rr;
        int c = c0 + tx;
        float v;
        if (mode == 0) {
            const float* base;
            int cc = c;
            if (cc < 2048)      base = qw + (cc >> 7) * (D_DIM * HD);
            else if (cc < 3072) { cc -= 2048; base = kvw + (cc >> 7) * (D_DIM * HD); }
            else                { cc -= 3072; base = kvw + (8 + (cc >> 7)) * (D_DIM * HD); }
            v = base[k * HD + (cc & 127)];
        } else {
            v = ow[k * D_DIM + c];
        }
        s[tx][rr] = v;
    }
    __syncthreads();
#pragma unroll
    for (int rr = ty; rr < 32; rr += 8) {
        __half hv = __float2half_rn(s[rr][tx]);
        dh[(c0 + rr) * D_DIM + k0 + tx] = reinterpret_cast<u16&>(hv);
    }
}

// ============================================================
// HMMA GEMM: fp16, runtime 1- or 2-term A (qkv=1, out=2).
// ============================================================
#define STAGE_BYTES 49152
#define GEMM_SMEM (3 * STAGE_BYTES)

__device__ __forceinline__ void load_stage256(
    u32 sbase, int p, int tid, int row0, int col0, int kk,
    const u16* __restrict__ Ah, const u16* __restrict__ Al,
    const u16* __restrict__ B, int two)
{
    u32 stg = sbase + (u32)p * STAGE_BYTES;
#pragma unroll
    for (int l = 0; l < 4; ++l) {
        int idx = tid + l * 256;
        int r = idx >> 3;
        int ch = idx & 7;
        u32 doff = (u32)(r * 128) + (u32)((ch * 16) ^ ((r & 7) << 4));
        int aoff = (row0 + r) * D_DIM + kk + ch * 8;
        int boff = (col0 + r) * D_DIM + kk + ch * 8;
        cp16(stg + doff,             Ah + aoff);
        if (two) cp16(stg + 16384 + doff, Al + aoff);
        cp16(stg + 32768 + doff,     B + boff);
    }
}

__device__ __forceinline__ void gemm_frags(
    u32 stg, u32 aRow, u32 aK, u32 aXor, u32 bRow, u32 bK, u32 kb,
    u32 ah[2][4], u32 al[2][4], u32 bf[4][4], int two)
{
#pragma unroll
    for (int mi = 0; mi < 2; ++mi) {
        u32 ao = aRow + (u32)(mi * 2048) + ((aK + kb) ^ aXor);
        ldsm4(ah[mi], stg + ao);
        if (two) ldsm4(al[mi], stg + 16384 + ao);
    }
#pragma unroll
    for (int n4 = 0; n4 < 4; ++n4) {
        u32 bo = bRow + (u32)(n4 * 2048) + ((bK + kb) ^ aXor);
        ldsm4(bf[n4], stg + 32768 + bo);
    }
}

__global__ __launch_bounds__(256, 1)
void hmma_gemm(float* __restrict__ dst0, int ldc0, int qkv_mode)
{
    extern __shared__ char smem[];
    const u32 sb = smem_u32(smem);
    const int tid = threadIdx.x;
    const int lane = tid & 31;
    const int w = tid >> 5;
    const int wm = w & 3;
    const int wn = w >> 2;
    const int row0 = blockIdx.y * 128;
    const int col0 = blockIdx.x * 128;
    const int two = qkv_mode ? 0 : 1;

    const u16 *Ah, *Al, *B;
    float* dst; int ldc, cofs;
    if (qkv_mode) {
        Ah = gx16; Al = gx16; B = gw;
        if (col0 < 2048)      { dst = g_q; ldc = 2048; cofs = col0; }
        else if (col0 < 3072) { dst = g_k; ldc = 1024; cofs = col0 - 2048; }
        else                  { dst = g_v; ldc = 1024; cofs = col0 - 3072; }
    } else {
        Ah = ge_h; Al = ge_l; B = gwo;
        dst = dst0; ldc = ldc0; cofs = col0;
    }

    float acc[2][8][4];
#pragma unroll
    for (int i = 0; i < 2; ++i)
#pragma unroll
        for (int j = 0; j < 8; ++j)
#pragma unroll
            for (int q = 0; q < 4; ++q) acc[i][j][q] = 0.0f;

    const u32 aRow = (u32)(wm * 32 + (lane & 15)) * 128;
    const u32 aXor = (u32)((lane & 7) << 4);
    const u32 aK   = (u32)((lane >> 4) * 16);
    const u32 bRow = (u32)(wn * 64 + ((lane >> 4) << 3) + (lane & 7)) * 128;
    const u32 bK   = (u32)(((lane >> 3) & 1) * 16);

    u32 ah[2][2][4], al[2][2][4], bf[2][4][4];

    load_stage256(sb, 0, tid, row0, col0, 0, Ah, Al, B, two);
    CP_COMMIT();
    load_stage256(sb, 1, tid, row0, col0, 64, Ah, Al, B, two);
    CP_COMMIT();

    int stage_c = 0;
    for (int c = 0; c < 32; ++c) {
        if (c < 31) { CP_WAIT(1); } else { CP_WAIT(0); }
        __syncthreads();
        if (c + 2 < 32) {
            int sn = stage_c + 2; if (sn >= 3) sn -= 3;
            load_stage256(sb, sn, tid, row0, col0, (c + 2) * 64, Ah, Al, B, two);
            CP_COMMIT();
        }

        const u32 stg = sb + (u32)stage_c * STAGE_BYTES;
        gemm_frags(stg, aRow, aK, aXor, bRow, bK, 0, ah[0], al[0], bf[0], two);
#pragma unroll
        for (int ks = 0; ks < 4; ++ks) {
            const int cur = ks & 1;
            if (ks < 3) {
                gemm_frags(stg, aRow, aK, aXor, bRow, bK, (u32)((ks + 1) * 32),
                           ah[cur ^ 1], al[cur ^ 1], bf[cur ^ 1], two);
            }
#pragma unroll
            for (int n4 = 0; n4 < 4; ++n4)
#pragma unroll
                for (int mi = 0; mi < 2; ++mi) {
                    mma_f16(acc[mi][2 * n4],     ah[cur][mi], bf[cur][n4][0], bf[cur][n4][1]);
                    mma_f16(acc[mi][2 * n4 + 1], ah[cur][mi], bf[cur][n4][2], bf[cur][n4][3]);
                }
            if (two) {
#pragma unroll
                for (int n4 = 0; n4 < 4; ++n4)
#pragma unroll
                    for (int mi = 0; mi < 2; ++mi) {
                        mma_f16(acc[mi][2 * n4],     al[cur][mi], bf[cur][n4][0], bf[cur][n4][1]);
                        mma_f16(acc[mi][2 * n4 + 1], al[cur][mi], bf[cur][n4][2], bf[cur][n4][3]);
                    }
            }
        }
        if (++stage_c >= 3) stage_c -= 3;
    }

    const int rbase = row0 + wm * 32 + (lane >> 2);
    const int cbase = cofs + wn * 64 + (lane & 3) * 2;
#pragma unroll
    for (int mi = 0; mi < 2; ++mi) {
#pragma unroll
        for (int nt = 0; nt < 8; ++nt) {
            int r = rbase + mi * 16;
            int cc = cbase + nt * 8;
            *reinterpret_cast<float2*>(dst + r * ldc + cc) =
                make_float2(acc[mi][nt][0], acc[mi][nt][1]);
            *reinterpret_cast<float2*>(dst + (r + 8) * ldc + cc) =
                make_float2(acc[mi][nt][2], acc[mi][nt][3]);
        }
    }
}

// ============================================================
// RoPE + fp16 convert fused: q/k/v all single fp16.
// ============================================================
__global__ void rope_split(const int* __restrict__ seg)
{
    __shared__ float s_ts[64];
    const int t = blockIdx.x;
    const int tid = threadIdx.x;
    if (tid < 64) {
        double f = (double)tid / 64.0;
        s_ts[tid] = (float)pow(10000.0, f);
    }
    __syncthreads();
    const float pos = (float)seg[t];
    for (int idx = tid; idx < (NQH + NKH) * 64; idx += 256) {
        int head = idx >> 6;
        int i = idx & 63;
        float ang = pos / s_ts[i];
        float sv, cv;
        sincosf(ang, &sv, &cv);
        if (head < NQH) {
            int off = t * (NQH * HD) + head * HD;
            const float* base = g_q + off;
            float x1 = base[i], x2 = base[i + 64];
            float o1 = (x1 * cv - x2 * sv) * QSCALE;
            float o2 = (x2 * cv + x1 * sv) * QSCALE;
            __half h1 = __float2half_rn(o1);
            __half h2 = __float2half_rn(o2);
            gq16[off + i]      = reinterpret_cast<u16&>(h1);
            gq16[off + i + 64] = reinterpret_cast<u16&>(h2);
        } else {
            int off = t * (NKH * HD) + (head - NQH) * HD;
            const float* base = g_k + off;
            float x1 = base[i], x2 = base[i + 64];
            float o1 = x1 * cv - x2 * sv;
            float o2 = x2 * cv + x1 * sv;
            __half h1 = __float2half_rn(o1);
            __half h2 = __float2half_rn(o2);
            gk16[off + i]      = reinterpret_cast<u16&>(h1);
            gk16[off + i + 64] = reinterpret_cast<u16&>(h2);
        }
    }
    {
        int off = t * (NKH * HD) + tid * 4;
        float4 v = *reinterpret_cast<const float4*>(g_v + off);
        __half v0 = __float2half_rn(v.x), v1 = __float2half_rn(v.y);
        __half v2 = __float2half_rn(v.z), v3 = __float2half_rn(v.w);
        ull pk = (ull)reinterpret_cast<u16&>(v0) | ((ull)reinterpret_cast<u16&>(v1) << 16)
               | ((ull)reinterpret_cast<u16&>(v2) << 32) | ((ull)reinterpret_cast<u16&>(v3) << 48);
        *reinterpret_cast<ull*>(gv16 + off) = pk;
    }
}

// ============================================================
// Attention: Q single fp16, K/V single fp16, P split fp16.
// K/V double-buffered; epilogue writes enc split directly.
// SMEM: Q 32K | KV[2] 2x32K | S 34K | P 32K | al/l
// ============================================================
#define SMEM_Q   0
#define SMEM_KV  32768
#define SMEM_S   98304
#define SMEM_P   133120
#define SMEM_AL  165888
#define SMEM_L   166400
#define ATT2_SMEM 166912

__device__ __forceinline__ void attn_load_kv(u32 sb, int p, int tid, int st, int kh)
{
    u32 kvb = sb + SMEM_KV + (u32)p * 32768;
#pragma unroll
    for (int l = 0; l < 4; ++l) {
        int idx = tid + l * 256;
        int r = idx >> 4, ch = idx & 15;
        size_t go = (size_t)((st + r) * NKH + kh) * HD + ch * 8;
        u32 dk = (u32)((ch >> 3) * 8192 + r * 128 + (((ch & 7) * 16) ^ ((r & 7) << 4)));
        u32 dv = (u32)(r * 256 + ((ch * 16) ^ ((r & 7) << 4)));
        cp16(kvb + dk,         gk16 + go);
        cp16(kvb + 16384 + dv, gv16 + go);
    }
}

__global__ __launch_bounds__(256, 1) void attn_mma()
{
    extern __shared__ char smc[];
    const u32 sb = smem_u32(smc);
    float* S = reinterpret_cast<float*>(smc + SMEM_S);
    float* al_s = reinterpret_cast<float*>(smc + SMEM_AL);
    float* l_s = reinterpret_cast<float*>(smc + SMEM_L);

    const int tid = threadIdx.x;
    const int lane = tid & 31;
    const int w = tid >> 5;
    const int wm = w & 3;
    const int wn = w >> 2;
    const int kh = blockIdx.x;
    const int t0 = (int)(31 - blockIdx.y) * 64;

    // ---- Q tile load (single fp16, 32K) ----
#pragma unroll
    for (int l = 0; l < 8; ++l) {
        int idx = tid + l * 256;
        int r = idx >> 4, ch = idx & 15;
        int t = t0 + (r & 63), n = kh * 2 + (r >> 6);
        u32 d = (u32)((ch >> 3) * 16384 + r * 128 + (((ch & 7) * 16) ^ ((r & 7) << 4)));
        cp16(sb + SMEM_Q + d, gq16 + (size_t)(t * NQH + n) * HD + ch * 8);
    }
    CP_COMMIT();

    float acc_o[2][8][4];
#pragma unroll
    for (int i = 0; i < 2; ++i)
#pragma unroll
        for (int j = 0; j < 8; ++j)
#pragma unroll
            for (int q = 0; q < 4; ++q) acc_o[i][j][q] = 0.0f;

    float m_reg = -1e30f, l_reg = 0.0f;

    const u32 aRow = (u32)((wm * 32 + (lane & 15)) * 128);
    const u32 aK   = (u32)((lane >> 4) * 16);
    const u32 aXor = (u32)((lane & 7) << 4);
    const u32 bK   = (u32)(((lane >> 3) & 1) * 16);
    u32 bRow[2];
    bRow[0] = (u32)((wn * 32 + ((lane >> 4) << 3) + (lane & 7)) * 128);
    bRow[1] = bRow[0] + 16 * 128;
    const int vrow_in = (lane & 7) + (lane & 8);
    const u32 vh8 = (u32)((lane >> 4) << 3);

    const int s_begin = (t0 >= (WINDOW - 1)) ? ((t0 - (WINDOW - 1)) & ~63) : 0;
    const int ntile = (t0 - s_begin) / 64 + 1;

    attn_load_kv(sb, 0, tid, s_begin, kh);
    CP_COMMIT();

    for (int it = 0; it < ntile; ++it) {
        const int st = s_begin + it * 64;
        const int p = it & 1;
        if (it + 1 < ntile) {
            attn_load_kv(sb, p ^ 1, tid, st + 64, kh);
            CP_COMMIT();
            CP_WAIT(1);
        } else {
            CP_WAIT(0);
        }
        __syncthreads();
        const u32 kvb = sb + SMEM_KV + (u32)p * 32768;

        // ---- S = Q K^T (single fp16) ----
        float s_acc[2][4][4];
#pragma unroll
        for (int i = 0; i < 2; ++i)
#pragma unroll
            for (int j = 0; j < 4; ++j)
#pragma unroll
                for (int q = 0; q < 4; ++q) s_acc[i][j][q] = 0.0f;

#pragma unroll
        for (int kk = 0; kk < 8; ++kk) {
            const int ks = (kk + w) & 7;
            const u32 kc = (u32)(ks >> 2);
            const u32 kb = (u32)((ks & 3) * 32);
            u32 qh[2][4];
#pragma unroll
            for (int mi = 0; mi < 2; ++mi) {
                u32 ao = kc * 16384 + aRow + (u32)(mi * 2048) + ((aK + kb) ^ aXor);
                ldsm4(qh[mi], sb + SMEM_Q + ao);
            }
            u32 kf[2][4];
#pragma unroll
            for (int g = 0; g < 2; ++g) {
                u32 bo = kc * 8192 + bRow[g] + ((bK + kb) ^ aXor);
                ldsm4(kf[g], kvb + bo);
            }
#pragma unroll
            for (int g = 0; g < 2; ++g)
#pragma unroll
                for (int mi = 0; mi < 2; ++mi) {
                    mma_f16(s_acc[mi][2 * g],     qh[mi], kf[g][0], kf[g][1]);
                    mma_f16(s_acc[mi][2 * g + 1], qh[mi], kf[g][2], kf[g][3]);
                }
        }

        // ---- softcap + mask, store S ----
#pragma unroll
        for (int mi = 0; mi < 2; ++mi) {
            int r0 = wm * 32 + mi * 16 + (lane >> 2);
#pragma unroll
            for (int n8 = 0; n8 < 4; ++n8) {
                int sl0 = wn * 32 + n8 * 8 + (lane & 3) * 2;
#pragma unroll
                for (int half = 0; half < 2; ++half) {
                    int rr = r0 + half * 8;
                    int t = t0 + (rr & 63);
                    float v0 = tanh_fast(s_acc[mi][n8][half * 2]     * (1.0f / SOFTCAP)) * SOFTCAP;
                    float v1 = tanh_fast(s_acc[mi][n8][half * 2 + 1] * (1.0f / SOFTCAP)) * SOFTCAP;
                    int sg0 = st + sl0, sg1 = sg0 + 1;
                    bool ok0 = (sg0 <= t) && (sg0 > t - WINDOW);
                    bool ok1 = (sg1 <= t) && (sg1 > t - WINDOW);
                    *reinterpret_cast<float2*>(&S[rr * 68 + sl0]) =
                        make_float2(ok0 ? v0 : -1e30f, ok1 ? v1 : -1e30f);
                }
            }
        }
        __syncthreads();

        // ---- online softmax: 2 threads per row, P split fp16 ----
        {
            const int row = tid >> 1;
            const int half = tid & 1;
            const int cb = half * 32;
            float tm = -1e30f;
#pragma unroll 8
            for (int c = 0; c < 32; ++c) tm = fmaxf(tm, S[row * 68 + cb + c]);
            tm = fmaxf(tm, __shfl_xor_sync(0xffffffffu, tm, 1));
            float mnew = fmaxf(m_reg, tm);
            float a = __expf(m_reg - mnew);
            float lsum = 0.0f;
            char* ph = smc + SMEM_P + row * 128;
            char* pl = smc + SMEM_P + 16384 + row * 128;
            const u32 xr = (u32)((row & 7) << 4);
#pragma unroll 8
            for (int c = 0; c < 32; ++c) {
                float p = __expf(S[row * 68 + cb + c] - mnew);
                lsum += p;
                u16 hh, ll;
                split_fp16(p, hh, ll);
                u32 off = ((u32)((cb + c) * 2)) ^ xr;
                *reinterpret_cast<u16*>(ph + off) = hh;
                *reinterpret_cast<u16*>(pl + off) = ll;
            }
            lsum += __shfl_xor_sync(0xffffffffu, lsum, 1);
            l_reg = l_reg * a + lsum;
            m_reg = mnew;
            if (half == 0) al_s[row] = a;
        }
        __syncthreads();

        // ---- rescale O, then O += P V (2-term fp16) ----
#pragma unroll
        for (int mi = 0; mi < 2; ++mi) {
            int r0 = wm * 32 + mi * 16 + (lane >> 2);
            float a0 = al_s[r0], a1 = al_s[r0 + 8];
#pragma unroll
            for (int n8 = 0; n8 < 8; ++n8) {
                acc_o[mi][n8][0] *= a0; acc_o[mi][n8][1] *= a0;
                acc_o[mi][n8][2] *= a1; acc_o[mi][n8][3] *= a1;
            }
        }
#pragma unroll
        for (int kk = 0; kk < 4; ++kk) {
            const int ks = (kk + (w & 3)) & 3;
            const u32 kb = (u32)(ks * 32);
            u32 ph[2][4], pl[2][4];
#pragma unroll
            for (int mi = 0; mi < 2; ++mi) {
                u32 ao = aRow + (u32)(mi * 2048) + ((aK + kb) ^ aXor);
                ldsm4(ph[mi], sb + SMEM_P + ao);
                ldsm4(pl[mi], sb + SMEM_P + 16384 + ao);
            }
            const int vrow = ks * 16 + vrow_in;
            const u32 vswz = (u32)(vrow * 256);
            const u32 vxr = (u32)((vrow & 7) << 4);
#pragma unroll
            for (int pg = 0; pg < 2; ++pg) {
                u32 vhf[2][4];
#pragma unroll
                for (int j = 0; j < 2; ++j) {
                    int pair = pg * 2 + j;
                    u32 hq = (u32)(wn * 64 + pair * 16) + vh8;
                    u32 va = kvb + 16384 + vswz + (((hq >> 3) * 16) ^ vxr);
                    ldsm4t(vhf[j], va);
                }
#pragma unroll
                for (int j = 0; j < 2; ++j) {
                    int pair = pg * 2 + j;
#pragma unroll
                    for (int mi = 0; mi < 2; ++mi) {
                        mma_f16(acc_o[mi][pair * 2],     ph[mi], vhf[j][0], vhf[j][1]);
                        mma_f16(acc_o[mi][pair * 2 + 1], ph[mi], vhf[j][2], vhf[j][3]);
                    }
                }
#pragma unroll
                for (int j = 0; j < 2; ++j) {
                    int pair = pg * 2 + j;
#pragma unroll
                    for (int mi = 0; mi < 2; ++mi) {
                        mma_f16(acc_o[mi][pair * 2],     pl[mi], vhf[j][0], vhf[j][1]);
                        mma_f16(acc_o[mi][pair * 2 + 1], pl[mi], vhf[j][2], vhf[j][3]);
                    }
                }
            }
        }
        __syncthreads();
    }

    if ((tid & 1) == 0) l_s[tid >> 1] = l_reg;
    __syncthreads();

    // ---- finalize: O/l -> enc split fp16 (hi/lo) directly ----
#pragma unroll
    for (int mi = 0; mi < 2; ++mi) {
        int r0 = wm * 32 + mi * 16 + (lane >> 2);
        float i0 = 1.0f / l_s[r0];
        float i1 = 1.0f / l_s[r0 + 8];
#pragma unroll
        for (int n8 = 0; n8 < 8; ++n8) {
            int h = wn * 64 + n8 * 8 + (lane & 3) * 2;
#pragma unroll
            for (int half = 0; half < 2; ++half) {
                int rr = r0 + half * 8;
                int t = t0 + (rr & 63);
                int n = kh * 2 + (rr >> 6);
                float iv = half ? i1 : i0;
                float o0 = acc_o[mi][n8][half * 2] * iv;
                float o1 = acc_o[mi][n8][half * 2 + 1] * iv;
                u16 h0, l0, h1, l1;
                split_fp16(o0, h0, l0);
                split_fp16(o1, h1, l1);
                size_t idx = (size_t)(t * NQH + n) * HD + h;
                *reinterpret_cast<u32*>(ge_h + idx) = (u32)h0 | ((u32)h1 << 16);
                *reinterpret_cast<u32*>(ge_l + idx) = (u32)l0 | ((u32)l1 << 16);
            }
        }
    }
}

// ============================================================
extern "C" void kernel_launch(void* const* d_in, const int* in_sizes, int n_in,
                              void* d_out, int out_size)
{
    (void)in_sizes; (void)n_in; (void)out_size;
    const float* x   = (const float*)d_in[0];
    const int*   seg = (const int*)d_in[1];
    const float* qw  = (const float*)d_in[3];
    const float* kvw = (const float*)d_in[4];
    const float* ow  = (const float*)d_in[5];
    float* out = (float*)d_out;

    cudaFuncSetAttribute(hmma_gemm, cudaFuncAttributeMaxDynamicSharedMemorySize, GEMM_SMEM);
    cudaFuncSetAttribute(attn_mma, cudaFuncAttributeMaxDynamicSharedMemorySize, ATT2_SMEM);

    convert_x<<<4096, 256>>>(x);
    wconv<<<dim3(128, 64), 256>>>(qw, kvw, ow, 0);
    wconv<<<dim3(64, 64), 256>>>(qw, kvw, ow, 1);
    hmma_gemm<<<dim3(32, 16), 256, GEMM_SMEM>>>(nullptr, 0, 1);   // qkv (1-term)
    rope_split<<<T_DIM, 256>>>(seg);
    attn_mma<<<dim3(NKH, 32), 256, ATT2_SMEM>>>();                 // writes ge_h/ge_l
    hmma_gemm<<<dim3(16, 16), 256, GEMM_SMEM>>>(out, D_DIM, 0);   // out proj (2-term)
}

// round 16
// speedup vs baseline: 4.7307x; 1.0496x over previous
#include <cuda_runtime.h>
#include <cuda_bf16.h>
#include <cuda_fp16.h>
#include <math.h>

typedef unsigned long long ull;
typedef unsigned int u32;
typedef unsigned short u16;

#define T_DIM 2048
#define D_DIM 2048
#define NQH 16
#define NKH 8
#define HD 128
#define WINDOW 1024
#define SOFTCAP 50.0f
#define QSCALE 0.08838834764831845f
#define QELEMS (T_DIM * NQH * HD)
#define KVELEMS (T_DIM * NKH * HD)

// fp32 scratch
__device__ float g_q[QELEMS];
__device__ float g_k[KVELEMS];
__device__ float g_v[KVELEMS];

// projection operands
__device__ u16 gx16[T_DIM * D_DIM];
__device__ u16 ge_h[T_DIM * D_DIM], ge_l[T_DIM * D_DIM];
__device__ u16 gw[4096 * D_DIM];
__device__ u16 gwo[D_DIM * D_DIM];
// attention operands: q/k/v single fp16
__device__ u16 gq16[QELEMS];
__device__ u16 gk16[KVELEMS];
__device__ u16 gv16[KVELEMS];

__device__ __forceinline__ u32 smem_u32(const void* p) {
    u32 a; asm("{ .reg .u64 t; cvta.to.shared.u64 t, %1; cvt.u32.u64 %0, t; }" : "=r"(a) : "l"(p));
    return a;
}
__device__ __forceinline__ void ldsm4(u32* r, u32 addr) {
    asm volatile("ldmatrix.sync.aligned.m8n8.x4.shared.b16 {%0,%1,%2,%3}, [%4];"
        : "=r"(r[0]), "=r"(r[1]), "=r"(r[2]), "=r"(r[3]) : "r"(addr));
}
__device__ __forceinline__ void ldsm4t(u32* r, u32 addr) {
    asm volatile("ldmatrix.sync.aligned.m8n8.x4.trans.shared.b16 {%0,%1,%2,%3}, [%4];"
        : "=r"(r[0]), "=r"(r[1]), "=r"(r[2]), "=r"(r[3]) : "r"(addr));
}
__device__ __forceinline__ void mma_f16(float* c, const u32* a, u32 b0, u32 b1) {
    asm volatile("mma.sync.aligned.m16n8k16.row.col.f32.f16.f16.f32 "
        "{%0,%1,%2,%3}, {%4,%5,%6,%7}, {%8,%9}, {%0,%1,%2,%3};"
        : "+f"(c[0]), "+f"(c[1]), "+f"(c[2]), "+f"(c[3])
        : "r"(a[0]), "r"(a[1]), "r"(a[2]), "r"(a[3]), "r"(b0), "r"(b1));
}
__device__ __forceinline__ void cp16(u32 dst, const void* src) {
    asm volatile("cp.async.cg.shared.global [%0], [%1], 16;" :: "r"(dst), "l"(src));
}
#define CP_COMMIT() asm volatile("cp.async.commit_group;" ::: "memory")
#define CP_WAIT(n)  asm volatile("cp.async.wait_group %0;" :: "n"(n) : "memory")

__device__ __forceinline__ void split_fp16(float v, u16& h, u16& l) {
    __half hh = __float2half_rn(v);
    float r = v - __half2float(hh);
    __half ll = __float2half_rn(r);
    h = reinterpret_cast<u16&>(hh);
    l = reinterpret_cast<u16&>(ll);
}
__device__ __forceinline__ float tanh_fast(float x) {
    float c = fminf(fmaxf(x, -12.0f), 12.0f);
    float e = __expf(2.0f * c);
    return (e - 1.0f) / (e + 1.0f);
}

// ============================================================
// x -> single fp16
// ============================================================
__global__ void convert_x(const float* __restrict__ src)
{
    int i = (blockIdx.x * 256 + threadIdx.x) * 4;
    float4 v = *reinterpret_cast<const float4*>(src + i);
    __half h0 = __float2half_rn(v.x), h1 = __float2half_rn(v.y);
    __half h2 = __float2half_rn(v.z), h3 = __float2half_rn(v.w);
    ull pk = (ull)reinterpret_cast<u16&>(h0) | ((ull)reinterpret_cast<u16&>(h1) << 16)
           | ((ull)reinterpret_cast<u16&>(h2) << 32) | ((ull)reinterpret_cast<u16&>(h3) << 48);
    *reinterpret_cast<ull*>(gx16 + i) = pk;
}

// ============================================================
// Weight transpose + fp16 convert, 32x32 tiles.
// ============================================================
__global__ void wconv(const float* __restrict__ qw, const float* __restrict__ kvw,
                      const float* __restrict__ ow, int mode)
{
    __shared__ float s[32][33];
    const int c0 = blockIdx.x * 32;
    const int k0 = blockIdx.y * 32;
    const int tx = threadIdx.x & 31;
    const int ty = threadIdx.x >> 5;
    u16* __restrict__ dh = mode ? gwo : gw;

#pragma unroll
    for (int rr = ty; rr < 32; rr += 8) {
        int k = k0 + rr;
        int c = c0 + tx;
        float v;
        if (mode == 0) {
            const float* base;
            int cc = c;
            if (cc < 2048)      base = qw + (cc >> 7) * (D_DIM * HD);
            else if (cc < 3072) { cc -= 2048; base = kvw + (cc >> 7) * (D_DIM * HD); }
            else                { cc -= 3072; base = kvw + (8 + (cc >> 7)) * (D_DIM * HD); }
            v = base[k * HD + (cc & 127)];
        } else {
            v = ow[k * D_DIM + c];
        }
        s[tx][rr] = v;
    }
    __syncthreads();
#pragma unroll
    for (int rr = ty; rr < 32; rr += 8) {
        __half hv = __float2half_rn(s[rr][tx]);
        dh[(c0 + rr) * D_DIM + k0 + tx] = reinterpret_cast<u16&>(hv);
    }
}

// ============================================================
// HMMA GEMM: fp16, runtime 1- or 2-term A (qkv=1, out=2).
// ============================================================
#define STAGE_BYTES 49152
#define GEMM_SMEM (3 * STAGE_BYTES)

__device__ __forceinline__ void load_stage256(
    u32 sbase, int p, int tid, int row0, int col0, int kk,
    const u16* __restrict__ Ah, const u16* __restrict__ Al,
    const u16* __restrict__ B, int two)
{
    u32 stg = sbase + (u32)p * STAGE_BYTES;
#pragma unroll
    for (int l = 0; l < 4; ++l) {
        int idx = tid + l * 256;
        int r = idx >> 3;
        int ch = idx & 7;
        u32 doff = (u32)(r * 128) + (u32)((ch * 16) ^ ((r & 7) << 4));
        int aoff = (row0 + r) * D_DIM + kk + ch * 8;
        int boff = (col0 + r) * D_DIM + kk + ch * 8;
        cp16(stg + doff,             Ah + aoff);
        if (two) cp16(stg + 16384 + doff, Al + aoff);
        cp16(stg + 32768 + doff,     B + boff);
    }
}

__device__ __forceinline__ void gemm_frags(
    u32 stg, u32 aRow, u32 aK, u32 aXor, u32 bRow, u32 bK, u32 kb,
    u32 ah[2][4], u32 al[2][4], u32 bf[4][4], int two)
{
#pragma unroll
    for (int mi = 0; mi < 2; ++mi) {
        u32 ao = aRow + (u32)(mi * 2048) + ((aK + kb) ^ aXor);
        ldsm4(ah[mi], stg + ao);
        if (two) ldsm4(al[mi], stg + 16384 + ao);
    }
#pragma unroll
    for (int n4 = 0; n4 < 4; ++n4) {
        u32 bo = bRow + (u32)(n4 * 2048) + ((bK + kb) ^ aXor);
        ldsm4(bf[n4], stg + 32768 + bo);
    }
}

__global__ __launch_bounds__(256, 1)
void hmma_gemm(float* __restrict__ dst0, int ldc0, int qkv_mode)
{
    extern __shared__ char smem[];
    const u32 sb = smem_u32(smem);
    const int tid = threadIdx.x;
    const int lane = tid & 31;
    const int w = tid >> 5;
    const int wm = w & 3;
    const int wn = w >> 2;
    const int row0 = blockIdx.y * 128;
    const int col0 = blockIdx.x * 128;
    const int two = qkv_mode ? 0 : 1;

    const u16 *Ah, *Al, *B;
    float* dst; int ldc, cofs;
    if (qkv_mode) {
        Ah = gx16; Al = gx16; B = gw;
        if (col0 < 2048)      { dst = g_q; ldc = 2048; cofs = col0; }
        else if (col0 < 3072) { dst = g_k; ldc = 1024; cofs = col0 - 2048; }
        else                  { dst = g_v; ldc = 1024; cofs = col0 - 3072; }
    } else {
        Ah = ge_h; Al = ge_l; B = gwo;
        dst = dst0; ldc = ldc0; cofs = col0;
    }

    float acc[2][8][4];
#pragma unroll
    for (int i = 0; i < 2; ++i)
#pragma unroll
        for (int j = 0; j < 8; ++j)
#pragma unroll
            for (int q = 0; q < 4; ++q) acc[i][j][q] = 0.0f;

    const u32 aRow = (u32)(wm * 32 + (lane & 15)) * 128;
    const u32 aXor = (u32)((lane & 7) << 4);
    const u32 aK   = (u32)((lane >> 4) * 16);
    const u32 bRow = (u32)(wn * 64 + ((lane >> 4) << 3) + (lane & 7)) * 128;
    const u32 bK   = (u32)(((lane >> 3) & 1) * 16);

    u32 ah[2][2][4], al[2][2][4], bf[2][4][4];

    load_stage256(sb, 0, tid, row0, col0, 0, Ah, Al, B, two);
    CP_COMMIT();
    load_stage256(sb, 1, tid, row0, col0, 64, Ah, Al, B, two);
    CP_COMMIT();

    int stage_c = 0;
    for (int c = 0; c < 32; ++c) {
        if (c < 31) { CP_WAIT(1); } else { CP_WAIT(0); }
        __syncthreads();
        if (c + 2 < 32) {
            int sn = stage_c + 2; if (sn >= 3) sn -= 3;
            load_stage256(sb, sn, tid, row0, col0, (c + 2) * 64, Ah, Al, B, two);
            CP_COMMIT();
        }

        const u32 stg = sb + (u32)stage_c * STAGE_BYTES;
        gemm_frags(stg, aRow, aK, aXor, bRow, bK, 0, ah[0], al[0], bf[0], two);
#pragma unroll
        for (int ks = 0; ks < 4; ++ks) {
            const int cur = ks & 1;
            if (ks < 3) {
                gemm_frags(stg, aRow, aK, aXor, bRow, bK, (u32)((ks + 1) * 32),
                           ah[cur ^ 1], al[cur ^ 1], bf[cur ^ 1], two);
            }
#pragma unroll
            for (int n4 = 0; n4 < 4; ++n4)
#pragma unroll
                for (int mi = 0; mi < 2; ++mi) {
                    mma_f16(acc[mi][2 * n4],     ah[cur][mi], bf[cur][n4][0], bf[cur][n4][1]);
                    mma_f16(acc[mi][2 * n4 + 1], ah[cur][mi], bf[cur][n4][2], bf[cur][n4][3]);
                }
            if (two) {
#pragma unroll
                for (int n4 = 0; n4 < 4; ++n4)
#pragma unroll
                    for (int mi = 0; mi < 2; ++mi) {
                        mma_f16(acc[mi][2 * n4],     al[cur][mi], bf[cur][n4][0], bf[cur][n4][1]);
                        mma_f16(acc[mi][2 * n4 + 1], al[cur][mi], bf[cur][n4][2], bf[cur][n4][3]);
                    }
            }
        }
        if (++stage_c >= 3) stage_c -= 3;
    }

    const int rbase = row0 + wm * 32 + (lane >> 2);
    const int cbase = cofs + wn * 64 + (lane & 3) * 2;
#pragma unroll
    for (int mi = 0; mi < 2; ++mi) {
#pragma unroll
        for (int nt = 0; nt < 8; ++nt) {
            int r = rbase + mi * 16;
            int cc = cbase + nt * 8;
            *reinterpret_cast<float2*>(dst + r * ldc + cc) =
                make_float2(acc[mi][nt][0], acc[mi][nt][1]);
            *reinterpret_cast<float2*>(dst + (r + 8) * ldc + cc) =
                make_float2(acc[mi][nt][2], acc[mi][nt][3]);
        }
    }
}

// ============================================================
// RoPE + fp16 convert fused: q/k/v all single fp16.
// ============================================================
__global__ void rope_split(const int* __restrict__ seg)
{
    __shared__ float s_ts[64];
    const int t = blockIdx.x;
    const int tid = threadIdx.x;
    if (tid < 64) {
        double f = (double)tid / 64.0;
        s_ts[tid] = (float)pow(10000.0, f);
    }
    __syncthreads();
    const float pos = (float)seg[t];
    for (int idx = tid; idx < (NQH + NKH) * 64; idx += 256) {
        int head = idx >> 6;
        int i = idx & 63;
        float ang = pos / s_ts[i];
        float sv, cv;
        sincosf(ang, &sv, &cv);
        if (head < NQH) {
            int off = t * (NQH * HD) + head * HD;
            const float* base = g_q + off;
            float x1 = base[i], x2 = base[i + 64];
            float o1 = (x1 * cv - x2 * sv) * QSCALE;
            float o2 = (x2 * cv + x1 * sv) * QSCALE;
            __half h1 = __float2half_rn(o1);
            __half h2 = __float2half_rn(o2);
            gq16[off + i]      = reinterpret_cast<u16&>(h1);
            gq16[off + i + 64] = reinterpret_cast<u16&>(h2);
        } else {
            int off = t * (NKH * HD) + (head - NQH) * HD;
            const float* base = g_k + off;
            float x1 = base[i], x2 = base[i + 64];
            float o1 = x1 * cv - x2 * sv;
            float o2 = x2 * cv + x1 * sv;
            __half h1 = __float2half_rn(o1);
            __half h2 = __float2half_rn(o2);
            gk16[off + i]      = reinterpret_cast<u16&>(h1);
            gk16[off + i + 64] = reinterpret_cast<u16&>(h2);
        }
    }
    {
        int off = t * (NKH * HD) + tid * 4;
        float4 v = *reinterpret_cast<const float4*>(g_v + off);
        __half v0 = __float2half_rn(v.x), v1 = __float2half_rn(v.y);
        __half v2 = __float2half_rn(v.z), v3 = __float2half_rn(v.w);
        ull pk = (ull)reinterpret_cast<u16&>(v0) | ((ull)reinterpret_cast<u16&>(v1) << 16)
               | ((ull)reinterpret_cast<u16&>(v2) << 32) | ((ull)reinterpret_cast<u16&>(v3) << 48);
        *reinterpret_cast<ull*>(gv16 + off) = pk;
    }
}

// ============================================================
// Attention: Q/K/V/P all single fp16 (P uncompensated).
// K/V double-buffered; epilogue writes enc split directly.
// SMEM: Q 32K | KV[2] 2x32K | S 34K | P 16K | al/l
// ============================================================
#define SMEM_Q   0
#define SMEM_KV  32768
#define SMEM_S   98304
#define SMEM_P   133120
#define SMEM_AL  149504
#define SMEM_L   150016
#define ATT2_SMEM 150528

__device__ __forceinline__ void attn_load_kv(u32 sb, int p, int tid, int st, int kh)
{
    u32 kvb = sb + SMEM_KV + (u32)p * 32768;
#pragma unroll
    for (int l = 0; l < 4; ++l) {
        int idx = tid + l * 256;
        int r = idx >> 4, ch = idx & 15;
        size_t go = (size_t)((st + r) * NKH + kh) * HD + ch * 8;
        u32 dk = (u32)((ch >> 3) * 8192 + r * 128 + (((ch & 7) * 16) ^ ((r & 7) << 4)));
        u32 dv = (u32)(r * 256 + ((ch * 16) ^ ((r & 7) << 4)));
        cp16(kvb + dk,         gk16 + go);
        cp16(kvb + 16384 + dv, gv16 + go);
    }
}

__global__ __launch_bounds__(256, 1) void attn_mma()
{
    extern __shared__ char smc[];
    const u32 sb = smem_u32(smc);
    float* S = reinterpret_cast<float*>(smc + SMEM_S);
    float* al_s = reinterpret_cast<float*>(smc + SMEM_AL);
    float* l_s = reinterpret_cast<float*>(smc + SMEM_L);

    const int tid = threadIdx.x;
    const int lane = tid & 31;
    const int w = tid >> 5;
    const int wm = w & 3;
    const int wn = w >> 2;
    const int kh = blockIdx.x;
    const int t0 = (int)(31 - blockIdx.y) * 64;

    // ---- Q tile load (single fp16) ----
#pragma unroll
    for (int l = 0; l < 8; ++l) {
        int idx = tid + l * 256;
        int r = idx >> 4, ch = idx & 15;
        int t = t0 + (r & 63), n = kh * 2 + (r >> 6);
        u32 d = (u32)((ch >> 3) * 16384 + r * 128 + (((ch & 7) * 16) ^ ((r & 7) << 4)));
        cp16(sb + SMEM_Q + d, gq16 + (size_t)(t * NQH + n) * HD + ch * 8);
    }
    CP_COMMIT();

    float acc_o[2][8][4];
#pragma unroll
    for (int i = 0; i < 2; ++i)
#pragma unroll
        for (int j = 0; j < 8; ++j)
#pragma unroll
            for (int q = 0; q < 4; ++q) acc_o[i][j][q] = 0.0f;

    float m_reg = -1e30f, l_reg = 0.0f;

    const u32 aRow = (u32)((wm * 32 + (lane & 15)) * 128);
    const u32 aK   = (u32)((lane >> 4) * 16);
    const u32 aXor = (u32)((lane & 7) << 4);
    const u32 bK   = (u32)(((lane >> 3) & 1) * 16);
    u32 bRow[2];
    bRow[0] = (u32)((wn * 32 + ((lane >> 4) << 3) + (lane & 7)) * 128);
    bRow[1] = bRow[0] + 16 * 128;
    const int vrow_in = (lane & 7) + (lane & 8);
    const u32 vh8 = (u32)((lane >> 4) << 3);

    const int s_begin = (t0 >= (WINDOW - 1)) ? ((t0 - (WINDOW - 1)) & ~63) : 0;
    const int ntile = (t0 - s_begin) / 64 + 1;

    attn_load_kv(sb, 0, tid, s_begin, kh);
    CP_COMMIT();

    for (int it = 0; it < ntile; ++it) {
        const int st = s_begin + it * 64;
        const int p = it & 1;
        if (it + 1 < ntile) {
            attn_load_kv(sb, p ^ 1, tid, st + 64, kh);
            CP_COMMIT();
            CP_WAIT(1);
        } else {
            CP_WAIT(0);
        }
        __syncthreads();
        const u32 kvb = sb + SMEM_KV + (u32)p * 32768;

        // ---- S = Q K^T (single fp16) ----
        float s_acc[2][4][4];
#pragma unroll
        for (int i = 0; i < 2; ++i)
#pragma unroll
            for (int j = 0; j < 4; ++j)
#pragma unroll
                for (int q = 0; q < 4; ++q) s_acc[i][j][q] = 0.0f;

#pragma unroll
        for (int kk = 0; kk < 8; ++kk) {
            const int ks = (kk + w) & 7;
            const u32 kc = (u32)(ks >> 2);
            const u32 kb = (u32)((ks & 3) * 32);
            u32 qh[2][4];
#pragma unroll
            for (int mi = 0; mi < 2; ++mi) {
                u32 ao = kc * 16384 + aRow + (u32)(mi * 2048) + ((aK + kb) ^ aXor);
                ldsm4(qh[mi], sb + SMEM_Q + ao);
            }
            u32 kf[2][4];
#pragma unroll
            for (int g = 0; g < 2; ++g) {
                u32 bo = kc * 8192 + bRow[g] + ((bK + kb) ^ aXor);
                ldsm4(kf[g], kvb + bo);
            }
#pragma unroll
            for (int g = 0; g < 2; ++g)
#pragma unroll
                for (int mi = 0; mi < 2; ++mi) {
                    mma_f16(s_acc[mi][2 * g],     qh[mi], kf[g][0], kf[g][1]);
                    mma_f16(s_acc[mi][2 * g + 1], qh[mi], kf[g][2], kf[g][3]);
                }
        }

        // ---- softcap + mask, store S ----
#pragma unroll
        for (int mi = 0; mi < 2; ++mi) {
            int r0 = wm * 32 + mi * 16 + (lane >> 2);
#pragma unroll
            for (int n8 = 0; n8 < 4; ++n8) {
                int sl0 = wn * 32 + n8 * 8 + (lane & 3) * 2;
#pragma unroll
                for (int half = 0; half < 2; ++half) {
                    int rr = r0 + half * 8;
                    int t = t0 + (rr & 63);
                    float v0 = tanh_fast(s_acc[mi][n8][half * 2]     * (1.0f / SOFTCAP)) * SOFTCAP;
                    float v1 = tanh_fast(s_acc[mi][n8][half * 2 + 1] * (1.0f / SOFTCAP)) * SOFTCAP;
                    int sg0 = st + sl0, sg1 = sg0 + 1;
                    bool ok0 = (sg0 <= t) && (sg0 > t - WINDOW);
                    bool ok1 = (sg1 <= t) && (sg1 > t - WINDOW);
                    *reinterpret_cast<float2*>(&S[rr * 68 + sl0]) =
                        make_float2(ok0 ? v0 : -1e30f, ok1 ? v1 : -1e30f);
                }
            }
        }
        __syncthreads();

        // ---- online softmax: 2 threads per row, P single fp16 ----
        {
            const int row = tid >> 1;
            const int half = tid & 1;
            const int cb = half * 32;
            float tm = -1e30f;
#pragma unroll 8
            for (int c = 0; c < 32; ++c) tm = fmaxf(tm, S[row * 68 + cb + c]);
            tm = fmaxf(tm, __shfl_xor_sync(0xffffffffu, tm, 1));
            float mnew = fmaxf(m_reg, tm);
            float a = __expf(m_reg - mnew);
            float lsum = 0.0f;
            char* ph = smc + SMEM_P + row * 128;
            const u32 xr = (u32)((row & 7) << 4);
#pragma unroll 8
            for (int c = 0; c < 32; ++c) {
                float p = __expf(S[row * 68 + cb + c] - mnew);
                lsum += p;
                __half hp = __float2half_rn(p);
                u32 off = ((u32)((cb + c) * 2)) ^ xr;
                *reinterpret_cast<u16*>(ph + off) = reinterpret_cast<u16&>(hp);
            }
            lsum += __shfl_xor_sync(0xffffffffu, lsum, 1);
            l_reg = l_reg * a + lsum;
            m_reg = mnew;
            if (half == 0) al_s[row] = a;
        }
        __syncthreads();

        // ---- rescale O, then O += P V (single fp16) ----
#pragma unroll
        for (int mi = 0; mi < 2; ++mi) {
            int r0 = wm * 32 + mi * 16 + (lane >> 2);
            float a0 = al_s[r0], a1 = al_s[r0 + 8];
#pragma unroll
            for (int n8 = 0; n8 < 8; ++n8) {
                acc_o[mi][n8][0] *= a0; acc_o[mi][n8][1] *= a0;
                acc_o[mi][n8][2] *= a1; acc_o[mi][n8][3] *= a1;
            }
        }
#pragma unroll
        for (int kk = 0; kk < 4; ++kk) {
            const int ks = (kk + (w & 3)) & 3;
            const u32 kb = (u32)(ks * 32);
            u32 ph[2][4];
#pragma unroll
            for (int mi = 0; mi < 2; ++mi) {
                u32 ao = aRow + (u32)(mi * 2048) + ((aK + kb) ^ aXor);
                ldsm4(ph[mi], sb + SMEM_P + ao);
            }
            const int vrow = ks * 16 + vrow_in;
            const u32 vswz = (u32)(vrow * 256);
            const u32 vxr = (u32)((vrow & 7) << 4);
#pragma unroll
            for (int pg = 0; pg < 2; ++pg) {
                u32 vhf[2][4];
#pragma unroll
                for (int j = 0; j < 2; ++j) {
                    int pair = pg * 2 + j;
                    u32 hq = (u32)(wn * 64 + pair * 16) + vh8;
                    u32 va = kvb + 16384 + vswz + (((hq >> 3) * 16) ^ vxr);
                    ldsm4t(vhf[j], va);
                }
#pragma unroll
                for (int j = 0; j < 2; ++j) {
                    int pair = pg * 2 + j;
#pragma unroll
                    for (int mi = 0; mi < 2; ++mi) {
                        mma_f16(acc_o[mi][pair * 2],     ph[mi], vhf[j][0], vhf[j][1]);
                        mma_f16(acc_o[mi][pair * 2 + 1], ph[mi], vhf[j][2], vhf[j][3]);
                    }
                }
            }
        }
        __syncthreads();
    }

    if ((tid & 1) == 0) l_s[tid >> 1] = l_reg;
    __syncthreads();

    // ---- finalize: O/l -> enc split fp16 directly ----
#pragma unroll
    for (int mi = 0; mi < 2; ++mi) {
        int r0 = wm * 32 + mi * 16 + (lane >> 2);
        float i0 = 1.0f / l_s[r0];
        float i1 = 1.0f / l_s[r0 + 8];
#pragma unroll
        for (int n8 = 0; n8 < 8; ++n8) {
            int h = wn * 64 + n8 * 8 + (lane & 3) * 2;
#pragma unroll
            for (int half = 0; half < 2; ++half) {
                int rr = r0 + half * 8;
                int t = t0 + (rr & 63);
                int n = kh * 2 + (rr >> 6);
                float iv = half ? i1 : i0;
                float o0 = acc_o[mi][n8][half * 2] * iv;
                float o1 = acc_o[mi][n8][half * 2 + 1] * iv;
                u16 h0, l0, h1, l1;
                split_fp16(o0, h0, l0);
                split_fp16(o1, h1, l1);
                size_t idx = (size_t)(t * NQH + n) * HD + h;
                *reinterpret_cast<u32*>(ge_h + idx) = (u32)h0 | ((u32)h1 << 16);
                *reinterpret_cast<u32*>(ge_l + idx) = (u32)l0 | ((u32)l1 << 16);
            }
        }
    }
}

// ============================================================
extern "C" void kernel_launch(void* const* d_in, const int* in_sizes, int n_in,
                              void* d_out, int out_size)
{
    (void)in_sizes; (void)n_in; (void)out_size;
    const float* x   = (const float*)d_in[0];
    const int*   seg = (const int*)d_in[1];
    const float* qw  = (const float*)d_in[3];
    const float* kvw = (const float*)d_in[4];
    const float* ow  = (const float*)d_in[5];
    float* out = (float*)d_out;

    cudaFuncSetAttribute(hmma_gemm, cudaFuncAttributeMaxDynamicSharedMemorySize, GEMM_SMEM);
    cudaFuncSetAttribute(attn_mma, cudaFuncAttributeMaxDynamicSharedMemorySize, ATT2_SMEM);

    convert_x<<<4096, 256>>>(x);
    wconv<<<dim3(128, 64), 256>>>(qw, kvw, ow, 0);
    wconv<<<dim3(64, 64), 256>>>(qw, kvw, ow, 1);
    hmma_gemm<<<dim3(32, 16), 256, GEMM_SMEM>>>(nullptr, 0, 1);   // qkv (1-term)
    rope_split<<<T_DIM, 256>>>(seg);
    attn_mma<<<dim3(NKH, 32), 256, ATT2_SMEM>>>();
    hmma_gemm<<<dim3(16, 16), 256, GEMM_SMEM>>>(out, D_DIM, 0);   // out proj (2-term)
}

// round 17
// speedup vs baseline: 5.2002x; 1.0992x over previous
#include <cuda_runtime.h>
#include <cuda_bf16.h>
#include <cuda_fp16.h>
#include <math.h>

typedef unsigned long long ull;
typedef unsigned int u32;
typedef unsigned short u16;

#define T_DIM 2048
#define D_DIM 2048
#define NQH 16
#define NKH 8
#define HD 128
#define WINDOW 1024
#define SOFTCAP 50.0f
#define QSCALE 0.08838834764831845f
#define QELEMS (T_DIM * NQH * HD)
#define KVELEMS (T_DIM * NKH * HD)

// fp32 scratch
__device__ float g_q[QELEMS];
__device__ float g_k[KVELEMS];
__device__ float g_v[KVELEMS];

// projection operands
__device__ u16 gx16[T_DIM * D_DIM];
__device__ u16 ge_h[T_DIM * D_DIM], ge_l[T_DIM * D_DIM];
__device__ u16 gw[4096 * D_DIM];
__device__ u16 gwo[D_DIM * D_DIM];
// attention operands: q/k/v single fp16
__device__ u16 gq16[QELEMS];
__device__ u16 gk16[KVELEMS];
__device__ u16 gv16[KVELEMS];

__device__ __forceinline__ u32 smem_u32(const void* p) {
    u32 a; asm("{ .reg .u64 t; cvta.to.shared.u64 t, %1; cvt.u32.u64 %0, t; }" : "=r"(a) : "l"(p));
    return a;
}
__device__ __forceinline__ void ldsm4(u32* r, u32 addr) {
    asm volatile("ldmatrix.sync.aligned.m8n8.x4.shared.b16 {%0,%1,%2,%3}, [%4];"
        : "=r"(r[0]), "=r"(r[1]), "=r"(r[2]), "=r"(r[3]) : "r"(addr));
}
__device__ __forceinline__ void ldsm4t(u32* r, u32 addr) {
    asm volatile("ldmatrix.sync.aligned.m8n8.x4.trans.shared.b16 {%0,%1,%2,%3}, [%4];"
        : "=r"(r[0]), "=r"(r[1]), "=r"(r[2]), "=r"(r[3]) : "r"(addr));
}
__device__ __forceinline__ void mma_f16(float* c, const u32* a, u32 b0, u32 b1) {
    asm volatile("mma.sync.aligned.m16n8k16.row.col.f32.f16.f16.f32 "
        "{%0,%1,%2,%3}, {%4,%5,%6,%7}, {%8,%9}, {%0,%1,%2,%3};"
        : "+f"(c[0]), "+f"(c[1]), "+f"(c[2]), "+f"(c[3])
        : "r"(a[0]), "r"(a[1]), "r"(a[2]), "r"(a[3]), "r"(b0), "r"(b1));
}
__device__ __forceinline__ void cp16(u32 dst, const void* src) {
    asm volatile("cp.async.cg.shared.global [%0], [%1], 16;" :: "r"(dst), "l"(src));
}
#define CP_COMMIT() asm volatile("cp.async.commit_group;" ::: "memory")
#define CP_WAIT(n)  asm volatile("cp.async.wait_group %0;" :: "n"(n) : "memory")

__device__ __forceinline__ void split_fp16(float v, u16& h, u16& l) {
    __half hh = __float2half_rn(v);
    float r = v - __half2float(hh);
    __half ll = __float2half_rn(r);
    h = reinterpret_cast<u16&>(hh);
    l = reinterpret_cast<u16&>(ll);
}
__device__ __forceinline__ float tanh_fast(float x) {
    float c = fminf(fmaxf(x, -12.0f), 12.0f);
    float e = __expf(2.0f * c);
    return (e - 1.0f) / (e + 1.0f);
}
__device__ __forceinline__ u32 pkh2(float a, float b) {
    __half2 h = __floats2half2_rn(a, b);
    return *reinterpret_cast<u32*>(&h);
}

// ============================================================
// x -> single fp16
// ============================================================
__global__ void convert_x(const float* __restrict__ src)
{
    int i = (blockIdx.x * 256 + threadIdx.x) * 4;
    float4 v = *reinterpret_cast<const float4*>(src + i);
    __half h0 = __float2half_rn(v.x), h1 = __float2half_rn(v.y);
    __half h2 = __float2half_rn(v.z), h3 = __float2half_rn(v.w);
    ull pk = (ull)reinterpret_cast<u16&>(h0) | ((ull)reinterpret_cast<u16&>(h1) << 16)
           | ((ull)reinterpret_cast<u16&>(h2) << 32) | ((ull)reinterpret_cast<u16&>(h3) << 48);
    *reinterpret_cast<ull*>(gx16 + i) = pk;
}

// ============================================================
// Weight transpose + fp16 convert, 32x32 tiles.
// ============================================================
__global__ void wconv(const float* __restrict__ qw, const float* __restrict__ kvw,
                      const float* __restrict__ ow, int mode)
{
    __shared__ float s[32][33];
    const int c0 = blockIdx.x * 32;
    const int k0 = blockIdx.y * 32;
    const int tx = threadIdx.x & 31;
    const int ty = threadIdx.x >> 5;
    u16* __restrict__ dh = mode ? gwo : gw;

#pragma unroll
    for (int rr = ty; rr < 32; rr += 8) {
        int k = k0 + rr;
        int c = c0 + tx;
        float v;
        if (mode == 0) {
            const float* base;
            int cc = c;
            if (cc < 2048)      base = qw + (cc >> 7) * (D_DIM * HD);
            else if (cc < 3072) { cc -= 2048; base = kvw + (cc >> 7) * (D_DIM * HD); }
            else                { cc -= 3072; base = kvw + (8 + (cc >> 7)) * (D_DIM * HD); }
            v = base[k * HD + (cc & 127)];
        } else {
            v = ow[k * D_DIM + c];
        }
        s[tx][rr] = v;
    }
    __syncthreads();
#pragma unroll
    for (int rr = ty; rr < 32; rr += 8) {
        __half hv = __float2half_rn(s[rr][tx]);
        dh[(c0 + rr) * D_DIM + k0 + tx] = reinterpret_cast<u16&>(hv);
    }
}

// ============================================================
// HMMA GEMM: fp16, runtime 1- or 2-term A (R14-verified).
// ============================================================
#define STAGE_BYTES 49152
#define GEMM_SMEM (3 * STAGE_BYTES)

__device__ __forceinline__ void load_stage256(
    u32 sbase, int p, int tid, int row0, int col0, int kk,
    const u16* __restrict__ Ah, const u16* __restrict__ Al,
    const u16* __restrict__ B, int two)
{
    u32 stg = sbase + (u32)p * STAGE_BYTES;
#pragma unroll
    for (int l = 0; l < 4; ++l) {
        int idx = tid + l * 256;
        int r = idx >> 3;
        int ch = idx & 7;
        u32 doff = (u32)(r * 128) + (u32)((ch * 16) ^ ((r & 7) << 4));
        int aoff = (row0 + r) * D_DIM + kk + ch * 8;
        int boff = (col0 + r) * D_DIM + kk + ch * 8;
        cp16(stg + doff,             Ah + aoff);
        if (two) cp16(stg + 16384 + doff, Al + aoff);
        cp16(stg + 32768 + doff,     B + boff);
    }
}

__device__ __forceinline__ void gemm_frags(
    u32 stg, u32 aRow, u32 aK, u32 aXor, u32 bRow, u32 bK, u32 kb,
    u32 ah[2][4], u32 al[2][4], u32 bf[4][4], int two)
{
#pragma unroll
    for (int mi = 0; mi < 2; ++mi) {
        u32 ao = aRow + (u32)(mi * 2048) + ((aK + kb) ^ aXor);
        ldsm4(ah[mi], stg + ao);
        if (two) ldsm4(al[mi], stg + 16384 + ao);
    }
#pragma unroll
    for (int n4 = 0; n4 < 4; ++n4) {
        u32 bo = bRow + (u32)(n4 * 2048) + ((bK + kb) ^ aXor);
        ldsm4(bf[n4], stg + 32768 + bo);
    }
}

__global__ __launch_bounds__(256, 1)
void hmma_gemm(float* __restrict__ dst0, int ldc0, int qkv_mode)
{
    extern __shared__ char smem[];
    const u32 sb = smem_u32(smem);
    const int tid = threadIdx.x;
    const int lane = tid & 31;
    const int w = tid >> 5;
    const int wm = w & 3;
    const int wn = w >> 2;
    const int row0 = blockIdx.y * 128;
    const int col0 = blockIdx.x * 128;
    const int two = qkv_mode ? 0 : 1;

    const u16 *Ah, *Al, *B;
    float* dst; int ldc, cofs;
    if (qkv_mode) {
        Ah = gx16; Al = gx16; B = gw;
        if (col0 < 2048)      { dst = g_q; ldc = 2048; cofs = col0; }
        else if (col0 < 3072) { dst = g_k; ldc = 1024; cofs = col0 - 2048; }
        else                  { dst = g_v; ldc = 1024; cofs = col0 - 3072; }
    } else {
        Ah = ge_h; Al = ge_l; B = gwo;
        dst = dst0; ldc = ldc0; cofs = col0;
    }

    float acc[2][8][4];
#pragma unroll
    for (int i = 0; i < 2; ++i)
#pragma unroll
        for (int j = 0; j < 8; ++j)
#pragma unroll
            for (int q = 0; q < 4; ++q) acc[i][j][q] = 0.0f;

    const u32 aRow = (u32)(wm * 32 + (lane & 15)) * 128;
    const u32 aXor = (u32)((lane & 7) << 4);
    const u32 aK   = (u32)((lane >> 4) * 16);
    const u32 bRow = (u32)(wn * 64 + ((lane >> 4) << 3) + (lane & 7)) * 128;
    const u32 bK   = (u32)(((lane >> 3) & 1) * 16);

    u32 ah[2][2][4], al[2][2][4], bf[2][4][4];

    load_stage256(sb, 0, tid, row0, col0, 0, Ah, Al, B, two);
    CP_COMMIT();
    load_stage256(sb, 1, tid, row0, col0, 64, Ah, Al, B, two);
    CP_COMMIT();

    int stage_c = 0;
    for (int c = 0; c < 32; ++c) {
        if (c < 31) { CP_WAIT(1); } else { CP_WAIT(0); }
        __syncthreads();
        if (c + 2 < 32) {
            int sn = stage_c + 2; if (sn >= 3) sn -= 3;
            load_stage256(sb, sn, tid, row0, col0, (c + 2) * 64, Ah, Al, B, two);
            CP_COMMIT();
        }

        const u32 stg = sb + (u32)stage_c * STAGE_BYTES;
        gemm_frags(stg, aRow, aK, aXor, bRow, bK, 0, ah[0], al[0], bf[0], two);
#pragma unroll
        for (int ks = 0; ks < 4; ++ks) {
            const int cur = ks & 1;
            if (ks < 3) {
                gemm_frags(stg, aRow, aK, aXor, bRow, bK, (u32)((ks + 1) * 32),
                           ah[cur ^ 1], al[cur ^ 1], bf[cur ^ 1], two);
            }
#pragma unroll
            for (int n4 = 0; n4 < 4; ++n4)
#pragma unroll
                for (int mi = 0; mi < 2; ++mi) {
                    mma_f16(acc[mi][2 * n4],     ah[cur][mi], bf[cur][n4][0], bf[cur][n4][1]);
                    mma_f16(acc[mi][2 * n4 + 1], ah[cur][mi], bf[cur][n4][2], bf[cur][n4][3]);
                }
            if (two) {
#pragma unroll
                for (int n4 = 0; n4 < 4; ++n4)
#pragma unroll
                    for (int mi = 0; mi < 2; ++mi) {
                        mma_f16(acc[mi][2 * n4],     al[cur][mi], bf[cur][n4][0], bf[cur][n4][1]);
                        mma_f16(acc[mi][2 * n4 + 1], al[cur][mi], bf[cur][n4][2], bf[cur][n4][3]);
                    }
            }
        }
        if (++stage_c >= 3) stage_c -= 3;
    }

    const int rbase = row0 + wm * 32 + (lane >> 2);
    const int cbase = cofs + wn * 64 + (lane & 3) * 2;
#pragma unroll
    for (int mi = 0; mi < 2; ++mi) {
#pragma unroll
        for (int nt = 0; nt < 8; ++nt) {
            int r = rbase + mi * 16;
            int cc = cbase + nt * 8;
            *reinterpret_cast<float2*>(dst + r * ldc + cc) =
                make_float2(acc[mi][nt][0], acc[mi][nt][1]);
            *reinterpret_cast<float2*>(dst + (r + 8) * ldc + cc) =
                make_float2(acc[mi][nt][2], acc[mi][nt][3]);
        }
    }
}

// ============================================================
// RoPE + fp16 convert fused.
// ============================================================
__global__ void rope_split(const int* __restrict__ seg)
{
    __shared__ float s_ts[64];
    const int t = blockIdx.x;
    const int tid = threadIdx.x;
    if (tid < 64) {
        double f = (double)tid / 64.0;
        s_ts[tid] = (float)pow(10000.0, f);
    }
    __syncthreads();
    const float pos = (float)seg[t];
    for (int idx = tid; idx < (NQH + NKH) * 64; idx += 256) {
        int head = idx >> 6;
        int i = idx & 63;
        float ang = pos / s_ts[i];
        float sv, cv;
        sincosf(ang, &sv, &cv);
        if (head < NQH) {
            int off = t * (NQH * HD) + head * HD;
            const float* base = g_q + off;
            float x1 = base[i], x2 = base[i + 64];
            float o1 = (x1 * cv - x2 * sv) * QSCALE;
            float o2 = (x2 * cv + x1 * sv) * QSCALE;
            __half h1 = __float2half_rn(o1);
            __half h2 = __float2half_rn(o2);
            gq16[off + i]      = reinterpret_cast<u16&>(h1);
            gq16[off + i + 64] = reinterpret_cast<u16&>(h2);
        } else {
            int off = t * (NKH * HD) + (head - NQH) * HD;
            const float* base = g_k + off;
            float x1 = base[i], x2 = base[i + 64];
            float o1 = x1 * cv - x2 * sv;
            float o2 = x2 * cv + x1 * sv;
            __half h1 = __float2half_rn(o1);
            __half h2 = __float2half_rn(o2);
            gk16[off + i]      = reinterpret_cast<u16&>(h1);
            gk16[off + i + 64] = reinterpret_cast<u16&>(h2);
        }
    }
    {
        int off = t * (NKH * HD) + tid * 4;
        float4 v = *reinterpret_cast<const float4*>(g_v + off);
        __half v0 = __float2half_rn(v.x), v1 = __float2half_rn(v.y);
        __half v2 = __float2half_rn(v.z), v3 = __float2half_rn(v.w);
        ull pk = (ull)reinterpret_cast<u16&>(v0) | ((ull)reinterpret_cast<u16&>(v1) << 16)
               | ((ull)reinterpret_cast<u16&>(v2) << 32) | ((ull)reinterpret_cast<u16&>(v3) << 48);
        *reinterpret_cast<ull*>(gv16 + off) = pk;
    }
}

// ============================================================
// Register-resident flash attention.
// Warp w owns rows w*16..w*16+15, full 64-key span.
// Softmax + P entirely in registers (C-frag == A-frag layout).
// SMEM: Q 32K | KV[2] 2x32K
// ============================================================
#define SMEM_Q   0
#define SMEM_KV  32768
#define ATT2_SMEM 98304

__device__ __forceinline__ void attn_load_kv(u32 sb, int p, int tid, int st, int kh)
{
    u32 kvb = sb + SMEM_KV + (u32)p * 32768;
#pragma unroll
    for (int l = 0; l < 4; ++l) {
        int idx = tid + l * 256;
        int r = idx >> 4, ch = idx & 15;
        size_t go = (size_t)((st + r) * NKH + kh) * HD + ch * 8;
        u32 dk = (u32)((ch >> 3) * 8192 + r * 128 + (((ch & 7) * 16) ^ ((r & 7) << 4)));
        u32 dv = (u32)(r * 256 + ((ch * 16) ^ ((r & 7) << 4)));
        cp16(kvb + dk,         gk16 + go);
        cp16(kvb + 16384 + dv, gv16 + go);
    }
}

__global__ __launch_bounds__(256, 1) void attn_mma()
{
    extern __shared__ char smc[];
    const u32 sb = smem_u32(smc);

    const int tid = threadIdx.x;
    const int lane = tid & 31;
    const int w = tid >> 5;
    const int kh = blockIdx.x;
    const int t0 = (int)(31 - blockIdx.y) * 64;

    // ---- Q tile load (128 rows cooperative) ----
#pragma unroll
    for (int l = 0; l < 8; ++l) {
        int idx = tid + l * 256;
        int r = idx >> 4, ch = idx & 15;
        int t = t0 + (r & 63), n = kh * 2 + (r >> 6);
        u32 d = (u32)((ch >> 3) * 16384 + r * 128 + (((ch & 7) * 16) ^ ((r & 7) << 4)));
        cp16(sb + SMEM_Q + d, gq16 + (size_t)(t * NQH + n) * HD + ch * 8);
    }
    CP_COMMIT();

    float acc_o[16][4];
#pragma unroll
    for (int j = 0; j < 16; ++j)
#pragma unroll
        for (int q = 0; q < 4; ++q) acc_o[j][q] = 0.0f;

    float m0 = -1e30f, m1 = -1e30f, l0 = 0.0f, l1 = 0.0f;

    const int gr = lane >> 2;
    // rows this thread owns
    const int rr0 = w * 16 + gr;         // 0..127
    const int rr1 = rr0 + 8;
    const int trow0 = t0 + (rr0 & 63);
    const int trow1 = t0 + (rr1 & 63);

    const u32 aRow = (u32)((w * 16 + (lane & 15)) * 128);
    const u32 aK   = (u32)((lane >> 4) * 16);
    const u32 aXor = (u32)((lane & 7) << 4);
    const u32 bK   = (u32)(((lane >> 3) & 1) * 16);
    const u32 kRow = (u32)((((lane >> 4) << 3) + (lane & 7)) * 128);
    const int vrow_in = (lane & 7) + (lane & 8);
    const u32 vh8 = (u32)((lane >> 4) << 3);

    const int s_begin = (t0 >= (WINDOW - 1)) ? ((t0 - (WINDOW - 1)) & ~63) : 0;
    const int ntile = (t0 - s_begin) / 64 + 1;

    attn_load_kv(sb, 0, tid, s_begin, kh);
    CP_COMMIT();

    for (int it = 0; it < ntile; ++it) {
        const int st = s_begin + it * 64;
        const int p = it & 1;
        if (it + 1 < ntile) {
            attn_load_kv(sb, p ^ 1, tid, st + 64, kh);
            CP_COMMIT();
            CP_WAIT(1);
        } else {
            CP_WAIT(0);
        }
        __syncthreads();
        const u32 kvb = sb + SMEM_KV + (u32)p * 32768;

        // ---- S = Q K^T : 8 n8-tiles covering all 64 keys ----
        float s_acc[8][4];
#pragma unroll
        for (int j = 0; j < 8; ++j)
#pragma unroll
            for (int q = 0; q < 4; ++q) s_acc[j][q] = 0.0f;

#pragma unroll
        for (int kk = 0; kk < 8; ++kk) {
            const int ks = (kk + w) & 7;
            const u32 kc = (u32)(ks >> 2);
            const u32 kb = (u32)((ks & 3) * 32);
            u32 qf[4];
            ldsm4(qf, sb + SMEM_Q + kc * 16384 + aRow + ((aK + kb) ^ aXor));
#pragma unroll
            for (int g = 0; g < 4; ++g) {
                u32 kf[4];
                ldsm4(kf, kvb + kc * 8192 + (u32)(g * 16 * 128) + kRow + ((bK + kb) ^ aXor));
                mma_f16(s_acc[2 * g],     qf, kf[0], kf[1]);
                mma_f16(s_acc[2 * g + 1], qf, kf[2], kf[3]);
            }
        }

        // ---- softcap + mask in registers ----
#pragma unroll
        for (int t8 = 0; t8 < 8; ++t8) {
            int c0 = st + t8 * 8 + (lane & 3) * 2;
            float v0 = tanh_fast(s_acc[t8][0] * (1.0f / SOFTCAP)) * SOFTCAP;
            float v1 = tanh_fast(s_acc[t8][1] * (1.0f / SOFTCAP)) * SOFTCAP;
            float v2 = tanh_fast(s_acc[t8][2] * (1.0f / SOFTCAP)) * SOFTCAP;
            float v3 = tanh_fast(s_acc[t8][3] * (1.0f / SOFTCAP)) * SOFTCAP;
            s_acc[t8][0] = (c0     <= trow0 && c0     > trow0 - WINDOW) ? v0 : -1e30f;
            s_acc[t8][1] = (c0 + 1 <= trow0 && c0 + 1 > trow0 - WINDOW) ? v1 : -1e30f;
            s_acc[t8][2] = (c0     <= trow1 && c0     > trow1 - WINDOW) ? v2 : -1e30f;
            s_acc[t8][3] = (c0 + 1 <= trow1 && c0 + 1 > trow1 - WINDOW) ? v3 : -1e30f;
        }

        // ---- register softmax (quad shuffle reduce) ----
        float mx0 = -1e30f, mx1 = -1e30f;
#pragma unroll
        for (int t8 = 0; t8 < 8; ++t8) {
            mx0 = fmaxf(mx0, fmaxf(s_acc[t8][0], s_acc[t8][1]));
            mx1 = fmaxf(mx1, fmaxf(s_acc[t8][2], s_acc[t8][3]));
        }
        mx0 = fmaxf(mx0, __shfl_xor_sync(0xffffffffu, mx0, 1));
        mx0 = fmaxf(mx0, __shfl_xor_sync(0xffffffffu, mx0, 2));
        mx1 = fmaxf(mx1, __shfl_xor_sync(0xffffffffu, mx1, 1));
        mx1 = fmaxf(mx1, __shfl_xor_sync(0xffffffffu, mx1, 2));

        float mn0 = fmaxf(m0, mx0);
        float mn1 = fmaxf(m1, mx1);
        float a0 = __expf(m0 - mn0);
        float a1 = __expf(m1 - mn1);

        u32 pa[4][4];
        float ls0 = 0.0f, ls1 = 0.0f;
#pragma unroll
        for (int j = 0; j < 4; ++j) {
            float p00 = __expf(s_acc[2 * j][0] - mn0);
            float p01 = __expf(s_acc[2 * j][1] - mn0);
            float p02 = __expf(s_acc[2 * j][2] - mn1);
            float p03 = __expf(s_acc[2 * j][3] - mn1);
            float p10 = __expf(s_acc[2 * j + 1][0] - mn0);
            float p11 = __expf(s_acc[2 * j + 1][1] - mn0);
            float p12 = __expf(s_acc[2 * j + 1][2] - mn1);
            float p13 = __expf(s_acc[2 * j + 1][3] - mn1);
            ls0 += p00 + p01 + p10 + p11;
            ls1 += p02 + p03 + p12 + p13;
            pa[j][0] = pkh2(p00, p01);
            pa[j][1] = pkh2(p02, p03);
            pa[j][2] = pkh2(p10, p11);
            pa[j][3] = pkh2(p12, p13);
        }
        ls0 += __shfl_xor_sync(0xffffffffu, ls0, 1);
        ls0 += __shfl_xor_sync(0xffffffffu, ls0, 2);
        ls1 += __shfl_xor_sync(0xffffffffu, ls1, 1);
        ls1 += __shfl_xor_sync(0xffffffffu, ls1, 2);
        l0 = l0 * a0 + ls0;
        l1 = l1 * a1 + ls1;
        m0 = mn0;
        m1 = mn1;

        // ---- rescale O, then O += P V (P from registers) ----
#pragma unroll
        for (int n8 = 0; n8 < 16; ++n8) {
            acc_o[n8][0] *= a0; acc_o[n8][1] *= a0;
            acc_o[n8][2] *= a1; acc_o[n8][3] *= a1;
        }
#pragma unroll
        for (int kk = 0; kk < 4; ++kk) {
            const int ks = (kk + (w & 3)) & 3;
            const int vrow = ks * 16 + vrow_in;
            const u32 vswz = (u32)(vrow * 256);
            const u32 vxr = (u32)((vrow & 7) << 4);
#pragma unroll
            for (int pair = 0; pair < 8; ++pair) {
                u32 hq = (u32)(pair * 16) + vh8;
                u32 vf[4];
                ldsm4t(vf, kvb + 16384 + vswz + (((hq >> 3) * 16) ^ vxr));
                mma_f16(acc_o[pair * 2],     pa[ks], vf[0], vf[1]);
                mma_f16(acc_o[pair * 2 + 1], pa[ks], vf[2], vf[3]);
            }
        }
        __syncthreads();
    }

    // ---- finalize: O/l -> enc split fp16 directly ----
    const float i0 = 1.0f / l0;
    const float i1 = 1.0f / l1;
    const int tg0 = t0 + (rr0 & 63), ng0 = kh * 2 + (rr0 >> 6);
    const int tg1 = t0 + (rr1 & 63), ng1 = kh * 2 + (rr1 >> 6);
#pragma unroll
    for (int n8 = 0; n8 < 16; ++n8) {
        int h = n8 * 8 + (lane & 3) * 2;
        float o0 = acc_o[n8][0] * i0;
        float o1 = acc_o[n8][1] * i0;
        float o2 = acc_o[n8][2] * i1;
        float o3 = acc_o[n8][3] * i1;
        u16 h0, lo0, h1, lo1, h2, lo2, h3, lo3;
        split_fp16(o0, h0, lo0); split_fp16(o1, h1, lo1);
        split_fp16(o2, h2, lo2); split_fp16(o3, h3, lo3);
        size_t i0x = (size_t)(tg0 * NQH + ng0) * HD + h;
        size_t i1x = (size_t)(tg1 * NQH + ng1) * HD + h;
        *reinterpret_cast<u32*>(ge_h + i0x) = (u32)h0 | ((u32)h1 << 16);
        *reinterpret_cast<u32*>(ge_l + i0x) = (u32)lo0 | ((u32)lo1 << 16);
        *reinterpret_cast<u32*>(ge_h + i1x) = (u32)h2 | ((u32)h3 << 16);
        *reinterpret_cast<u32*>(ge_l + i1x) = (u32)lo2 | ((u32)lo3 << 16);
    }
}

// ============================================================
extern "C" void kernel_launch(void* const* d_in, const int* in_sizes, int n_in,
                              void* d_out, int out_size)
{
    (void)in_sizes; (void)n_in; (void)out_size;
    const float* x   = (const float*)d_in[0];
    const int*   seg = (const int*)d_in[1];
    const float* qw  = (const float*)d_in[3];
    const float* kvw = (const float*)d_in[4];
    const float* ow  = (const float*)d_in[5];
    float* out = (float*)d_out;

    cudaFuncSetAttribute(hmma_gemm, cudaFuncAttributeMaxDynamicSharedMemorySize, GEMM_SMEM);
    cudaFuncSetAttribute(attn_mma, cudaFuncAttributeMaxDynamicSharedMemorySize, ATT2_SMEM);

    convert_x<<<4096, 256>>>(x);
    wconv<<<dim3(128, 64), 256>>>(qw, kvw, ow, 0);
    wconv<<<dim3(64, 64), 256>>>(qw, kvw, ow, 1);
    hmma_gemm<<<dim3(32, 16), 256, GEMM_SMEM>>>(nullptr, 0, 1);   // qkv (1-term)
    rope_split<<<T_DIM, 256>>>(seg);
    attn_mma<<<dim3(NKH, 32), 256, ATT2_SMEM>>>();
    hmma_gemm<<<dim3(16, 16), 256, GEMM_SMEM>>>(out, D_DIM, 0);   // out proj (2-term)
}